// round 11
// baseline (speedup 1.0000x reference)
#include <cuda_runtime.h>
#include <cuda_bf16.h>
#include <math.h>
#include <stdint.h>

// ---------------- problem constants ----------------
#define Bn 32
#define Pn 49
#define En 256
#define Hn 256
#define Tn 48
#define STEPS 47
#define Vn 32000
#define INn 792          // E + VP + LB + H + E
#define XSn 536          // E + VP + LB + H
#define ROWS (Bn*STEPS)  // 1504

#define ATT_OFF 0
#define LOGP_OFF (ROWS*(Pn+1))                 // 75200
#define TXT_OFF  (LOGP_OFF + (size_t)ROWS*Vn)

// ---------------- scratch (device globals; no allocation) ----------------
__device__ float g_xs  [Bn*XSn];
__device__ float g_h0  [Bn*Hn];
__device__ float g_m0  [Bn*Hn];
__device__ float g_xcat[ROWS*INn];          // compact rows
__device__ float g_xg  [ROWS*4*Hn];         // compact rows
__device__ float4 g_whhR4[Hn*Hn];
__device__ float g_v   [Bn*Pn*Hn];
__device__ float g_hs  [ROWS*Hn];           // compact rows
__device__ float g_fo  [ROWS*2*En];         // compact rows
__device__ float g_hh2 [ROWS*Hn];           // compact rows
__device__ float g_ss2 [ROWS*Hn];           // compact rows
__device__ float g_chh [ROWS*En];           // compact rows
__device__ float g_logits[(size_t)ROWS*Vn]; // compact rows (~192 MB cap)

// valid-row compaction maps
__device__ int g_V[1];
__device__ int g_rmap[ROWS];   // bt -> compact index (or -1)
__device__ int g_bcnt[Bn];     // valid steps per batch
__device__ int g_bstart[Bn];   // compact row offset per batch

// bf16 hi/lo splits for tensor-core logits GEMM
__device__ __align__(256) __nv_bfloat16 g_wph[(size_t)Vn*En];
__device__ __align__(256) __nv_bfloat16 g_wpl[(size_t)Vn*En];
__device__ __align__(256) __nv_bfloat16 g_chh_h[ROWS*En];
__device__ __align__(256) __nv_bfloat16 g_chh_l[ROWS*En];

// ---------------- packed f32x2 helpers (Blackwell FFMA2) ----------------
__device__ __forceinline__ unsigned long long fpk(float lo, float hi) {
    unsigned long long r;
    asm("mov.b64 %0, {%1, %2};" : "=l"(r) : "f"(lo), "f"(hi));
    return r;
}
__device__ __forceinline__ void ffma2(unsigned long long& d,
                                      unsigned long long a,
                                      unsigned long long b) {
    asm("fma.rn.f32x2 %0, %1, %2, %3;" : "=l"(d) : "l"(a), "l"(b), "l"(d));
}
__device__ __forceinline__ float2 fup(unsigned long long v) {
    float2 r;
    asm("mov.b64 {%0, %1}, %2;" : "=f"(r.x), "=f"(r.y) : "l"(v));
    return r;
}
__device__ __forceinline__ float sigm(float x) {
    return 1.0f / (1.0f + __expf(-x));
}
__device__ __forceinline__ uint32_t smem_u32(const void* p) {
    uint32_t a;
    asm("{ .reg .u64 t; cvta.to.shared.u64 t, %1; cvt.u32.u64 %0, t; }"
        : "=r"(a) : "l"(p));
    return a;
}

// ---------------- warp-level tensor core helpers (sm_80+ ISA) ----------------
__device__ __forceinline__ void ldsm4(uint32_t* r, uint32_t addr) {
    asm volatile("ldmatrix.sync.aligned.m8n8.x4.shared.b16 {%0,%1,%2,%3}, [%4];"
        : "=r"(r[0]), "=r"(r[1]), "=r"(r[2]), "=r"(r[3]) : "r"(addr));
}
__device__ __forceinline__ void ldsm2(uint32_t* r, uint32_t addr) {
    asm volatile("ldmatrix.sync.aligned.m8n8.x2.shared.b16 {%0,%1}, [%2];"
        : "=r"(r[0]), "=r"(r[1]) : "r"(addr));
}
__device__ __forceinline__ void mma_bf16(float* c, const uint32_t* a, const uint32_t* b) {
    asm volatile(
        "mma.sync.aligned.m16n8k16.row.col.f32.bf16.bf16.f32 "
        "{%0,%1,%2,%3}, {%4,%5,%6,%7}, {%8,%9}, {%0,%1,%2,%3};"
        : "+f"(c[0]), "+f"(c[1]), "+f"(c[2]), "+f"(c[3])
        : "r"(a[0]), "r"(a[1]), "r"(a[2]), "r"(a[3]), "r"(b[0]), "r"(b[1]));
}

// ---------------- valid-row maps ----------------
__global__ void build_maps(const int* __restrict__ length) {
    __shared__ int cnt[Bn], start[Bn];
    int tid = threadIdx.x;
    if (tid < Bn) {
        int c = length[tid] - 1;
        if (c < 0) c = 0;
        if (c > STEPS) c = STEPS;
        cnt[tid] = c;
        g_bcnt[tid] = c;
    }
    __syncthreads();
    if (tid == 0) {
        int s = 0;
        for (int b = 0; b < Bn; b++) { start[b] = s; g_bstart[b] = s; s += cnt[b]; }
        g_V[0] = s;
    }
    __syncthreads();
    for (int bt = tid; bt < ROWS; bt += 256) {
        int b = bt / STEPS, t = bt % STEPS;
        g_rmap[bt] = (t < cnt[b]) ? (start[b] + t) : -1;
    }
}

// ---------------- prep: image_mean, x_static, h0, m0 ----------------
__global__ void prep_kernel(const float* __restrict__ image,
                            const float* __restrict__ vp,
                            const float* __restrict__ label,
                            const float* __restrict__ topic,
                            const float* __restrict__ Wh, const float* __restrict__ bh,
                            const float* __restrict__ Wm, const float* __restrict__ bm) {
    int b = blockIdx.x;
    int tid = threadIdx.x;   // 256
    __shared__ __align__(16) float im[En];

    float s = 0.f;
    #pragma unroll 7
    for (int p = 0; p < Pn; p++) s += image[(b*Pn + p)*En + tid];
    float mean = s * (1.0f/49.0f);
    im[tid] = mean;

    g_xs[b*XSn + tid] = mean;
    if (tid < 8)  g_xs[b*XSn + 256 + tid] = vp[b*8 + tid];
    if (tid < 16) g_xs[b*XSn + 264 + tid] = label[b*16 + tid];
    g_xs[b*XSn + 280 + tid] = topic[b*Hn + tid];
    __syncthreads();

    float ah = bh[tid], am = bm[tid];
    #pragma unroll 8
    for (int k = 0; k < En; k++) {
        float x = im[k];
        ah = fmaf(x, Wh[tid*En + k], ah);
        am = fmaf(x, Wm[tid*En + k], am);
    }
    g_h0[b*Hn + tid] = tanhf(ah);
    g_m0[b*Hn + tid] = tanhf(am);
}

// ---------------- Whh reorder for coalesced LSTM reads ----------------
__global__ void whh_transpose(const float* __restrict__ Whh) {
    int k = blockIdx.x;
    int j = threadIdx.x;
    float4 w;
    w.x = Whh[(0*Hn + j)*Hn + k];
    w.y = Whh[(1*Hn + j)*Hn + k];
    w.z = Whh[(2*Hn + j)*Hn + k];
    w.w = Whh[(3*Hn + j)*Hn + k];
    g_whhR4[k*Hn + j] = w;
}

// ---------------- build concat rows (compact) ----------------
__global__ void xcat_kernel(const int* __restrict__ text,
                            const float* __restrict__ emb) {
    int bt = blockIdx.x;
    int v = g_rmap[bt];
    if (v < 0) return;
    int b = bt / STEPS, t = bt % STEPS;
    int tid = threadIdx.x;
    int tok = text[b*Tn + t];
    float* row = g_xcat + (size_t)v*INn;
    for (int i = tid; i < XSn; i += 256) row[i] = g_xs[b*XSn + i];
    row[XSn + tid] = emb[(size_t)tok*En + tid];
}

// ---------------- bf16 hi/lo split ----------------
__global__ void split_bf16(const float* __restrict__ src,
                           __nv_bfloat16* __restrict__ hi,
                           __nv_bfloat16* __restrict__ lo, int n4,
                           const int* __restrict__ rows4) {
    int i = blockIdx.x*256 + threadIdx.x;
    int lim = rows4 ? rows4[0]*(En/4) : n4;
    if (i >= lim) return;
    float4 v = ((const float4*)src)[i];
    float f[4] = {v.x, v.y, v.z, v.w};
    unsigned short h[4], l[4];
    #pragma unroll
    for (int k = 0; k < 4; k++) {
        __nv_bfloat16 hb = __float2bfloat16_rn(f[k]);
        float r = f[k] - __bfloat162float(hb);
        __nv_bfloat16 lb = __float2bfloat16_rn(r);
        h[k] = __bfloat16_as_ushort(hb);
        l[k] = __bfloat16_as_ushort(lb);
    }
    uint2 uh, ul;
    uh.x = (uint32_t)h[0] | ((uint32_t)h[1] << 16);
    uh.y = (uint32_t)h[2] | ((uint32_t)h[3] << 16);
    ul.x = (uint32_t)l[0] | ((uint32_t)l[1] << 16);
    ul.y = (uint32_t)l[2] | ((uint32_t)l[3] << 16);
    ((uint2*)hi)[i] = uh;
    ((uint2*)lo)[i] = ul;
}

// ============== SIMT fp32 GEMM (128x128), runtime M ==============
#define SPAD 132
__global__ __launch_bounds__(256, 2)
void gemm_tn128(const float* __restrict__ A, int lda,
                const float* __restrict__ W,
                const float* __restrict__ bias,
                float* __restrict__ C,
                int M, int N, int K, int doRelu,
                const int* __restrict__ Mdev) {
    const int Mv = Mdev ? Mdev[0] : M;
    const int m0 = blockIdx.y * 128, n0 = blockIdx.x * 128;
    if (m0 >= Mv) return;

    __shared__ __align__(16) float As[2][16][SPAD];
    __shared__ __align__(16) float Bs[2][16][SPAD];

    const int tid = threadIdx.x;
    const int tx = tid & 15, ty = tid >> 4;

    const int lr = tid >> 2;
    const int lk = (tid & 3) * 4;

    unsigned long long acc[8][4];
    #pragma unroll
    for (int i = 0; i < 8; i++)
        #pragma unroll
        for (int j = 0; j < 4; j++) acc[i][j] = 0ULL;

    const int KT = (K + 15) / 16;
    const float4 z4 = make_float4(0.f, 0.f, 0.f, 0.f);
    float4 fa0, fa1, fb0, fb1;

    {
        int k = lk;
        bool kok = (k < K);
        int mA0 = m0 + lr, mA1 = m0 + lr + 64;
        int nB0 = n0 + lr, nB1 = n0 + lr + 64;
        fa0 = (kok && mA0 < Mv) ? *(const float4*)&A[(size_t)mA0*lda + k] : z4;
        fa1 = (kok && mA1 < Mv) ? *(const float4*)&A[(size_t)mA1*lda + k] : z4;
        fb0 = (kok && nB0 < N) ? *(const float4*)&W[(size_t)nB0*K + k] : z4;
        fb1 = (kok && nB1 < N) ? *(const float4*)&W[(size_t)nB1*K + k] : z4;
    }
    As[0][lk+0][lr] = fa0.x; As[0][lk+1][lr] = fa0.y; As[0][lk+2][lr] = fa0.z; As[0][lk+3][lr] = fa0.w;
    As[0][lk+0][lr+64] = fa1.x; As[0][lk+1][lr+64] = fa1.y; As[0][lk+2][lr+64] = fa1.z; As[0][lk+3][lr+64] = fa1.w;
    Bs[0][lk+0][lr] = fb0.x; Bs[0][lk+1][lr] = fb0.y; Bs[0][lk+2][lr] = fb0.z; Bs[0][lk+3][lr] = fb0.w;
    Bs[0][lk+0][lr+64] = fb1.x; Bs[0][lk+1][lr+64] = fb1.y; Bs[0][lk+2][lr+64] = fb1.z; Bs[0][lk+3][lr+64] = fb1.w;
    __syncthreads();

    for (int kt = 0; kt < KT; kt++) {
        int cur = kt & 1;
        if (kt + 1 < KT) {
            int k = (kt + 1) * 16 + lk;
            bool kok = (k < K);
            int mA0 = m0 + lr, mA1 = m0 + lr + 64;
            int nB0 = n0 + lr, nB1 = n0 + lr + 64;
            fa0 = (kok && mA0 < Mv) ? *(const float4*)&A[(size_t)mA0*lda + k] : z4;
            fa1 = (kok && mA1 < Mv) ? *(const float4*)&A[(size_t)mA1*lda + k] : z4;
            fb0 = (kok && nB0 < N) ? *(const float4*)&W[(size_t)nB0*K + k] : z4;
            fb1 = (kok && nB1 < N) ? *(const float4*)&W[(size_t)nB1*K + k] : z4;
        }
        #pragma unroll
        for (int kk = 0; kk < 16; kk++) {
            float4 a0 = *(const float4*)&As[cur][kk][ty*8];
            float4 a1 = *(const float4*)&As[cur][kk][ty*8 + 4];
            float4 b0 = *(const float4*)&Bs[cur][kk][tx*8];
            float4 b1 = *(const float4*)&Bs[cur][kk][tx*8 + 4];
            unsigned long long bp0 = fpk(b0.x, b0.y);
            unsigned long long bp1 = fpk(b0.z, b0.w);
            unsigned long long bp2 = fpk(b1.x, b1.y);
            unsigned long long bp3 = fpk(b1.z, b1.w);
            float av[8] = {a0.x, a0.y, a0.z, a0.w, a1.x, a1.y, a1.z, a1.w};
            #pragma unroll
            for (int i = 0; i < 8; i++) {
                unsigned long long ad = fpk(av[i], av[i]);
                ffma2(acc[i][0], ad, bp0);
                ffma2(acc[i][1], ad, bp1);
                ffma2(acc[i][2], ad, bp2);
                ffma2(acc[i][3], ad, bp3);
            }
        }
        if (kt + 1 < KT) {
            int nxt = cur ^ 1;
            As[nxt][lk+0][lr] = fa0.x; As[nxt][lk+1][lr] = fa0.y; As[nxt][lk+2][lr] = fa0.z; As[nxt][lk+3][lr] = fa0.w;
            As[nxt][lk+0][lr+64] = fa1.x; As[nxt][lk+1][lr+64] = fa1.y; As[nxt][lk+2][lr+64] = fa1.z; As[nxt][lk+3][lr+64] = fa1.w;
            Bs[nxt][lk+0][lr] = fb0.x; Bs[nxt][lk+1][lr] = fb0.y; Bs[nxt][lk+2][lr] = fb0.z; Bs[nxt][lk+3][lr] = fb0.w;
            Bs[nxt][lk+0][lr+64] = fb1.x; Bs[nxt][lk+1][lr+64] = fb1.y; Bs[nxt][lk+2][lr+64] = fb1.z; Bs[nxt][lk+3][lr+64] = fb1.w;
            __syncthreads();
        }
    }

    int nb = n0 + tx*8;
    float bvals[8];
    #pragma unroll
    for (int j = 0; j < 8; j++) bvals[j] = (nb + j < N) ? bias[nb + j] : 0.f;

    #pragma unroll
    for (int i = 0; i < 8; i++) {
        int m = m0 + ty*8 + i;
        if (m >= Mv) continue;
        float out[8];
        #pragma unroll
        for (int j = 0; j < 4; j++) {
            float2 v = fup(acc[i][j]);
            out[2*j]   = v.x + bvals[2*j];
            out[2*j+1] = v.y + bvals[2*j+1];
        }
        if (doRelu) {
            #pragma unroll
            for (int j = 0; j < 8; j++) out[j] = fmaxf(out[j], 0.f);
        }
        if (nb + 7 < N) {
            *(float4*)&C[(size_t)m*N + nb]     = make_float4(out[0], out[1], out[2], out[3]);
            *(float4*)&C[(size_t)m*N + nb + 4] = make_float4(out[4], out[5], out[6], out[7]);
        } else {
            #pragma unroll
            for (int j = 0; j < 8; j++)
                if (nb + j < N) C[(size_t)m*N + nb + j] = out[j];
        }
    }
}

// ---------------- small fp32 GEMM (64x64) with runtime M ----------------
__global__ void gemm_tn(const float* __restrict__ A, int lda,
                        const float* __restrict__ W,
                        const float* __restrict__ bias,
                        float* __restrict__ C,
                        int M, int N, int K, int doRelu,
                        const int* __restrict__ Mdev) {
    const int Mv = Mdev ? Mdev[0] : M;
    const int m0 = blockIdx.y * 64, n0 = blockIdx.x * 64;
    if (m0 >= Mv) return;

    __shared__ __align__(16) float As[16][64];
    __shared__ __align__(16) float Bs[16][64];

    const int tid = threadIdx.x;
    const int tx = tid & 15, ty = tid >> 4;

    unsigned long long acc[4][2];
    #pragma unroll
    for (int i = 0; i < 4; i++) { acc[i][0] = 0ULL; acc[i][1] = 0ULL; }

    for (int k0 = 0; k0 < K; k0 += 16) {
        #pragma unroll
        for (int i = 0; i < 4; i++) {
            int idx = tid + i*256;
            int r = idx >> 4, kk = idx & 15;
            int m = m0 + r, k = k0 + kk, n = n0 + r;
            As[kk][r] = (m < Mv && k < K) ? A[(size_t)m*lda + k] : 0.f;
            Bs[kk][r] = (n < N && k < K) ? W[(size_t)n*K + k] : 0.f;
        }
        __syncthreads();
        #pragma unroll
        for (int kk = 0; kk < 16; kk++) {
            float4 a4 = *(const float4*)&As[kk][ty*4];
            float4 b4 = *(const float4*)&Bs[kk][tx*4];
            unsigned long long b01 = fpk(b4.x, b4.y);
            unsigned long long b23 = fpk(b4.z, b4.w);
            unsigned long long a0 = fpk(a4.x, a4.x);
            unsigned long long a1 = fpk(a4.y, a4.y);
            unsigned long long a2 = fpk(a4.z, a4.z);
            unsigned long long a3 = fpk(a4.w, a4.w);
            ffma2(acc[0][0], a0, b01); ffma2(acc[0][1], a0, b23);
            ffma2(acc[1][0], a1, b01); ffma2(acc[1][1], a1, b23);
            ffma2(acc[2][0], a2, b01); ffma2(acc[2][1], a2, b23);
            ffma2(acc[3][0], a3, b01); ffma2(acc[3][1], a3, b23);
        }
        __syncthreads();
    }

    #pragma unroll
    for (int i = 0; i < 4; i++) {
        int m = m0 + ty*4 + i;
        if (m >= Mv) continue;
        float2 v0 = fup(acc[i][0]);
        float2 v1 = fup(acc[i][1]);
        float vals[4] = {v0.x, v0.y, v1.x, v1.y};
        #pragma unroll
        for (int jj = 0; jj < 4; jj++) {
            int n = n0 + tx*4 + jj;
            if (n < N) {
                float o = vals[jj] + bias[n];
                if (doRelu) o = fmaxf(o, 0.f);
                C[(size_t)m*N + n] = o;
            }
        }
    }
}

// ---------------- sequential LSTM (compact rows, per-batch early exit) ----------------
__global__ void lstm_kernel(const float* __restrict__ bhh) {
    int b = blockIdx.x;
    int j = threadIdx.x;
    __shared__ __align__(16) float hs[Hn];

    const int steps = g_bcnt[b];
    const int base_row = g_bstart[b];

    float m = g_m0[b*Hn + j];
    hs[j] = g_h0[b*Hn + j];
    float bi = bhh[j], bf = bhh[256 + j], bg = bhh[512 + j], bo = bhh[768 + j];
    const ulonglong2* W2 = reinterpret_cast<const ulonglong2*>(g_whhR4);
    __syncthreads();

    for (int t = 0; t < steps; t++) {
        unsigned long long aIF = 0ULL, aGO = 0ULL;
        #pragma unroll 4
        for (int k0 = 0; k0 < Hn; k0 += 4) {
            float4 h4 = *(const float4*)&hs[k0];
            ulonglong2 w;
            unsigned long long hd;
            w = W2[(k0+0)*Hn + j]; hd = fpk(h4.x, h4.x); ffma2(aIF, hd, w.x); ffma2(aGO, hd, w.y);
            w = W2[(k0+1)*Hn + j]; hd = fpk(h4.y, h4.y); ffma2(aIF, hd, w.x); ffma2(aGO, hd, w.y);
            w = W2[(k0+2)*Hn + j]; hd = fpk(h4.z, h4.z); ffma2(aIF, hd, w.x); ffma2(aGO, hd, w.y);
            w = W2[(k0+3)*Hn + j]; hd = fpk(h4.w, h4.w); ffma2(aIF, hd, w.x); ffma2(aGO, hd, w.y);
        }
        float2 IF = fup(aIF), GO = fup(aGO);
        size_t base = (size_t)(base_row + t) * (4*Hn) + j;
        float gi = g_xg[base]        + bi + IF.x;
        float gf = g_xg[base + 256]  + bf + IF.y;
        float gg = g_xg[base + 512]  + bg + GO.x;
        float go = g_xg[base + 768]  + bo + GO.y;
        m = sigm(gf)*m + sigm(gi)*tanhf(gg);
        float hn = sigm(go)*tanhf(m);
        __syncthreads();
        hs[j] = hn;
        g_hs[(size_t)(base_row + t)*Hn + j] = hn;
        __syncthreads();
    }
}

// ---------------- fused attention per (b,t), compact-aware ----------------
__global__ void attn_kernel(const float* __restrict__ image,
                            const float* __restrict__ Wz,
                            const float* __restrict__ bz,
                            float* __restrict__ dout) {
    int bt = blockIdx.x;
    int b = bt / STEPS;
    int tid = threadIdx.x;             // 128
    int wid = tid >> 5, lane = tid & 31;
    int v = g_rmap[bt];

    if (v < 0) {
        if (tid < Pn+1)
            dout[ATT_OFF + (size_t)bt*(Pn+1) + tid] = 0.f;
        return;
    }

    __shared__ float shh2[Hn], shh[Hn], ss[Hn], ss2[Hn];
    __shared__ float zz[Pn+1], aw[Pn+1];

    for (int k = tid; k < Hn; k += 128) {
        shh2[k] = g_hh2[(size_t)v*Hn + k];
        shh [k] = g_fo [(size_t)v*2*En + k];
        ss  [k] = g_fo [(size_t)v*2*En + En + k];
        ss2 [k] = g_ss2[(size_t)v*Hn + k];
    }
    __syncthreads();

    for (int p = wid; p < Pn+1; p += 4) {
        float part = 0.f;
        const float* vrow = (p < Pn) ? (g_v + (size_t)(b*Pn + p)*Hn) : ss2;
        for (int k = lane; k < Hn; k += 32)
            part += Wz[k] * tanhf(vrow[k] + shh2[k]);
        #pragma unroll
        for (int off = 16; off > 0; off >>= 1)
            part += __shfl_down_sync(0xffffffff, part, off);
        if (lane == 0) zz[p] = part + bz[0];
    }
    __syncthreads();

    if (tid == 0) {
        float mx = zz[0];
        for (int p = 1; p < Pn+1; p++) mx = fmaxf(mx, zz[p]);
        float s = 0.f;
        for (int p = 0; p < Pn+1; p++) { float e = __expf(zz[p]-mx); aw[p] = e; s += e; }
        float inv = 1.f / s;
        for (int p = 0; p < Pn+1; p++) aw[p] *= inv;
    }
    __syncthreads();

    if (tid < Pn+1)
        dout[ATT_OFF + (size_t)bt*(Pn+1) + tid] = aw[tid];

    for (int k = tid; k < En; k += 128) {
        float c = aw[Pn] * ss[k];
        #pragma unroll 7
        for (int p = 0; p < Pn; p++)
            c = fmaf(aw[p], image[(size_t)(b*Pn + p)*En + k], c);
        g_chh[(size_t)v*En + k] = c + shh[k];
    }
}

// ============== tensor-core logits GEMM via mma.sync (bf16 hi/lo, fp32 acc) ==============
#define LTK 64
#define LCHUNK_B (128*LTK*2)            // 16384 bytes per tile buffer
#define LOGITS_SMEM (4*LCHUNK_B)        // 65536

__device__ __forceinline__ void load_chunk(__nv_bfloat16* dst,
                                           const __nv_bfloat16* __restrict__ src,
                                           int row0, int rows_valid, int kc, int tid) {
    #pragma unroll
    for (int i = 0; i < 4; i++) {
        int idx = tid + i*256;
        int row = idx >> 3, ch = idx & 7;
        uint32_t off = (uint32_t)(row*128 + ch*16);
        off ^= (off >> 3) & 0x70;
        int gr = row0 + row;
        uint4 v = (gr < rows_valid) ? *(const uint4*)(src + (size_t)gr*256 + kc + ch*8)
                                    : make_uint4(0u, 0u, 0u, 0u);
        *(uint4*)((char*)dst + off) = v;
    }
}

__global__ __launch_bounds__(256)
void logits_mma(const __nv_bfloat16* __restrict__ Ah, const __nv_bfloat16* __restrict__ Al,
                const __nv_bfloat16* __restrict__ Bh, const __nv_bfloat16* __restrict__ Bl,
                const float* __restrict__ bp, float* __restrict__ out,
                const int* __restrict__ Vdev) {
    const int V = Vdev[0];
    const int m0 = blockIdx.y * 128;
    if (m0 >= V) return;
    const int n0 = blockIdx.x * 128;

    extern __shared__ char smem[];
    __nv_bfloat16* sAh = (__nv_bfloat16*)smem;
    __nv_bfloat16* sAl = (__nv_bfloat16*)(smem + LCHUNK_B);
    __nv_bfloat16* sBh = (__nv_bfloat16*)(smem + 2*LCHUNK_B);
    __nv_bfloat16* sBl = (__nv_bfloat16*)(smem + 3*LCHUNK_B);
    const uint32_t uAh = smem_u32(sAh), uAl = smem_u32(sAl);
    const uint32_t uBh = smem_u32(sBh), uBl = smem_u32(sBl);

    const int tid = threadIdx.x;
    const int wid = tid >> 5, lane = tid & 31;
    const int wm = wid >> 2;      // 0..1
    const int wn = wid & 3;       // 0..3

    float acc[4][4][4];
    #pragma unroll
    for (int a = 0; a < 4; a++)
        #pragma unroll
        for (int b = 0; b < 4; b++)
            #pragma unroll
            for (int c = 0; c < 4; c++) acc[a][b][c] = 0.f;

    const int a_lr = lane & 15, a_lc = lane >> 4;
    const int b_lr = lane & 7,  b_lc = (lane >> 3) & 1;

    for (int kc = 0; kc < En; kc += LTK) {
        load_chunk(sAh, Ah, m0, V, kc, tid);
        load_chunk(sAl, Al, m0, V, kc, tid);
        load_chunk(sBh, Bh, n0, Vn, kc, tid);
        load_chunk(sBl, Bl, n0, Vn, kc, tid);
        __syncthreads();

        #pragma unroll
        for (int ks = 0; ks < LTK/16; ks++) {
            uint32_t ah[4][4], al[4][4], bh[4][2], bl[4][2];
            #pragma unroll
            for (int mt = 0; mt < 4; mt++) {
                uint32_t off = (uint32_t)((wm*64 + mt*16 + a_lr)*128 + ks*32 + a_lc*16);
                off ^= (off >> 3) & 0x70;
                ldsm4(ah[mt], uAh + off);
                ldsm4(al[mt], uAl + off);
            }
            #pragma unroll
            for (int nt = 0; nt < 4; nt++) {
                uint32_t off = (uint32_t)((wn*32 + nt*8 + b_lr)*128 + ks*32 + b_lc*16);
                off ^= (off >> 3) & 0x70;
                ldsm2(bh[nt], uBh + off);
                ldsm2(bl[nt], uBl + off);
            }
            #pragma unroll
            for (int mt = 0; mt < 4; mt++)
                #pragma unroll
                for (int nt = 0; nt < 4; nt++)
                    mma_bf16(acc[mt][nt], ah[mt], bh[nt]);
            #pragma unroll
            for (int mt = 0; mt < 4; mt++)
                #pragma unroll
                for (int nt = 0; nt < 4; nt++)
                    mma_bf16(acc[mt][nt], ah[mt], bl[nt]);
            #pragma unroll
            for (int mt = 0; mt < 4; mt++)
                #pragma unroll
                for (int nt = 0; nt < 4; nt++)
                    mma_bf16(acc[mt][nt], al[mt], bh[nt]);
        }
        __syncthreads();
    }

    #pragma unroll
    for (int mt = 0; mt < 4; mt++) {
        int m1 = m0 + wm*64 + mt*16 + (lane >> 2);
        int m2 = m1 + 8;
        #pragma unroll
        for (int nt = 0; nt < 4; nt++) {
            int n = n0 + wn*32 + nt*8 + (lane & 3)*2;
            float2 bb = *(const float2*)&bp[n];
            const float* c = acc[mt][nt];
            if (m1 < V)
                *(float2*)&out[(size_t)m1*Vn + n] = make_float2(c[0] + bb.x, c[1] + bb.y);
            if (m2 < V)
                *(float2*)&out[(size_t)m2*Vn + n] = make_float2(c[2] + bb.x, c[3] + bb.y);
        }
    }
}

// ---------------- online log-softmax + argmax + mask + output ----------------
__global__ void softmax_kernel(const float* __restrict__ temp,
                               float* __restrict__ dout) {
    int bt = blockIdx.x;
    int b = bt / STEPS;
    int tid = threadIdx.x;             // 512
    int crow = g_rmap[bt];
    float4* lp4 = (float4*)(dout + LOGP_OFF + (size_t)bt*Vn);

    __shared__ float smx[512]; __shared__ int sai[512]; __shared__ float ssum[512];

    if (crow < 0) {
        float4 z = make_float4(0.f, 0.f, 0.f, 0.f);
        for (int i = tid; i < Vn/4; i += 512) lp4[i] = z;
        if (tid == 0) dout[TXT_OFF + bt] = 0.f;
        return;
    }

    float ls = 1.0f / temp[b];
    const float4* row4 = (const float4*)(g_logits + (size_t)crow*Vn);

    float mx = -3.402823466e38f; float sum = 0.f; int ai = 0;
    for (int i = tid; i < Vn/4; i += 512) {
        float4 v = row4[i];
        float vv[4] = {v.x, v.y, v.z, v.w};
        #pragma unroll
        for (int c = 0; c < 4; c++) {
            float x = vv[c];
            if (x > mx) {
                sum = sum * __expf((mx - x)*ls) + 1.f;
                mx = x; ai = 4*i + c;
            } else {
                sum += __expf((x - mx)*ls);
            }
        }
    }
    smx[tid] = mx; sai[tid] = ai; ssum[tid] = sum; __syncthreads();
    for (int s = 256; s > 0; s >>= 1) {
        if (tid < s) {
            float m1 = smx[tid],   m2 = smx[tid+s];
            float s1 = ssum[tid],  s2 = ssum[tid+s];
            int   i1 = sai[tid],   i2 = sai[tid+s];
            if (m2 > m1 || (m2 == m1 && i2 < i1)) {
                smx[tid] = m2; sai[tid] = i2;
                ssum[tid] = s2 + s1 * __expf((m1 - m2)*ls);
            } else {
                ssum[tid] = s1 + s2 * __expf((m2 - m1)*ls);
            }
        }
        __syncthreads();
    }
    mx = smx[0]; ai = sai[0];
    float lse = logf(ssum[0]);

    for (int i = tid; i < Vn/4; i += 512) {
        float4 v = row4[i];
        float4 o;
        o.x = (v.x - mx)*ls - lse;
        o.y = (v.y - mx)*ls - lse;
        o.z = (v.z - mx)*ls - lse;
        o.w = (v.w - mx)*ls - lse;
        lp4[i] = o;
    }
    if (tid == 0) dout[TXT_OFF + bt] = (float)ai;
}

// ---------------- launcher ----------------
extern "C" void kernel_launch(void* const* d_in, const int* in_sizes, int n_in,
                              void* d_out, int out_size) {
    const float* image = (const float*)d_in[0];
    const float* vp    = (const float*)d_in[1];
    const float* label = (const float*)d_in[2];
    const float* topic = (const float*)d_in[3];
    const float* temp  = (const float*)d_in[4];
    const int*   text  = (const int*)  d_in[5];
    const int*   length= (const int*)  d_in[6];
    const float* emb   = (const float*)d_in[7];
    const float* Wv    = (const float*)d_in[8];
    const float* bv    = (const float*)d_in[9];
    const float* Wh    = (const float*)d_in[10];
    const float* bh    = (const float*)d_in[11];
    const float* Wm    = (const float*)d_in[12];
    const float* bm    = (const float*)d_in[13];
    const float* Wih   = (const float*)d_in[14];
    const float* bih   = (const float*)d_in[15];
    const float* Whh   = (const float*)d_in[16];
    const float* bhh   = (const float*)d_in[17];
    const float* Wfc   = (const float*)d_in[18];
    const float* bfc   = (const float*)d_in[19];
    const float* Whh2  = (const float*)d_in[20];
    const float* bhh2  = (const float*)d_in[21];
    const float* Ws    = (const float*)d_in[22];
    const float* bs    = (const float*)d_in[23];
    const float* Wz    = (const float*)d_in[24];
    const float* bz    = (const float*)d_in[25];
    const float* Wp    = (const float*)d_in[26];
    const float* bp    = (const float*)d_in[27];
    float* dout = (float*)d_out;

    float *p_xcat, *p_xg, *p_v, *p_hs, *p_fo, *p_hh2, *p_ss2, *p_chh, *p_logits;
    __nv_bfloat16 *p_wph, *p_wpl, *p_chh_h, *p_chh_l;
    int *p_V;
    cudaGetSymbolAddress((void**)&p_xcat,   g_xcat);
    cudaGetSymbolAddress((void**)&p_xg,     g_xg);
    cudaGetSymbolAddress((void**)&p_v,      g_v);
    cudaGetSymbolAddress((void**)&p_hs,     g_hs);
    cudaGetSymbolAddress((void**)&p_fo,     g_fo);
    cudaGetSymbolAddress((void**)&p_hh2,    g_hh2);
    cudaGetSymbolAddress((void**)&p_ss2,    g_ss2);
    cudaGetSymbolAddress((void**)&p_chh,    g_chh);
    cudaGetSymbolAddress((void**)&p_logits, g_logits);
    cudaGetSymbolAddress((void**)&p_wph,    g_wph);
    cudaGetSymbolAddress((void**)&p_wpl,    g_wpl);
    cudaGetSymbolAddress((void**)&p_chh_h,  g_chh_h);
    cudaGetSymbolAddress((void**)&p_chh_l,  g_chh_l);
    cudaGetSymbolAddress((void**)&p_V,      g_V);

    cudaFuncSetAttribute(logits_mma, cudaFuncAttributeMaxDynamicSharedMemorySize,
                         LOGITS_SMEM);

    // valid-row maps + Wp hi/lo split (independent)
    build_maps<<<1, 256>>>(length);
    split_bf16<<<(Vn*En/4 + 255)/256, 256>>>(Wp, p_wph, p_wpl, Vn*En/4, nullptr);

    prep_kernel<<<Bn, 256>>>(image, vp, label, topic, Wh, bh, Wm, bm);
    whh_transpose<<<Hn, Hn>>>(Whh);
    xcat_kernel<<<ROWS, 256>>>(text, emb);   // compact rows

    // Xg = Xcat @ Wih^T + bih on COMPACT rows : (V x 1024), K=792
    gemm_tn128<<<dim3((4*Hn+127)/128, (ROWS+127)/128), 256>>>(p_xcat, INn, Wih, bih, p_xg,
                                                              ROWS, 4*Hn, INn, 0, p_V);
    // v = image @ Wv^T + bv (all rows)
    gemm_tn<<<dim3((Hn+63)/64, (Bn*Pn+63)/64), 256>>>(image, En, Wv, bv, p_v,
                                                      Bn*Pn, Hn, En, 0, nullptr);
    // sequential LSTM on compact rows, per-batch early exit
    lstm_kernel<<<Bn, 256>>>(bhh);

    // fo = relu(Hs @ Wfc^T + bfc) on compact rows (direct, no gather)
    gemm_tn<<<dim3((2*En+63)/64, (ROWS+63)/64), 256>>>(p_hs, Hn, Wfc, bfc, p_fo,
                                                       ROWS, 2*En, Hn, 1, p_V);
    // _hh, _s on compact rows
    gemm_tn<<<dim3((Hn+63)/64, (ROWS+63)/64), 256>>>(p_fo, 2*En, Whh2, bhh2, p_hh2,
                                                     ROWS, Hn, En, 0, p_V);
    gemm_tn<<<dim3((Hn+63)/64, (ROWS+63)/64), 256>>>(p_fo + En, 2*En, Ws, bs, p_ss2,
                                                     ROWS, Hn, En, 0, p_V);
    // attention: att out (all bt; zeros for invalid) + chh on compact rows
    attn_kernel<<<ROWS, 128>>>(image, Wz, bz, dout);

    // chh hi/lo split (compact rows), then tensor-core logits GEMM (compact rows)
    split_bf16<<<(ROWS*En/4 + 255)/256, 256>>>(p_chh, p_chh_h, p_chh_l, ROWS*En/4, p_V);
    logits_mma<<<dim3(Vn/128, (ROWS+127)/128), 256, LOGITS_SMEM>>>(
        p_chh_h, p_chh_l, p_wph, p_wpl, bp, p_logits, p_V);

    // online log-softmax + argmax + masking + outputs
    softmax_kernel<<<ROWS, 512>>>(temp, dout);
}

// round 12
// speedup vs baseline: 1.2728x; 1.2728x over previous
#include <cuda_runtime.h>
#include <cuda_bf16.h>
#include <math.h>
#include <stdint.h>

// ---------------- problem constants ----------------
#define Bn 32
#define Pn 49
#define En 256
#define Hn 256
#define Tn 48
#define STEPS 47
#define Vn 32000
#define INn 792          // E + VP + LB + H + E
#define XSn 536          // E + VP + LB + H
#define ROWS (Bn*STEPS)  // 1504

#define ATT_OFF 0
#define LOGP_OFF (ROWS*(Pn+1))                 // 75200
#define TXT_OFF  (LOGP_OFF + (size_t)ROWS*Vn)

// ---------------- scratch (device globals; no allocation) ----------------
__device__ float g_xs  [Bn*XSn];
__device__ float g_h0  [Bn*Hn];
__device__ float g_m0  [Bn*Hn];
__device__ float g_xcat[ROWS*INn];          // compact rows
__device__ float g_xg  [ROWS*4*Hn];         // compact rows
__device__ float4 g_whhR4[Hn*Hn];
__device__ float g_v   [Bn*Pn*Hn];
__device__ float g_hs  [ROWS*Hn];           // compact rows
__device__ float g_fo  [ROWS*2*En];         // compact rows
__device__ float g_hh2 [ROWS*Hn];           // compact rows
__device__ float g_ss2 [ROWS*Hn];           // compact rows
__device__ float g_logits[(size_t)ROWS*Vn]; // compact rows (~192 MB cap)

// valid-row compaction maps
__device__ int g_V[1];
__device__ int g_rmap[ROWS];   // bt -> compact index (or -1)
__device__ int g_bcnt[Bn];     // valid steps per batch
__device__ int g_bstart[Bn];   // compact row offset per batch

// bf16 hi/lo splits for tensor-core logits GEMM
__device__ __align__(256) __nv_bfloat16 g_wph[(size_t)Vn*En];
__device__ __align__(256) __nv_bfloat16 g_wpl[(size_t)Vn*En];
__device__ __align__(256) __nv_bfloat16 g_chh_h[ROWS*En];
__device__ __align__(256) __nv_bfloat16 g_chh_l[ROWS*En];

// ---------------- packed f32x2 helpers (Blackwell FFMA2) ----------------
__device__ __forceinline__ unsigned long long fpk(float lo, float hi) {
    unsigned long long r;
    asm("mov.b64 %0, {%1, %2};" : "=l"(r) : "f"(lo), "f"(hi));
    return r;
}
__device__ __forceinline__ void ffma2(unsigned long long& d,
                                      unsigned long long a,
                                      unsigned long long b) {
    asm("fma.rn.f32x2 %0, %1, %2, %3;" : "=l"(d) : "l"(a), "l"(b), "l"(d));
}
__device__ __forceinline__ float2 fup(unsigned long long v) {
    float2 r;
    asm("mov.b64 {%0, %1}, %2;" : "=f"(r.x), "=f"(r.y) : "l"(v));
    return r;
}
__device__ __forceinline__ float sigm(float x) {
    return 1.0f / (1.0f + __expf(-x));
}
__device__ __forceinline__ uint32_t smem_u32(const void* p) {
    uint32_t a;
    asm("{ .reg .u64 t; cvta.to.shared.u64 t, %1; cvt.u32.u64 %0, t; }"
        : "=r"(a) : "l"(p));
    return a;
}

// ---------------- warp-level tensor core helpers (sm_80+ ISA) ----------------
__device__ __forceinline__ void ldsm4(uint32_t* r, uint32_t addr) {
    asm volatile("ldmatrix.sync.aligned.m8n8.x4.shared.b16 {%0,%1,%2,%3}, [%4];"
        : "=r"(r[0]), "=r"(r[1]), "=r"(r[2]), "=r"(r[3]) : "r"(addr));
}
__device__ __forceinline__ void ldsm2(uint32_t* r, uint32_t addr) {
    asm volatile("ldmatrix.sync.aligned.m8n8.x2.shared.b16 {%0,%1}, [%2];"
        : "=r"(r[0]), "=r"(r[1]) : "r"(addr));
}
__device__ __forceinline__ void mma_bf16(float* c, const uint32_t* a, const uint32_t* b) {
    asm volatile(
        "mma.sync.aligned.m16n8k16.row.col.f32.bf16.bf16.f32 "
        "{%0,%1,%2,%3}, {%4,%5,%6,%7}, {%8,%9}, {%0,%1,%2,%3};"
        : "+f"(c[0]), "+f"(c[1]), "+f"(c[2]), "+f"(c[3])
        : "r"(a[0]), "r"(a[1]), "r"(a[2]), "r"(a[3]), "r"(b[0]), "r"(b[1]));
}

// ---------------- valid-row maps ----------------
__global__ void build_maps(const int* __restrict__ length) {
    __shared__ int cnt[Bn], start[Bn];
    int tid = threadIdx.x;
    if (tid < Bn) {
        int c = length[tid] - 1;
        if (c < 0) c = 0;
        if (c > STEPS) c = STEPS;
        cnt[tid] = c;
        g_bcnt[tid] = c;
    }
    __syncthreads();
    if (tid == 0) {
        int s = 0;
        for (int b = 0; b < Bn; b++) { start[b] = s; g_bstart[b] = s; s += cnt[b]; }
        g_V[0] = s;
    }
    __syncthreads();
    for (int bt = tid; bt < ROWS; bt += 256) {
        int b = bt / STEPS, t = bt % STEPS;
        g_rmap[bt] = (t < cnt[b]) ? (start[b] + t) : -1;
    }
}

// ---------------- prep: image_mean, x_static, h0, m0 ----------------
__global__ void prep_kernel(const float* __restrict__ image,
                            const float* __restrict__ vp,
                            const float* __restrict__ label,
                            const float* __restrict__ topic,
                            const float* __restrict__ Wh, const float* __restrict__ bh,
                            const float* __restrict__ Wm, const float* __restrict__ bm) {
    int b = blockIdx.x;
    int tid = threadIdx.x;   // 256
    __shared__ __align__(16) float im[En];

    float s = 0.f;
    #pragma unroll 7
    for (int p = 0; p < Pn; p++) s += image[(b*Pn + p)*En + tid];
    float mean = s * (1.0f/49.0f);
    im[tid] = mean;

    g_xs[b*XSn + tid] = mean;
    if (tid < 8)  g_xs[b*XSn + 256 + tid] = vp[b*8 + tid];
    if (tid < 16) g_xs[b*XSn + 264 + tid] = label[b*16 + tid];
    g_xs[b*XSn + 280 + tid] = topic[b*Hn + tid];
    __syncthreads();

    float ah = bh[tid], am = bm[tid];
    #pragma unroll 8
    for (int k = 0; k < En; k++) {
        float x = im[k];
        ah = fmaf(x, Wh[tid*En + k], ah);
        am = fmaf(x, Wm[tid*En + k], am);
    }
    g_h0[b*Hn + tid] = tanhf(ah);
    g_m0[b*Hn + tid] = tanhf(am);
}

// ---------------- Whh reorder for coalesced LSTM reads ----------------
__global__ void whh_transpose(const float* __restrict__ Whh) {
    int k = blockIdx.x;
    int j = threadIdx.x;
    float4 w;
    w.x = Whh[(0*Hn + j)*Hn + k];
    w.y = Whh[(1*Hn + j)*Hn + k];
    w.z = Whh[(2*Hn + j)*Hn + k];
    w.w = Whh[(3*Hn + j)*Hn + k];
    g_whhR4[k*Hn + j] = w;
}

// ---------------- build concat rows (compact) ----------------
__global__ void xcat_kernel(const int* __restrict__ text,
                            const float* __restrict__ emb) {
    int bt = blockIdx.x;
    int v = g_rmap[bt];
    if (v < 0) return;
    int b = bt / STEPS, t = bt % STEPS;
    int tid = threadIdx.x;
    int tok = text[b*Tn + t];
    float* row = g_xcat + (size_t)v*INn;
    for (int i = tid; i < XSn; i += 256) row[i] = g_xs[b*XSn + i];
    row[XSn + tid] = emb[(size_t)tok*En + tid];
}

// ---------------- bf16 hi/lo split (for Wp) ----------------
__global__ void split_bf16(const float* __restrict__ src,
                           __nv_bfloat16* __restrict__ hi,
                           __nv_bfloat16* __restrict__ lo, int n4) {
    int i = blockIdx.x*256 + threadIdx.x;
    if (i >= n4) return;
    float4 v = ((const float4*)src)[i];
    float f[4] = {v.x, v.y, v.z, v.w};
    unsigned short h[4], l[4];
    #pragma unroll
    for (int k = 0; k < 4; k++) {
        __nv_bfloat16 hb = __float2bfloat16_rn(f[k]);
        float r = f[k] - __bfloat162float(hb);
        __nv_bfloat16 lb = __float2bfloat16_rn(r);
        h[k] = __bfloat16_as_ushort(hb);
        l[k] = __bfloat16_as_ushort(lb);
    }
    uint2 uh, ul;
    uh.x = (uint32_t)h[0] | ((uint32_t)h[1] << 16);
    uh.y = (uint32_t)h[2] | ((uint32_t)h[3] << 16);
    ul.x = (uint32_t)l[0] | ((uint32_t)l[1] << 16);
    ul.y = (uint32_t)l[2] | ((uint32_t)l[3] << 16);
    ((uint2*)hi)[i] = uh;
    ((uint2*)lo)[i] = ul;
}

// ============== SIMT fp32 GEMM (128x128), runtime M ==============
#define SPAD 132
__global__ __launch_bounds__(256, 2)
void gemm_tn128(const float* __restrict__ A, int lda,
                const float* __restrict__ W,
                const float* __restrict__ bias,
                float* __restrict__ C,
                int M, int N, int K, int doRelu,
                const int* __restrict__ Mdev) {
    const int Mv = Mdev ? Mdev[0] : M;
    const int m0 = blockIdx.y * 128, n0 = blockIdx.x * 128;
    if (m0 >= Mv) return;

    __shared__ __align__(16) float As[2][16][SPAD];
    __shared__ __align__(16) float Bs[2][16][SPAD];

    const int tid = threadIdx.x;
    const int tx = tid & 15, ty = tid >> 4;

    const int lr = tid >> 2;
    const int lk = (tid & 3) * 4;

    unsigned long long acc[8][4];
    #pragma unroll
    for (int i = 0; i < 8; i++)
        #pragma unroll
        for (int j = 0; j < 4; j++) acc[i][j] = 0ULL;

    const int KT = (K + 15) / 16;
    const float4 z4 = make_float4(0.f, 0.f, 0.f, 0.f);
    float4 fa0, fa1, fb0, fb1;

    {
        int k = lk;
        bool kok = (k < K);
        int mA0 = m0 + lr, mA1 = m0 + lr + 64;
        int nB0 = n0 + lr, nB1 = n0 + lr + 64;
        fa0 = (kok && mA0 < Mv) ? *(const float4*)&A[(size_t)mA0*lda + k] : z4;
        fa1 = (kok && mA1 < Mv) ? *(const float4*)&A[(size_t)mA1*lda + k] : z4;
        fb0 = (kok && nB0 < N) ? *(const float4*)&W[(size_t)nB0*K + k] : z4;
        fb1 = (kok && nB1 < N) ? *(const float4*)&W[(size_t)nB1*K + k] : z4;
    }
    As[0][lk+0][lr] = fa0.x; As[0][lk+1][lr] = fa0.y; As[0][lk+2][lr] = fa0.z; As[0][lk+3][lr] = fa0.w;
    As[0][lk+0][lr+64] = fa1.x; As[0][lk+1][lr+64] = fa1.y; As[0][lk+2][lr+64] = fa1.z; As[0][lk+3][lr+64] = fa1.w;
    Bs[0][lk+0][lr] = fb0.x; Bs[0][lk+1][lr] = fb0.y; Bs[0][lk+2][lr] = fb0.z; Bs[0][lk+3][lr] = fb0.w;
    Bs[0][lk+0][lr+64] = fb1.x; Bs[0][lk+1][lr+64] = fb1.y; Bs[0][lk+2][lr+64] = fb1.z; Bs[0][lk+3][lr+64] = fb1.w;
    __syncthreads();

    for (int kt = 0; kt < KT; kt++) {
        int cur = kt & 1;
        if (kt + 1 < KT) {
            int k = (kt + 1) * 16 + lk;
            bool kok = (k < K);
            int mA0 = m0 + lr, mA1 = m0 + lr + 64;
            int nB0 = n0 + lr, nB1 = n0 + lr + 64;
            fa0 = (kok && mA0 < Mv) ? *(const float4*)&A[(size_t)mA0*lda + k] : z4;
            fa1 = (kok && mA1 < Mv) ? *(const float4*)&A[(size_t)mA1*lda + k] : z4;
            fb0 = (kok && nB0 < N) ? *(const float4*)&W[(size_t)nB0*K + k] : z4;
            fb1 = (kok && nB1 < N) ? *(const float4*)&W[(size_t)nB1*K + k] : z4;
        }
        #pragma unroll
        for (int kk = 0; kk < 16; kk++) {
            float4 a0 = *(const float4*)&As[cur][kk][ty*8];
            float4 a1 = *(const float4*)&As[cur][kk][ty*8 + 4];
            float4 b0 = *(const float4*)&Bs[cur][kk][tx*8];
            float4 b1 = *(const float4*)&Bs[cur][kk][tx*8 + 4];
            unsigned long long bp0 = fpk(b0.x, b0.y);
            unsigned long long bp1 = fpk(b0.z, b0.w);
            unsigned long long bp2 = fpk(b1.x, b1.y);
            unsigned long long bp3 = fpk(b1.z, b1.w);
            float av[8] = {a0.x, a0.y, a0.z, a0.w, a1.x, a1.y, a1.z, a1.w};
            #pragma unroll
            for (int i = 0; i < 8; i++) {
                unsigned long long ad = fpk(av[i], av[i]);
                ffma2(acc[i][0], ad, bp0);
                ffma2(acc[i][1], ad, bp1);
                ffma2(acc[i][2], ad, bp2);
                ffma2(acc[i][3], ad, bp3);
            }
        }
        if (kt + 1 < KT) {
            int nxt = cur ^ 1;
            As[nxt][lk+0][lr] = fa0.x; As[nxt][lk+1][lr] = fa0.y; As[nxt][lk+2][lr] = fa0.z; As[nxt][lk+3][lr] = fa0.w;
            As[nxt][lk+0][lr+64] = fa1.x; As[nxt][lk+1][lr+64] = fa1.y; As[nxt][lk+2][lr+64] = fa1.z; As[nxt][lk+3][lr+64] = fa1.w;
            Bs[nxt][lk+0][lr] = fb0.x; Bs[nxt][lk+1][lr] = fb0.y; Bs[nxt][lk+2][lr] = fb0.z; Bs[nxt][lk+3][lr] = fb0.w;
            Bs[nxt][lk+0][lr+64] = fb1.x; Bs[nxt][lk+1][lr+64] = fb1.y; Bs[nxt][lk+2][lr+64] = fb1.z; Bs[nxt][lk+3][lr+64] = fb1.w;
            __syncthreads();
        }
    }

    int nb = n0 + tx*8;
    float bvals[8];
    #pragma unroll
    for (int j = 0; j < 8; j++) bvals[j] = (nb + j < N) ? bias[nb + j] : 0.f;

    #pragma unroll
    for (int i = 0; i < 8; i++) {
        int m = m0 + ty*8 + i;
        if (m >= Mv) continue;
        float out[8];
        #pragma unroll
        for (int j = 0; j < 4; j++) {
            float2 v = fup(acc[i][j]);
            out[2*j]   = v.x + bvals[2*j];
            out[2*j+1] = v.y + bvals[2*j+1];
        }
        if (doRelu) {
            #pragma unroll
            for (int j = 0; j < 8; j++) out[j] = fmaxf(out[j], 0.f);
        }
        if (nb + 7 < N) {
            *(float4*)&C[(size_t)m*N + nb]     = make_float4(out[0], out[1], out[2], out[3]);
            *(float4*)&C[(size_t)m*N + nb + 4] = make_float4(out[4], out[5], out[6], out[7]);
        } else {
            #pragma unroll
            for (int j = 0; j < 8; j++)
                if (nb + j < N) C[(size_t)m*N + nb + j] = out[j];
        }
    }
}

// ---------------- small fp32 GEMM (64x64) with runtime M ----------------
__global__ void gemm_tn(const float* __restrict__ A, int lda,
                        const float* __restrict__ W,
                        const float* __restrict__ bias,
                        float* __restrict__ C,
                        int M, int N, int K, int doRelu,
                        const int* __restrict__ Mdev) {
    const int Mv = Mdev ? Mdev[0] : M;
    const int m0 = blockIdx.y * 64, n0 = blockIdx.x * 64;
    if (m0 >= Mv) return;

    __shared__ __align__(16) float As[16][64];
    __shared__ __align__(16) float Bs[16][64];

    const int tid = threadIdx.x;
    const int tx = tid & 15, ty = tid >> 4;

    unsigned long long acc[4][2];
    #pragma unroll
    for (int i = 0; i < 4; i++) { acc[i][0] = 0ULL; acc[i][1] = 0ULL; }

    for (int k0 = 0; k0 < K; k0 += 16) {
        #pragma unroll
        for (int i = 0; i < 4; i++) {
            int idx = tid + i*256;
            int r = idx >> 4, kk = idx & 15;
            int m = m0 + r, k = k0 + kk, n = n0 + r;
            As[kk][r] = (m < Mv && k < K) ? A[(size_t)m*lda + k] : 0.f;
            Bs[kk][r] = (n < N && k < K) ? W[(size_t)n*K + k] : 0.f;
        }
        __syncthreads();
        #pragma unroll
        for (int kk = 0; kk < 16; kk++) {
            float4 a4 = *(const float4*)&As[kk][ty*4];
            float4 b4 = *(const float4*)&Bs[kk][tx*4];
            unsigned long long b01 = fpk(b4.x, b4.y);
            unsigned long long b23 = fpk(b4.z, b4.w);
            unsigned long long a0 = fpk(a4.x, a4.x);
            unsigned long long a1 = fpk(a4.y, a4.y);
            unsigned long long a2 = fpk(a4.z, a4.z);
            unsigned long long a3 = fpk(a4.w, a4.w);
            ffma2(acc[0][0], a0, b01); ffma2(acc[0][1], a0, b23);
            ffma2(acc[1][0], a1, b01); ffma2(acc[1][1], a1, b23);
            ffma2(acc[2][0], a2, b01); ffma2(acc[2][1], a2, b23);
            ffma2(acc[3][0], a3, b01); ffma2(acc[3][1], a3, b23);
        }
        __syncthreads();
    }

    #pragma unroll
    for (int i = 0; i < 4; i++) {
        int m = m0 + ty*4 + i;
        if (m >= Mv) continue;
        float2 v0 = fup(acc[i][0]);
        float2 v1 = fup(acc[i][1]);
        float vals[4] = {v0.x, v0.y, v1.x, v1.y};
        #pragma unroll
        for (int jj = 0; jj < 4; jj++) {
            int n = n0 + tx*4 + jj;
            if (n < N) {
                float o = vals[jj] + bias[n];
                if (doRelu) o = fmaxf(o, 0.f);
                C[(size_t)m*N + n] = o;
            }
        }
    }
}

// ---------------- sequential LSTM (compact rows, per-batch early exit) ----------------
__global__ void lstm_kernel(const float* __restrict__ bhh) {
    int b = blockIdx.x;
    int j = threadIdx.x;
    __shared__ __align__(16) float hs[Hn];

    const int steps = g_bcnt[b];
    const int base_row = g_bstart[b];

    float m = g_m0[b*Hn + j];
    hs[j] = g_h0[b*Hn + j];
    float bi = bhh[j], bf = bhh[256 + j], bg = bhh[512 + j], bo = bhh[768 + j];
    const ulonglong2* W2 = reinterpret_cast<const ulonglong2*>(g_whhR4);
    __syncthreads();

    for (int t = 0; t < steps; t++) {
        unsigned long long aIF = 0ULL, aGO = 0ULL;
        #pragma unroll 4
        for (int k0 = 0; k0 < Hn; k0 += 4) {
            float4 h4 = *(const float4*)&hs[k0];
            ulonglong2 w;
            unsigned long long hd;
            w = W2[(k0+0)*Hn + j]; hd = fpk(h4.x, h4.x); ffma2(aIF, hd, w.x); ffma2(aGO, hd, w.y);
            w = W2[(k0+1)*Hn + j]; hd = fpk(h4.y, h4.y); ffma2(aIF, hd, w.x); ffma2(aGO, hd, w.y);
            w = W2[(k0+2)*Hn + j]; hd = fpk(h4.z, h4.z); ffma2(aIF, hd, w.x); ffma2(aGO, hd, w.y);
            w = W2[(k0+3)*Hn + j]; hd = fpk(h4.w, h4.w); ffma2(aIF, hd, w.x); ffma2(aGO, hd, w.y);
        }
        float2 IF = fup(aIF), GO = fup(aGO);
        size_t base = (size_t)(base_row + t) * (4*Hn) + j;
        float gi = g_xg[base]        + bi + IF.x;
        float gf = g_xg[base + 256]  + bf + IF.y;
        float gg = g_xg[base + 512]  + bg + GO.x;
        float go = g_xg[base + 768]  + bo + GO.y;
        m = sigm(gf)*m + sigm(gi)*tanhf(gg);
        float hn = sigm(go)*tanhf(m);
        __syncthreads();
        hs[j] = hn;
        g_hs[(size_t)(base_row + t)*Hn + j] = hn;
        __syncthreads();
    }
}

// ---------------- fused attention per (b,t), compact-aware, fused chh split ----------------
__global__ void attn_kernel(const float* __restrict__ image,
                            const float* __restrict__ Wz,
                            const float* __restrict__ bz,
                            float* __restrict__ dout) {
    int bt = blockIdx.x;
    int b = bt / STEPS;
    int tid = threadIdx.x;             // 128
    int wid = tid >> 5, lane = tid & 31;
    int v = g_rmap[bt];

    if (v < 0) {
        if (tid < Pn+1)
            dout[ATT_OFF + (size_t)bt*(Pn+1) + tid] = 0.f;
        return;
    }

    __shared__ float shh2[Hn], shh[Hn], ss[Hn], ss2[Hn];
    __shared__ float zz[Pn+1], aw[Pn+1];

    for (int k = tid; k < Hn; k += 128) {
        shh2[k] = g_hh2[(size_t)v*Hn + k];
        shh [k] = g_fo [(size_t)v*2*En + k];
        ss  [k] = g_fo [(size_t)v*2*En + En + k];
        ss2 [k] = g_ss2[(size_t)v*Hn + k];
    }
    __syncthreads();

    for (int p = wid; p < Pn+1; p += 4) {
        float part = 0.f;
        const float* vrow = (p < Pn) ? (g_v + (size_t)(b*Pn + p)*Hn) : ss2;
        for (int k = lane; k < Hn; k += 32)
            part += Wz[k] * tanhf(vrow[k] + shh2[k]);
        #pragma unroll
        for (int off = 16; off > 0; off >>= 1)
            part += __shfl_down_sync(0xffffffff, part, off);
        if (lane == 0) zz[p] = part + bz[0];
    }
    __syncthreads();

    if (tid == 0) {
        float mx = zz[0];
        for (int p = 1; p < Pn+1; p++) mx = fmaxf(mx, zz[p]);
        float s = 0.f;
        for (int p = 0; p < Pn+1; p++) { float e = __expf(zz[p]-mx); aw[p] = e; s += e; }
        float inv = 1.f / s;
        for (int p = 0; p < Pn+1; p++) aw[p] *= inv;
    }
    __syncthreads();

    if (tid < Pn+1)
        dout[ATT_OFF + (size_t)bt*(Pn+1) + tid] = aw[tid];

    // chh = c + hh, split to bf16 hi/lo inline (2 elements per thread)
    #pragma unroll
    for (int kk = 0; kk < 2; kk++) {
        int k = tid + kk*128;
        float c = aw[Pn] * ss[k];
        #pragma unroll 7
        for (int p = 0; p < Pn; p++)
            c = fmaf(aw[p], image[(size_t)(b*Pn + p)*En + k], c);
        float f = c + shh[k];
        __nv_bfloat16 hb = __float2bfloat16_rn(f);
        float r = f - __bfloat162float(hb);
        g_chh_h[(size_t)v*En + k] = hb;
        g_chh_l[(size_t)v*En + k] = __float2bfloat16_rn(r);
    }
}

// ============== tensor-core logits GEMM via mma.sync (bf16 hi/lo, fp32 acc) ==============
#define LTK 64
#define LCHUNK_B (128*LTK*2)            // 16384 bytes per tile buffer
#define LOGITS_SMEM (4*LCHUNK_B)        // 65536

__device__ __forceinline__ void load_chunk(__nv_bfloat16* dst,
                                           const __nv_bfloat16* __restrict__ src,
                                           int row0, int rows_valid, int kc, int tid) {
    #pragma unroll
    for (int i = 0; i < 4; i++) {
        int idx = tid + i*256;
        int row = idx >> 3, ch = idx & 7;
        uint32_t off = (uint32_t)(row*128 + ch*16);
        off ^= (off >> 3) & 0x70;
        int gr = row0 + row;
        uint4 v = (gr < rows_valid) ? *(const uint4*)(src + (size_t)gr*256 + kc + ch*8)
                                    : make_uint4(0u, 0u, 0u, 0u);
        *(uint4*)((char*)dst + off) = v;
    }
}

__global__ __launch_bounds__(256)
void logits_mma(const __nv_bfloat16* __restrict__ Ah, const __nv_bfloat16* __restrict__ Al,
                const __nv_bfloat16* __restrict__ Bh, const __nv_bfloat16* __restrict__ Bl,
                const float* __restrict__ bp, float* __restrict__ out,
                const int* __restrict__ Vdev) {
    const int V = Vdev[0];
    const int m0 = blockIdx.y * 128;
    if (m0 >= V) return;
    const int n0 = blockIdx.x * 128;

    extern __shared__ char smem[];
    __nv_bfloat16* sAh = (__nv_bfloat16*)smem;
    __nv_bfloat16* sAl = (__nv_bfloat16*)(smem + LCHUNK_B);
    __nv_bfloat16* sBh = (__nv_bfloat16*)(smem + 2*LCHUNK_B);
    __nv_bfloat16* sBl = (__nv_bfloat16*)(smem + 3*LCHUNK_B);
    const uint32_t uAh = smem_u32(sAh), uAl = smem_u32(sAl);
    const uint32_t uBh = smem_u32(sBh), uBl = smem_u32(sBl);

    const int tid = threadIdx.x;
    const int wid = tid >> 5, lane = tid & 31;
    const int wm = wid >> 2;      // 0..1
    const int wn = wid & 3;       // 0..3

    float acc[4][4][4];
    #pragma unroll
    for (int a = 0; a < 4; a++)
        #pragma unroll
        for (int b = 0; b < 4; b++)
            #pragma unroll
            for (int c = 0; c < 4; c++) acc[a][b][c] = 0.f;

    const int a_lr = lane & 15, a_lc = lane >> 4;
    const int b_lr = lane & 7,  b_lc = (lane >> 3) & 1;

    for (int kc = 0; kc < En; kc += LTK) {
        load_chunk(sAh, Ah, m0, V, kc, tid);
        load_chunk(sAl, Al, m0, V, kc, tid);
        load_chunk(sBh, Bh, n0, Vn, kc, tid);
        load_chunk(sBl, Bl, n0, Vn, kc, tid);
        __syncthreads();

        #pragma unroll
        for (int ks = 0; ks < LTK/16; ks++) {
            uint32_t ah[4][4], al[4][4], bh[4][2], bl[4][2];
            #pragma unroll
            for (int mt = 0; mt < 4; mt++) {
                uint32_t off = (uint32_t)((wm*64 + mt*16 + a_lr)*128 + ks*32 + a_lc*16);
                off ^= (off >> 3) & 0x70;
                ldsm4(ah[mt], uAh + off);
                ldsm4(al[mt], uAl + off);
            }
            #pragma unroll
            for (int nt = 0; nt < 4; nt++) {
                uint32_t off = (uint32_t)((wn*32 + nt*8 + b_lr)*128 + ks*32 + b_lc*16);
                off ^= (off >> 3) & 0x70;
                ldsm2(bh[nt], uBh + off);
                ldsm2(bl[nt], uBl + off);
            }
            #pragma unroll
            for (int mt = 0; mt < 4; mt++)
                #pragma unroll
                for (int nt = 0; nt < 4; nt++)
                    mma_bf16(acc[mt][nt], ah[mt], bh[nt]);
            #pragma unroll
            for (int mt = 0; mt < 4; mt++)
                #pragma unroll
                for (int nt = 0; nt < 4; nt++)
                    mma_bf16(acc[mt][nt], ah[mt], bl[nt]);
            #pragma unroll
            for (int mt = 0; mt < 4; mt++)
                #pragma unroll
                for (int nt = 0; nt < 4; nt++)
                    mma_bf16(acc[mt][nt], al[mt], bh[nt]);
        }
        __syncthreads();
    }

    #pragma unroll
    for (int mt = 0; mt < 4; mt++) {
        int m1 = m0 + wm*64 + mt*16 + (lane >> 2);
        int m2 = m1 + 8;
        #pragma unroll
        for (int nt = 0; nt < 4; nt++) {
            int n = n0 + wn*32 + nt*8 + (lane & 3)*2;
            float2 bb = *(const float2*)&bp[n];
            const float* c = acc[mt][nt];
            if (m1 < V)
                *(float2*)&out[(size_t)m1*Vn + n] = make_float2(c[0] + bb.x, c[1] + bb.y);
            if (m2 < V)
                *(float2*)&out[(size_t)m2*Vn + n] = make_float2(c[2] + bb.x, c[3] + bb.y);
        }
    }
}

// ---------------- online log-softmax + argmax + mask + output ----------------
__global__ void softmax_kernel(const float* __restrict__ temp,
                               float* __restrict__ dout) {
    int bt = blockIdx.x;
    int b = bt / STEPS;
    int tid = threadIdx.x;             // 512
    int crow = g_rmap[bt];
    float4* lp4 = (float4*)(dout + LOGP_OFF + (size_t)bt*Vn);

    __shared__ float smx[512]; __shared__ int sai[512]; __shared__ float ssum[512];

    if (crow < 0) {
        float4 z = make_float4(0.f, 0.f, 0.f, 0.f);
        for (int i = tid; i < Vn/4; i += 512) lp4[i] = z;
        if (tid == 0) dout[TXT_OFF + bt] = 0.f;
        return;
    }

    float ls = 1.0f / temp[b];
    const float4* row4 = (const float4*)(g_logits + (size_t)crow*Vn);

    float mx = -3.402823466e38f; float sum = 0.f; int ai = 0;
    for (int i = tid; i < Vn/4; i += 512) {
        float4 v = row4[i];
        float vv[4] = {v.x, v.y, v.z, v.w};
        #pragma unroll
        for (int c = 0; c < 4; c++) {
            float x = vv[c];
            if (x > mx) {
                sum = sum * __expf((mx - x)*ls) + 1.f;
                mx = x; ai = 4*i + c;
            } else {
                sum += __expf((x - mx)*ls);
            }
        }
    }
    smx[tid] = mx; sai[tid] = ai; ssum[tid] = sum; __syncthreads();
    for (int s = 256; s > 0; s >>= 1) {
        if (tid < s) {
            float m1 = smx[tid],   m2 = smx[tid+s];
            float s1 = ssum[tid],  s2 = ssum[tid+s];
            int   i1 = sai[tid],   i2 = sai[tid+s];
            if (m2 > m1 || (m2 == m1 && i2 < i1)) {
                smx[tid] = m2; sai[tid] = i2;
                ssum[tid] = s2 + s1 * __expf((m1 - m2)*ls);
            } else {
                ssum[tid] = s1 + s2 * __expf((m2 - m1)*ls);
            }
        }
        __syncthreads();
    }
    mx = smx[0]; ai = sai[0];
    float lse = logf(ssum[0]);

    for (int i = tid; i < Vn/4; i += 512) {
        float4 v = row4[i];
        float4 o;
        o.x = (v.x - mx)*ls - lse;
        o.y = (v.y - mx)*ls - lse;
        o.z = (v.z - mx)*ls - lse;
        o.w = (v.w - mx)*ls - lse;
        lp4[i] = o;
    }
    if (tid == 0) dout[TXT_OFF + bt] = (float)ai;
}

// ---------------- launcher ----------------
extern "C" void kernel_launch(void* const* d_in, const int* in_sizes, int n_in,
                              void* d_out, int out_size) {
    const float* image = (const float*)d_in[0];
    const float* vp    = (const float*)d_in[1];
    const float* label = (const float*)d_in[2];
    const float* topic = (const float*)d_in[3];
    const float* temp  = (const float*)d_in[4];
    const int*   text  = (const int*)  d_in[5];
    const int*   length= (const int*)  d_in[6];
    const float* emb   = (const float*)d_in[7];
    const float* Wv    = (const float*)d_in[8];
    const float* bv    = (const float*)d_in[9];
    const float* Wh    = (const float*)d_in[10];
    const float* bh    = (const float*)d_in[11];
    const float* Wm    = (const float*)d_in[12];
    const float* bm    = (const float*)d_in[13];
    const float* Wih   = (const float*)d_in[14];
    const float* bih   = (const float*)d_in[15];
    const float* Whh   = (const float*)d_in[16];
    const float* bhh   = (const float*)d_in[17];
    const float* Wfc   = (const float*)d_in[18];
    const float* bfc   = (const float*)d_in[19];
    const float* Whh2  = (const float*)d_in[20];
    const float* bhh2  = (const float*)d_in[21];
    const float* Ws    = (const float*)d_in[22];
    const float* bs    = (const float*)d_in[23];
    const float* Wz    = (const float*)d_in[24];
    const float* bz    = (const float*)d_in[25];
    const float* Wp    = (const float*)d_in[26];
    const float* bp    = (const float*)d_in[27];
    float* dout = (float*)d_out;

    float *p_xcat, *p_xg, *p_v, *p_hs, *p_fo, *p_hh2, *p_ss2, *p_logits;
    __nv_bfloat16 *p_wph, *p_wpl, *p_chh_h, *p_chh_l;
    int *p_V;
    cudaGetSymbolAddress((void**)&p_xcat,   g_xcat);
    cudaGetSymbolAddress((void**)&p_xg,     g_xg);
    cudaGetSymbolAddress((void**)&p_v,      g_v);
    cudaGetSymbolAddress((void**)&p_hs,     g_hs);
    cudaGetSymbolAddress((void**)&p_fo,     g_fo);
    cudaGetSymbolAddress((void**)&p_hh2,    g_hh2);
    cudaGetSymbolAddress((void**)&p_ss2,    g_ss2);
    cudaGetSymbolAddress((void**)&p_logits, g_logits);
    cudaGetSymbolAddress((void**)&p_wph,    g_wph);
    cudaGetSymbolAddress((void**)&p_wpl,    g_wpl);
    cudaGetSymbolAddress((void**)&p_chh_h,  g_chh_h);
    cudaGetSymbolAddress((void**)&p_chh_l,  g_chh_l);
    cudaGetSymbolAddress((void**)&p_V,      g_V);

    cudaFuncSetAttribute(logits_mma, cudaFuncAttributeMaxDynamicSharedMemorySize,
                         LOGITS_SMEM);

    // valid-row maps + Wp hi/lo split (independent)
    build_maps<<<1, 256>>>(length);
    split_bf16<<<(Vn*En/4 + 255)/256, 256>>>(Wp, p_wph, p_wpl, Vn*En/4);

    prep_kernel<<<Bn, 256>>>(image, vp, label, topic, Wh, bh, Wm, bm);
    whh_transpose<<<Hn, Hn>>>(Whh);
    xcat_kernel<<<ROWS, 256>>>(text, emb);   // compact rows

    // Xg = Xcat @ Wih^T + bih on COMPACT rows : (V x 1024), K=792
    gemm_tn128<<<dim3((4*Hn+127)/128, (ROWS+127)/128), 256>>>(p_xcat, INn, Wih, bih, p_xg,
                                                              ROWS, 4*Hn, INn, 0, p_V);
    // v = image @ Wv^T + bv (all rows)
    gemm_tn<<<dim3((Hn+63)/64, (Bn*Pn+63)/64), 256>>>(image, En, Wv, bv, p_v,
                                                      Bn*Pn, Hn, En, 0, nullptr);
    // sequential LSTM on compact rows, per-batch early exit
    lstm_kernel<<<Bn, 256>>>(bhh);

    // fo = relu(Hs @ Wfc^T + bfc) on compact rows
    gemm_tn<<<dim3((2*En+63)/64, (ROWS+63)/64), 256>>>(p_hs, Hn, Wfc, bfc, p_fo,
                                                       ROWS, 2*En, Hn, 1, p_V);
    // _hh, _s on compact rows
    gemm_tn<<<dim3((Hn+63)/64, (ROWS+63)/64), 256>>>(p_fo, 2*En, Whh2, bhh2, p_hh2,
                                                     ROWS, Hn, En, 0, p_V);
    gemm_tn<<<dim3((Hn+63)/64, (ROWS+63)/64), 256>>>(p_fo + En, 2*En, Ws, bs, p_ss2,
                                                     ROWS, Hn, En, 0, p_V);
    // attention: att out + chh bf16 hi/lo split fused into epilogue
    attn_kernel<<<ROWS, 128>>>(image, Wz, bz, dout);

    // tensor-core logits GEMM (compact rows)
    logits_mma<<<dim3(Vn/128, (ROWS+127)/128), 256, LOGITS_SMEM>>>(
        p_chh_h, p_chh_l, p_wph, p_wpl, bp, p_logits, p_V);

    // online log-softmax + argmax + masking + outputs
    softmax_kernel<<<ROWS, 512>>>(temp, dout);
}

// round 13
// speedup vs baseline: 1.2986x; 1.0203x over previous
#include <cuda_runtime.h>
#include <cuda_bf16.h>
#include <math.h>
#include <stdint.h>

// ---------------- problem constants ----------------
#define Bn 32
#define Pn 49
#define En 256
#define Hn 256
#define Tn 48
#define STEPS 47
#define Vn 32000
#define INn 792          // E + VP + LB + H + E
#define XSn 536          // E + VP + LB + H
#define ROWS (Bn*STEPS)  // 1504

#define ATT_OFF 0
#define LOGP_OFF (ROWS*(Pn+1))                 // 75200
#define TXT_OFF  (LOGP_OFF + (size_t)ROWS*Vn)

// ---------------- scratch (device globals; no allocation) ----------------
__device__ float g_xs  [Bn*XSn];
__device__ float g_h0  [Bn*Hn];
__device__ float g_m0  [Bn*Hn];
__device__ float g_xcat[ROWS*INn];          // compact rows
__device__ float g_xg  [ROWS*4*Hn];         // compact rows
__device__ float4 g_whhR4[Hn*Hn];
__device__ float g_v   [Bn*Pn*Hn];
__device__ float g_hs  [ROWS*Hn];           // compact rows
__device__ float g_fo  [ROWS*2*En];         // compact rows
__device__ float g_hh2 [ROWS*Hn];           // compact rows
__device__ float g_ss2 [ROWS*Hn];           // compact rows
__device__ float g_logits[(size_t)ROWS*Vn]; // compact rows (~192 MB cap)

// valid-row compaction maps
__device__ int g_V[1];
__device__ int g_rmap[ROWS];   // bt -> compact index (or -1)
__device__ int g_bcnt[Bn];     // valid steps per batch
__device__ int g_bstart[Bn];   // compact row offset per batch

// bf16 hi/lo splits for tensor-core logits GEMM
__device__ __align__(256) __nv_bfloat16 g_wph[(size_t)Vn*En];
__device__ __align__(256) __nv_bfloat16 g_wpl[(size_t)Vn*En];
__device__ __align__(256) __nv_bfloat16 g_chh_h[ROWS*En];
__device__ __align__(256) __nv_bfloat16 g_chh_l[ROWS*En];

// ---------------- packed f32x2 helpers (Blackwell FFMA2) ----------------
__device__ __forceinline__ unsigned long long fpk(float lo, float hi) {
    unsigned long long r;
    asm("mov.b64 %0, {%1, %2};" : "=l"(r) : "f"(lo), "f"(hi));
    return r;
}
__device__ __forceinline__ void ffma2(unsigned long long& d,
                                      unsigned long long a,
                                      unsigned long long b) {
    asm("fma.rn.f32x2 %0, %1, %2, %3;" : "=l"(d) : "l"(a), "l"(b), "l"(d));
}
__device__ __forceinline__ float2 fup(unsigned long long v) {
    float2 r;
    asm("mov.b64 {%0, %1}, %2;" : "=f"(r.x), "=f"(r.y) : "l"(v));
    return r;
}
__device__ __forceinline__ float sigm(float x) {
    return 1.0f / (1.0f + __expf(-x));
}
__device__ __forceinline__ uint32_t smem_u32(const void* p) {
    uint32_t a;
    asm("{ .reg .u64 t; cvta.to.shared.u64 t, %1; cvt.u32.u64 %0, t; }"
        : "=r"(a) : "l"(p));
    return a;
}

// ---------------- warp-level tensor core helpers (sm_80+ ISA) ----------------
__device__ __forceinline__ void ldsm4(uint32_t* r, uint32_t addr) {
    asm volatile("ldmatrix.sync.aligned.m8n8.x4.shared.b16 {%0,%1,%2,%3}, [%4];"
        : "=r"(r[0]), "=r"(r[1]), "=r"(r[2]), "=r"(r[3]) : "r"(addr));
}
__device__ __forceinline__ void ldsm2(uint32_t* r, uint32_t addr) {
    asm volatile("ldmatrix.sync.aligned.m8n8.x2.shared.b16 {%0,%1}, [%2];"
        : "=r"(r[0]), "=r"(r[1]) : "r"(addr));
}
__device__ __forceinline__ void mma_bf16(float* c, const uint32_t* a, const uint32_t* b) {
    asm volatile(
        "mma.sync.aligned.m16n8k16.row.col.f32.bf16.bf16.f32 "
        "{%0,%1,%2,%3}, {%4,%5,%6,%7}, {%8,%9}, {%0,%1,%2,%3};"
        : "+f"(c[0]), "+f"(c[1]), "+f"(c[2]), "+f"(c[3])
        : "r"(a[0]), "r"(a[1]), "r"(a[2]), "r"(a[3]), "r"(b[0]), "r"(b[1]));
}

// ---------------- valid-row maps ----------------
__global__ void build_maps(const int* __restrict__ length) {
    __shared__ int cnt[Bn], start[Bn];
    int tid = threadIdx.x;
    if (tid < Bn) {
        int c = length[tid] - 1;
        if (c < 0) c = 0;
        if (c > STEPS) c = STEPS;
        cnt[tid] = c;
        g_bcnt[tid] = c;
    }
    __syncthreads();
    if (tid == 0) {
        int s = 0;
        for (int b = 0; b < Bn; b++) { start[b] = s; g_bstart[b] = s; s += cnt[b]; }
        g_V[0] = s;
    }
    __syncthreads();
    for (int bt = tid; bt < ROWS; bt += 256) {
        int b = bt / STEPS, t = bt % STEPS;
        g_rmap[bt] = (t < cnt[b]) ? (start[b] + t) : -1;
    }
}

// ---------------- prep: image_mean, x_static, h0, m0 ----------------
__global__ void prep_kernel(const float* __restrict__ image,
                            const float* __restrict__ vp,
                            const float* __restrict__ label,
                            const float* __restrict__ topic,
                            const float* __restrict__ Wh, const float* __restrict__ bh,
                            const float* __restrict__ Wm, const float* __restrict__ bm) {
    int b = blockIdx.x;
    int tid = threadIdx.x;   // 256
    __shared__ __align__(16) float im[En];

    float s = 0.f;
    #pragma unroll 7
    for (int p = 0; p < Pn; p++) s += image[(b*Pn + p)*En + tid];
    float mean = s * (1.0f/49.0f);
    im[tid] = mean;

    g_xs[b*XSn + tid] = mean;
    if (tid < 8)  g_xs[b*XSn + 256 + tid] = vp[b*8 + tid];
    if (tid < 16) g_xs[b*XSn + 264 + tid] = label[b*16 + tid];
    g_xs[b*XSn + 280 + tid] = topic[b*Hn + tid];
    __syncthreads();

    float ah = bh[tid], am = bm[tid];
    #pragma unroll 8
    for (int k = 0; k < En; k++) {
        float x = im[k];
        ah = fmaf(x, Wh[tid*En + k], ah);
        am = fmaf(x, Wm[tid*En + k], am);
    }
    g_h0[b*Hn + tid] = tanhf(ah);
    g_m0[b*Hn + tid] = tanhf(am);
}

// ---------------- Whh reorder for coalesced LSTM reads ----------------
__global__ void whh_transpose(const float* __restrict__ Whh) {
    int k = blockIdx.x;
    int j = threadIdx.x;
    float4 w;
    w.x = Whh[(0*Hn + j)*Hn + k];
    w.y = Whh[(1*Hn + j)*Hn + k];
    w.z = Whh[(2*Hn + j)*Hn + k];
    w.w = Whh[(3*Hn + j)*Hn + k];
    g_whhR4[k*Hn + j] = w;
}

// ---------------- build concat rows (compact) ----------------
__global__ void xcat_kernel(const int* __restrict__ text,
                            const float* __restrict__ emb) {
    int bt = blockIdx.x;
    int v = g_rmap[bt];
    if (v < 0) return;
    int b = bt / STEPS, t = bt % STEPS;
    int tid = threadIdx.x;
    int tok = text[b*Tn + t];
    float* row = g_xcat + (size_t)v*INn;
    for (int i = tid; i < XSn; i += 256) row[i] = g_xs[b*XSn + i];
    row[XSn + tid] = emb[(size_t)tok*En + tid];
}

// ---------------- bf16 hi/lo split (for Wp) ----------------
__global__ void split_bf16(const float* __restrict__ src,
                           __nv_bfloat16* __restrict__ hi,
                           __nv_bfloat16* __restrict__ lo, int n4) {
    int i = blockIdx.x*256 + threadIdx.x;
    if (i >= n4) return;
    float4 v = ((const float4*)src)[i];
    float f[4] = {v.x, v.y, v.z, v.w};
    unsigned short h[4], l[4];
    #pragma unroll
    for (int k = 0; k < 4; k++) {
        __nv_bfloat16 hb = __float2bfloat16_rn(f[k]);
        float r = f[k] - __bfloat162float(hb);
        __nv_bfloat16 lb = __float2bfloat16_rn(r);
        h[k] = __bfloat16_as_ushort(hb);
        l[k] = __bfloat16_as_ushort(lb);
    }
    uint2 uh, ul;
    uh.x = (uint32_t)h[0] | ((uint32_t)h[1] << 16);
    uh.y = (uint32_t)h[2] | ((uint32_t)h[3] << 16);
    ul.x = (uint32_t)l[0] | ((uint32_t)l[1] << 16);
    ul.y = (uint32_t)l[2] | ((uint32_t)l[3] << 16);
    ((uint2*)hi)[i] = uh;
    ((uint2*)lo)[i] = ul;
}

// ============== SIMT fp32 GEMM (128x128), runtime M ==============
#define SPAD 132
__global__ __launch_bounds__(256, 2)
void gemm_tn128(const float* __restrict__ A, int lda,
                const float* __restrict__ W,
                const float* __restrict__ bias,
                float* __restrict__ C,
                int M, int N, int K, int doRelu,
                const int* __restrict__ Mdev) {
    const int Mv = Mdev ? Mdev[0] : M;
    const int m0 = blockIdx.y * 128, n0 = blockIdx.x * 128;
    if (m0 >= Mv) return;

    __shared__ __align__(16) float As[2][16][SPAD];
    __shared__ __align__(16) float Bs[2][16][SPAD];

    const int tid = threadIdx.x;
    const int tx = tid & 15, ty = tid >> 4;

    const int lr = tid >> 2;
    const int lk = (tid & 3) * 4;

    unsigned long long acc[8][4];
    #pragma unroll
    for (int i = 0; i < 8; i++)
        #pragma unroll
        for (int j = 0; j < 4; j++) acc[i][j] = 0ULL;

    const int KT = (K + 15) / 16;
    const float4 z4 = make_float4(0.f, 0.f, 0.f, 0.f);
    float4 fa0, fa1, fb0, fb1;

    {
        int k = lk;
        bool kok = (k < K);
        int mA0 = m0 + lr, mA1 = m0 + lr + 64;
        int nB0 = n0 + lr, nB1 = n0 + lr + 64;
        fa0 = (kok && mA0 < Mv) ? *(const float4*)&A[(size_t)mA0*lda + k] : z4;
        fa1 = (kok && mA1 < Mv) ? *(const float4*)&A[(size_t)mA1*lda + k] : z4;
        fb0 = (kok && nB0 < N) ? *(const float4*)&W[(size_t)nB0*K + k] : z4;
        fb1 = (kok && nB1 < N) ? *(const float4*)&W[(size_t)nB1*K + k] : z4;
    }
    As[0][lk+0][lr] = fa0.x; As[0][lk+1][lr] = fa0.y; As[0][lk+2][lr] = fa0.z; As[0][lk+3][lr] = fa0.w;
    As[0][lk+0][lr+64] = fa1.x; As[0][lk+1][lr+64] = fa1.y; As[0][lk+2][lr+64] = fa1.z; As[0][lk+3][lr+64] = fa1.w;
    Bs[0][lk+0][lr] = fb0.x; Bs[0][lk+1][lr] = fb0.y; Bs[0][lk+2][lr] = fb0.z; Bs[0][lk+3][lr] = fb0.w;
    Bs[0][lk+0][lr+64] = fb1.x; Bs[0][lk+1][lr+64] = fb1.y; Bs[0][lk+2][lr+64] = fb1.z; Bs[0][lk+3][lr+64] = fb1.w;
    __syncthreads();

    for (int kt = 0; kt < KT; kt++) {
        int cur = kt & 1;
        if (kt + 1 < KT) {
            int k = (kt + 1) * 16 + lk;
            bool kok = (k < K);
            int mA0 = m0 + lr, mA1 = m0 + lr + 64;
            int nB0 = n0 + lr, nB1 = n0 + lr + 64;
            fa0 = (kok && mA0 < Mv) ? *(const float4*)&A[(size_t)mA0*lda + k] : z4;
            fa1 = (kok && mA1 < Mv) ? *(const float4*)&A[(size_t)mA1*lda + k] : z4;
            fb0 = (kok && nB0 < N) ? *(const float4*)&W[(size_t)nB0*K + k] : z4;
            fb1 = (kok && nB1 < N) ? *(const float4*)&W[(size_t)nB1*K + k] : z4;
        }
        #pragma unroll
        for (int kk = 0; kk < 16; kk++) {
            float4 a0 = *(const float4*)&As[cur][kk][ty*8];
            float4 a1 = *(const float4*)&As[cur][kk][ty*8 + 4];
            float4 b0 = *(const float4*)&Bs[cur][kk][tx*8];
            float4 b1 = *(const float4*)&Bs[cur][kk][tx*8 + 4];
            unsigned long long bp0 = fpk(b0.x, b0.y);
            unsigned long long bp1 = fpk(b0.z, b0.w);
            unsigned long long bp2 = fpk(b1.x, b1.y);
            unsigned long long bp3 = fpk(b1.z, b1.w);
            float av[8] = {a0.x, a0.y, a0.z, a0.w, a1.x, a1.y, a1.z, a1.w};
            #pragma unroll
            for (int i = 0; i < 8; i++) {
                unsigned long long ad = fpk(av[i], av[i]);
                ffma2(acc[i][0], ad, bp0);
                ffma2(acc[i][1], ad, bp1);
                ffma2(acc[i][2], ad, bp2);
                ffma2(acc[i][3], ad, bp3);
            }
        }
        if (kt + 1 < KT) {
            int nxt = cur ^ 1;
            As[nxt][lk+0][lr] = fa0.x; As[nxt][lk+1][lr] = fa0.y; As[nxt][lk+2][lr] = fa0.z; As[nxt][lk+3][lr] = fa0.w;
            As[nxt][lk+0][lr+64] = fa1.x; As[nxt][lk+1][lr+64] = fa1.y; As[nxt][lk+2][lr+64] = fa1.z; As[nxt][lk+3][lr+64] = fa1.w;
            Bs[nxt][lk+0][lr] = fb0.x; Bs[nxt][lk+1][lr] = fb0.y; Bs[nxt][lk+2][lr] = fb0.z; Bs[nxt][lk+3][lr] = fb0.w;
            Bs[nxt][lk+0][lr+64] = fb1.x; Bs[nxt][lk+1][lr+64] = fb1.y; Bs[nxt][lk+2][lr+64] = fb1.z; Bs[nxt][lk+3][lr+64] = fb1.w;
            __syncthreads();
        }
    }

    int nb = n0 + tx*8;
    float bvals[8];
    #pragma unroll
    for (int j = 0; j < 8; j++) bvals[j] = (nb + j < N) ? bias[nb + j] : 0.f;

    #pragma unroll
    for (int i = 0; i < 8; i++) {
        int m = m0 + ty*8 + i;
        if (m >= Mv) continue;
        float out[8];
        #pragma unroll
        for (int j = 0; j < 4; j++) {
            float2 v = fup(acc[i][j]);
            out[2*j]   = v.x + bvals[2*j];
            out[2*j+1] = v.y + bvals[2*j+1];
        }
        if (doRelu) {
            #pragma unroll
            for (int j = 0; j < 8; j++) out[j] = fmaxf(out[j], 0.f);
        }
        if (nb + 7 < N) {
            *(float4*)&C[(size_t)m*N + nb]     = make_float4(out[0], out[1], out[2], out[3]);
            *(float4*)&C[(size_t)m*N + nb + 4] = make_float4(out[4], out[5], out[6], out[7]);
        } else {
            #pragma unroll
            for (int j = 0; j < 8; j++)
                if (nb + j < N) C[(size_t)m*N + nb + j] = out[j];
        }
    }
}

// ---------------- small fp32 GEMM (64x64) with runtime M ----------------
__global__ void gemm_tn(const float* __restrict__ A, int lda,
                        const float* __restrict__ W,
                        const float* __restrict__ bias,
                        float* __restrict__ C,
                        int M, int N, int K, int doRelu,
                        const int* __restrict__ Mdev) {
    const int Mv = Mdev ? Mdev[0] : M;
    const int m0 = blockIdx.y * 64, n0 = blockIdx.x * 64;
    if (m0 >= Mv) return;

    __shared__ __align__(16) float As[16][64];
    __shared__ __align__(16) float Bs[16][64];

    const int tid = threadIdx.x;
    const int tx = tid & 15, ty = tid >> 4;

    unsigned long long acc[4][2];
    #pragma unroll
    for (int i = 0; i < 4; i++) { acc[i][0] = 0ULL; acc[i][1] = 0ULL; }

    for (int k0 = 0; k0 < K; k0 += 16) {
        #pragma unroll
        for (int i = 0; i < 4; i++) {
            int idx = tid + i*256;
            int r = idx >> 4, kk = idx & 15;
            int m = m0 + r, k = k0 + kk, n = n0 + r;
            As[kk][r] = (m < Mv && k < K) ? A[(size_t)m*lda + k] : 0.f;
            Bs[kk][r] = (n < N && k < K) ? W[(size_t)n*K + k] : 0.f;
        }
        __syncthreads();
        #pragma unroll
        for (int kk = 0; kk < 16; kk++) {
            float4 a4 = *(const float4*)&As[kk][ty*4];
            float4 b4 = *(const float4*)&Bs[kk][tx*4];
            unsigned long long b01 = fpk(b4.x, b4.y);
            unsigned long long b23 = fpk(b4.z, b4.w);
            unsigned long long a0 = fpk(a4.x, a4.x);
            unsigned long long a1 = fpk(a4.y, a4.y);
            unsigned long long a2 = fpk(a4.z, a4.z);
            unsigned long long a3 = fpk(a4.w, a4.w);
            ffma2(acc[0][0], a0, b01); ffma2(acc[0][1], a0, b23);
            ffma2(acc[1][0], a1, b01); ffma2(acc[1][1], a1, b23);
            ffma2(acc[2][0], a2, b01); ffma2(acc[2][1], a2, b23);
            ffma2(acc[3][0], a3, b01); ffma2(acc[3][1], a3, b23);
        }
        __syncthreads();
    }

    #pragma unroll
    for (int i = 0; i < 4; i++) {
        int m = m0 + ty*4 + i;
        if (m >= Mv) continue;
        float2 v0 = fup(acc[i][0]);
        float2 v1 = fup(acc[i][1]);
        float vals[4] = {v0.x, v0.y, v1.x, v1.y};
        #pragma unroll
        for (int jj = 0; jj < 4; jj++) {
            int n = n0 + tx*4 + jj;
            if (n < N) {
                float o = vals[jj] + bias[n];
                if (doRelu) o = fmaxf(o, 0.f);
                C[(size_t)m*N + n] = o;
            }
        }
    }
}

// ---------------- sequential LSTM (compact rows, per-batch early exit) ----------------
__global__ void lstm_kernel(const float* __restrict__ bhh) {
    int b = blockIdx.x;
    int j = threadIdx.x;
    __shared__ __align__(16) float hs[Hn];

    const int steps = g_bcnt[b];
    const int base_row = g_bstart[b];

    float m = g_m0[b*Hn + j];
    hs[j] = g_h0[b*Hn + j];
    float bi = bhh[j], bf = bhh[256 + j], bg = bhh[512 + j], bo = bhh[768 + j];
    const ulonglong2* W2 = reinterpret_cast<const ulonglong2*>(g_whhR4);
    __syncthreads();

    for (int t = 0; t < steps; t++) {
        unsigned long long aIF = 0ULL, aGO = 0ULL;
        #pragma unroll 4
        for (int k0 = 0; k0 < Hn; k0 += 4) {
            float4 h4 = *(const float4*)&hs[k0];
            ulonglong2 w;
            unsigned long long hd;
            w = W2[(k0+0)*Hn + j]; hd = fpk(h4.x, h4.x); ffma2(aIF, hd, w.x); ffma2(aGO, hd, w.y);
            w = W2[(k0+1)*Hn + j]; hd = fpk(h4.y, h4.y); ffma2(aIF, hd, w.x); ffma2(aGO, hd, w.y);
            w = W2[(k0+2)*Hn + j]; hd = fpk(h4.z, h4.z); ffma2(aIF, hd, w.x); ffma2(aGO, hd, w.y);
            w = W2[(k0+3)*Hn + j]; hd = fpk(h4.w, h4.w); ffma2(aIF, hd, w.x); ffma2(aGO, hd, w.y);
        }
        float2 IF = fup(aIF), GO = fup(aGO);
        size_t base = (size_t)(base_row + t) * (4*Hn) + j;
        float gi = g_xg[base]        + bi + IF.x;
        float gf = g_xg[base + 256]  + bf + IF.y;
        float gg = g_xg[base + 512]  + bg + GO.x;
        float go = g_xg[base + 768]  + bo + GO.y;
        m = sigm(gf)*m + sigm(gi)*tanhf(gg);
        float hn = sigm(go)*tanhf(m);
        __syncthreads();
        hs[j] = hn;
        g_hs[(size_t)(base_row + t)*Hn + j] = hn;
        __syncthreads();
    }
}

// ---------------- fused attention per (b,t), compact-aware, fused chh split ----------------
__global__ void attn_kernel(const float* __restrict__ image,
                            const float* __restrict__ Wz,
                            const float* __restrict__ bz,
                            float* __restrict__ dout) {
    int bt = blockIdx.x;
    int b = bt / STEPS;
    int tid = threadIdx.x;             // 128
    int wid = tid >> 5, lane = tid & 31;
    int v = g_rmap[bt];

    if (v < 0) {
        if (tid < Pn+1)
            dout[ATT_OFF + (size_t)bt*(Pn+1) + tid] = 0.f;
        return;
    }

    __shared__ float shh2[Hn], shh[Hn], ss[Hn], ss2[Hn];
    __shared__ float zz[Pn+1], aw[Pn+1];

    for (int k = tid; k < Hn; k += 128) {
        shh2[k] = g_hh2[(size_t)v*Hn + k];
        shh [k] = g_fo [(size_t)v*2*En + k];
        ss  [k] = g_fo [(size_t)v*2*En + En + k];
        ss2 [k] = g_ss2[(size_t)v*Hn + k];
    }
    __syncthreads();

    for (int p = wid; p < Pn+1; p += 4) {
        float part = 0.f;
        const float* vrow = (p < Pn) ? (g_v + (size_t)(b*Pn + p)*Hn) : ss2;
        for (int k = lane; k < Hn; k += 32)
            part += Wz[k] * tanhf(vrow[k] + shh2[k]);
        #pragma unroll
        for (int off = 16; off > 0; off >>= 1)
            part += __shfl_down_sync(0xffffffff, part, off);
        if (lane == 0) zz[p] = part + bz[0];
    }
    __syncthreads();

    if (tid == 0) {
        float mx = zz[0];
        for (int p = 1; p < Pn+1; p++) mx = fmaxf(mx, zz[p]);
        float s = 0.f;
        for (int p = 0; p < Pn+1; p++) { float e = __expf(zz[p]-mx); aw[p] = e; s += e; }
        float inv = 1.f / s;
        for (int p = 0; p < Pn+1; p++) aw[p] *= inv;
    }
    __syncthreads();

    if (tid < Pn+1)
        dout[ATT_OFF + (size_t)bt*(Pn+1) + tid] = aw[tid];

    // chh = c + hh, split to bf16 hi/lo inline (2 elements per thread)
    #pragma unroll
    for (int kk = 0; kk < 2; kk++) {
        int k = tid + kk*128;
        float c = aw[Pn] * ss[k];
        #pragma unroll 7
        for (int p = 0; p < Pn; p++)
            c = fmaf(aw[p], image[(size_t)(b*Pn + p)*En + k], c);
        float f = c + shh[k];
        __nv_bfloat16 hb = __float2bfloat16_rn(f);
        float r = f - __bfloat162float(hb);
        g_chh_h[(size_t)v*En + k] = hb;
        g_chh_l[(size_t)v*En + k] = __float2bfloat16_rn(r);
    }
}

// ============== tensor-core logits GEMM via mma.sync (bf16 hi/lo, fp32 acc) ==============
// Tile 128x64, 8 warps (4x2), warp tile 32x32, 2 CTAs/SM.
#define LTK 64
#define LCHUNK_A (128*LTK*2)            // 16384 bytes per A buffer
#define LCHUNK_Bt (64*LTK*2)            // 8192 bytes per B buffer
#define LOGITS_SMEM (2*LCHUNK_A + 2*LCHUNK_Bt)   // 49152

__device__ __forceinline__ void load_chunk_a(__nv_bfloat16* dst,
                                             const __nv_bfloat16* __restrict__ src,
                                             int row0, int rows_valid, int kc, int tid) {
    #pragma unroll
    for (int i = 0; i < 4; i++) {       // 128 rows x 8 chunks = 1024
        int idx = tid + i*256;
        int row = idx >> 3, ch = idx & 7;
        uint32_t off = (uint32_t)(row*128 + ch*16);
        off ^= (off >> 3) & 0x70;
        int gr = row0 + row;
        uint4 v = (gr < rows_valid) ? *(const uint4*)(src + (size_t)gr*256 + kc + ch*8)
                                    : make_uint4(0u, 0u, 0u, 0u);
        *(uint4*)((char*)dst + off) = v;
    }
}
__device__ __forceinline__ void load_chunk_b(__nv_bfloat16* dst,
                                             const __nv_bfloat16* __restrict__ src,
                                             int row0, int kc, int tid) {
    #pragma unroll
    for (int i = 0; i < 2; i++) {       // 64 rows x 8 chunks = 512
        int idx = tid + i*256;
        int row = idx >> 3, ch = idx & 7;
        uint32_t off = (uint32_t)(row*128 + ch*16);
        off ^= (off >> 3) & 0x70;
        uint4 v = *(const uint4*)(src + (size_t)(row0 + row)*256 + kc + ch*8);
        *(uint4*)((char*)dst + off) = v;
    }
}

__global__ __launch_bounds__(256, 2)
void logits_mma(const __nv_bfloat16* __restrict__ Ah, const __nv_bfloat16* __restrict__ Al,
                const __nv_bfloat16* __restrict__ Bh, const __nv_bfloat16* __restrict__ Bl,
                const float* __restrict__ bp, float* __restrict__ out,
                const int* __restrict__ Vdev) {
    const int V = Vdev[0];
    const int m0 = blockIdx.y * 128;
    if (m0 >= V) return;
    const int n0 = blockIdx.x * 64;

    extern __shared__ char smem[];
    __nv_bfloat16* sAh = (__nv_bfloat16*)smem;
    __nv_bfloat16* sAl = (__nv_bfloat16*)(smem + LCHUNK_A);
    __nv_bfloat16* sBh = (__nv_bfloat16*)(smem + 2*LCHUNK_A);
    __nv_bfloat16* sBl = (__nv_bfloat16*)(smem + 2*LCHUNK_A + LCHUNK_Bt);
    const uint32_t uAh = smem_u32(sAh), uAl = smem_u32(sAl);
    const uint32_t uBh = smem_u32(sBh), uBl = smem_u32(sBl);

    const int tid = threadIdx.x;
    const int wid = tid >> 5, lane = tid & 31;
    const int wm = wid >> 1;      // 0..3  (32 rows each)
    const int wn = wid & 1;       // 0..1  (32 cols each)

    float acc[2][4][4];
    #pragma unroll
    for (int a = 0; a < 2; a++)
        #pragma unroll
        for (int b = 0; b < 4; b++)
            #pragma unroll
            for (int c = 0; c < 4; c++) acc[a][b][c] = 0.f;

    const int a_lr = lane & 15, a_lc = lane >> 4;
    const int b_lr = lane & 7,  b_lc = (lane >> 3) & 1;

    for (int kc = 0; kc < En; kc += LTK) {
        load_chunk_a(sAh, Ah, m0, V, kc, tid);
        load_chunk_a(sAl, Al, m0, V, kc, tid);
        load_chunk_b(sBh, Bh, n0, kc, tid);
        load_chunk_b(sBl, Bl, n0, kc, tid);
        __syncthreads();

        #pragma unroll
        for (int ks = 0; ks < LTK/16; ks++) {
            uint32_t ah[2][4], al[2][4], bh[4][2], bl[4][2];
            #pragma unroll
            for (int mt = 0; mt < 2; mt++) {
                uint32_t off = (uint32_t)((wm*32 + mt*16 + a_lr)*128 + ks*32 + a_lc*16);
                off ^= (off >> 3) & 0x70;
                ldsm4(ah[mt], uAh + off);
                ldsm4(al[mt], uAl + off);
            }
            #pragma unroll
            for (int nt = 0; nt < 4; nt++) {
                uint32_t off = (uint32_t)((wn*32 + nt*8 + b_lr)*128 + ks*32 + b_lc*16);
                off ^= (off >> 3) & 0x70;
                ldsm2(bh[nt], uBh + off);
                ldsm2(bl[nt], uBl + off);
            }
            #pragma unroll
            for (int mt = 0; mt < 2; mt++)
                #pragma unroll
                for (int nt = 0; nt < 4; nt++)
                    mma_bf16(acc[mt][nt], ah[mt], bh[nt]);
            #pragma unroll
            for (int mt = 0; mt < 2; mt++)
                #pragma unroll
                for (int nt = 0; nt < 4; nt++)
                    mma_bf16(acc[mt][nt], ah[mt], bl[nt]);
            #pragma unroll
            for (int mt = 0; mt < 2; mt++)
                #pragma unroll
                for (int nt = 0; nt < 4; nt++)
                    mma_bf16(acc[mt][nt], al[mt], bh[nt]);
        }
        __syncthreads();
    }

    #pragma unroll
    for (int mt = 0; mt < 2; mt++) {
        int m1 = m0 + wm*32 + mt*16 + (lane >> 2);
        int m2 = m1 + 8;
        #pragma unroll
        for (int nt = 0; nt < 4; nt++) {
            int n = n0 + wn*32 + nt*8 + (lane & 3)*2;
            float2 bb = *(const float2*)&bp[n];
            const float* c = acc[mt][nt];
            if (m1 < V)
                *(float2*)&out[(size_t)m1*Vn + n] = make_float2(c[0] + bb.x, c[1] + bb.y);
            if (m2 < V)
                *(float2*)&out[(size_t)m2*Vn + n] = make_float2(c[2] + bb.x, c[3] + bb.y);
        }
    }
}

// ---------------- online log-softmax + argmax + mask + output ----------------
__global__ void softmax_kernel(const float* __restrict__ temp,
                               float* __restrict__ dout) {
    int bt = blockIdx.x;
    int b = bt / STEPS;
    int tid = threadIdx.x;             // 512
    int crow = g_rmap[bt];
    float4* lp4 = (float4*)(dout + LOGP_OFF + (size_t)bt*Vn);

    __shared__ float smx[512]; __shared__ int sai[512]; __shared__ float ssum[512];

    if (crow < 0) {
        float4 z = make_float4(0.f, 0.f, 0.f, 0.f);
        for (int i = tid; i < Vn/4; i += 512) lp4[i] = z;
        if (tid == 0) dout[TXT_OFF + bt] = 0.f;
        return;
    }

    float ls = 1.0f / temp[b];
    const float4* row4 = (const float4*)(g_logits + (size_t)crow*Vn);

    float mx = -3.402823466e38f; float sum = 0.f; int ai = 0;
    for (int i = tid; i < Vn/4; i += 512) {
        float4 v = row4[i];
        float vv[4] = {v.x, v.y, v.z, v.w};
        #pragma unroll
        for (int c = 0; c < 4; c++) {
            float x = vv[c];
            if (x > mx) {
                sum = sum * __expf((mx - x)*ls) + 1.f;
                mx = x; ai = 4*i + c;
            } else {
                sum += __expf((x - mx)*ls);
            }
        }
    }
    smx[tid] = mx; sai[tid] = ai; ssum[tid] = sum; __syncthreads();
    for (int s = 256; s > 0; s >>= 1) {
        if (tid < s) {
            float m1 = smx[tid],   m2 = smx[tid+s];
            float s1 = ssum[tid],  s2 = ssum[tid+s];
            int   i1 = sai[tid],   i2 = sai[tid+s];
            if (m2 > m1 || (m2 == m1 && i2 < i1)) {
                smx[tid] = m2; sai[tid] = i2;
                ssum[tid] = s2 + s1 * __expf((m1 - m2)*ls);
            } else {
                ssum[tid] = s1 + s2 * __expf((m2 - m1)*ls);
            }
        }
        __syncthreads();
    }
    mx = smx[0]; ai = sai[0];
    float lse = logf(ssum[0]);

    for (int i = tid; i < Vn/4; i += 512) {
        float4 v = row4[i];
        float4 o;
        o.x = (v.x - mx)*ls - lse;
        o.y = (v.y - mx)*ls - lse;
        o.z = (v.z - mx)*ls - lse;
        o.w = (v.w - mx)*ls - lse;
        lp4[i] = o;
    }
    if (tid == 0) dout[TXT_OFF + bt] = (float)ai;
}

// ---------------- launcher ----------------
extern "C" void kernel_launch(void* const* d_in, const int* in_sizes, int n_in,
                              void* d_out, int out_size) {
    const float* image = (const float*)d_in[0];
    const float* vp    = (const float*)d_in[1];
    const float* label = (const float*)d_in[2];
    const float* topic = (const float*)d_in[3];
    const float* temp  = (const float*)d_in[4];
    const int*   text  = (const int*)  d_in[5];
    const int*   length= (const int*)  d_in[6];
    const float* emb   = (const float*)d_in[7];
    const float* Wv    = (const float*)d_in[8];
    const float* bv    = (const float*)d_in[9];
    const float* Wh    = (const float*)d_in[10];
    const float* bh    = (const float*)d_in[11];
    const float* Wm    = (const float*)d_in[12];
    const float* bm    = (const float*)d_in[13];
    const float* Wih   = (const float*)d_in[14];
    const float* bih   = (const float*)d_in[15];
    const float* Whh   = (const float*)d_in[16];
    const float* bhh   = (const float*)d_in[17];
    const float* Wfc   = (const float*)d_in[18];
    const float* bfc   = (const float*)d_in[19];
    const float* Whh2  = (const float*)d_in[20];
    const float* bhh2  = (const float*)d_in[21];
    const float* Ws    = (const float*)d_in[22];
    const float* bs    = (const float*)d_in[23];
    const float* Wz    = (const float*)d_in[24];
    const float* bz    = (const float*)d_in[25];
    const float* Wp    = (const float*)d_in[26];
    const float* bp    = (const float*)d_in[27];
    float* dout = (float*)d_out;

    float *p_xcat, *p_xg, *p_v, *p_hs, *p_fo, *p_hh2, *p_ss2, *p_logits;
    __nv_bfloat16 *p_wph, *p_wpl, *p_chh_h, *p_chh_l;
    int *p_V;
    cudaGetSymbolAddress((void**)&p_xcat,   g_xcat);
    cudaGetSymbolAddress((void**)&p_xg,     g_xg);
    cudaGetSymbolAddress((void**)&p_v,      g_v);
    cudaGetSymbolAddress((void**)&p_hs,     g_hs);
    cudaGetSymbolAddress((void**)&p_fo,     g_fo);
    cudaGetSymbolAddress((void**)&p_hh2,    g_hh2);
    cudaGetSymbolAddress((void**)&p_ss2,    g_ss2);
    cudaGetSymbolAddress((void**)&p_logits, g_logits);
    cudaGetSymbolAddress((void**)&p_wph,    g_wph);
    cudaGetSymbolAddress((void**)&p_wpl,    g_wpl);
    cudaGetSymbolAddress((void**)&p_chh_h,  g_chh_h);
    cudaGetSymbolAddress((void**)&p_chh_l,  g_chh_l);
    cudaGetSymbolAddress((void**)&p_V,      g_V);

    cudaFuncSetAttribute(logits_mma, cudaFuncAttributeMaxDynamicSharedMemorySize,
                         LOGITS_SMEM);

    // valid-row maps + Wp hi/lo split (independent)
    build_maps<<<1, 256>>>(length);
    split_bf16<<<(Vn*En/4 + 255)/256, 256>>>(Wp, p_wph, p_wpl, Vn*En/4);

    prep_kernel<<<Bn, 256>>>(image, vp, label, topic, Wh, bh, Wm, bm);
    whh_transpose<<<Hn, Hn>>>(Whh);
    xcat_kernel<<<ROWS, 256>>>(text, emb);   // compact rows

    // Xg = Xcat @ Wih^T + bih on COMPACT rows : (V x 1024), K=792
    gemm_tn128<<<dim3((4*Hn+127)/128, (ROWS+127)/128), 256>>>(p_xcat, INn, Wih, bih, p_xg,
                                                              ROWS, 4*Hn, INn, 0, p_V);
    // v = image @ Wv^T + bv (all rows)
    gemm_tn<<<dim3((Hn+63)/64, (Bn*Pn+63)/64), 256>>>(image, En, Wv, bv, p_v,
                                                      Bn*Pn, Hn, En, 0, nullptr);
    // sequential LSTM on compact rows, per-batch early exit
    lstm_kernel<<<Bn, 256>>>(bhh);

    // fo = relu(Hs @ Wfc^T + bfc) on compact rows
    gemm_tn<<<dim3((2*En+63)/64, (ROWS+63)/64), 256>>>(p_hs, Hn, Wfc, bfc, p_fo,
                                                       ROWS, 2*En, Hn, 1, p_V);
    // _hh, _s on compact rows
    gemm_tn<<<dim3((Hn+63)/64, (ROWS+63)/64), 256>>>(p_fo, 2*En, Whh2, bhh2, p_hh2,
                                                     ROWS, Hn, En, 0, p_V);
    gemm_tn<<<dim3((Hn+63)/64, (ROWS+63)/64), 256>>>(p_fo + En, 2*En, Ws, bs, p_ss2,
                                                     ROWS, Hn, En, 0, p_V);
    // attention: att out + chh bf16 hi/lo split fused into epilogue
    attn_kernel<<<ROWS, 128>>>(image, Wz, bz, dout);

    // tensor-core logits GEMM (compact rows), 128x64 tiles, 2 CTAs/SM
    logits_mma<<<dim3(Vn/64, (ROWS+127)/128), 256, LOGITS_SMEM>>>(
        p_chh_h, p_chh_l, p_wph, p_wpl, bp, p_logits, p_V);

    // online log-softmax + argmax + masking + outputs
    softmax_kernel<<<ROWS, 512>>>(temp, dout);
}

// round 14
// speedup vs baseline: 1.9236x; 1.4812x over previous
#include <cuda_runtime.h>
#include <cuda_bf16.h>
#include <math.h>
#include <stdint.h>

// ---------------- problem constants ----------------
#define Bn 32
#define Pn 49
#define En 256
#define Hn 256
#define Tn 48
#define STEPS 47
#define Vn 32000
#define INn 792          // E + VP + LB + H + E
#define XSn 536          // E + VP + LB + H
#define ROWS (Bn*STEPS)  // 1504

#define ATT_OFF 0
#define LOGP_OFF (ROWS*(Pn+1))                 // 75200
#define TXT_OFF  (LOGP_OFF + (size_t)ROWS*Vn)

// ---------------- scratch (device globals; no allocation) ----------------
__device__ float g_xs  [Bn*XSn];
__device__ float g_h0  [Bn*Hn];
__device__ float g_m0  [Bn*Hn];
__device__ float g_xcat[ROWS*INn];          // compact rows
__device__ float g_xg  [ROWS*4*Hn];         // compact rows
__device__ float4 g_whhR4[Hn*Hn];
__device__ float g_v   [Bn*Pn*Hn];
__device__ float g_hs  [ROWS*Hn];           // compact rows
__device__ float g_fo  [ROWS*2*En];         // compact rows
__device__ float g_hh2 [ROWS*Hn];           // compact rows
__device__ float g_ss2 [ROWS*Hn];           // compact rows
__device__ float g_logits[(size_t)ROWS*Vn]; // compact rows (~192 MB cap)

// valid-row compaction maps
__device__ int g_V[1];
__device__ int g_rmap[ROWS];   // bt -> compact index (or -1)
__device__ int g_bcnt[Bn];     // valid steps per batch
__device__ int g_bstart[Bn];   // compact row offset per batch

// bf16 hi/lo splits for tensor-core logits GEMM
__device__ __align__(256) __nv_bfloat16 g_wph[(size_t)Vn*En];
__device__ __align__(256) __nv_bfloat16 g_wpl[(size_t)Vn*En];
__device__ __align__(256) __nv_bfloat16 g_chh_h[ROWS*En];
__device__ __align__(256) __nv_bfloat16 g_chh_l[ROWS*En];

// ---------------- packed f32x2 helpers (Blackwell FFMA2) ----------------
__device__ __forceinline__ unsigned long long fpk(float lo, float hi) {
    unsigned long long r;
    asm("mov.b64 %0, {%1, %2};" : "=l"(r) : "f"(lo), "f"(hi));
    return r;
}
__device__ __forceinline__ void ffma2(unsigned long long& d,
                                      unsigned long long a,
                                      unsigned long long b) {
    asm("fma.rn.f32x2 %0, %1, %2, %3;" : "=l"(d) : "l"(a), "l"(b), "l"(d));
}
__device__ __forceinline__ float2 fup(unsigned long long v) {
    float2 r;
    asm("mov.b64 {%0, %1}, %2;" : "=f"(r.x), "=f"(r.y) : "l"(v));
    return r;
}
__device__ __forceinline__ float sigm(float x) {
    return 1.0f / (1.0f + __expf(-x));
}
__device__ __forceinline__ uint32_t smem_u32(const void* p) {
    uint32_t a;
    asm("{ .reg .u64 t; cvta.to.shared.u64 t, %1; cvt.u32.u64 %0, t; }"
        : "=r"(a) : "l"(p));
    return a;
}

// ---------------- warp-level tensor core helpers (sm_80+ ISA) ----------------
__device__ __forceinline__ void ldsm4(uint32_t* r, uint32_t addr) {
    asm volatile("ldmatrix.sync.aligned.m8n8.x4.shared.b16 {%0,%1,%2,%3}, [%4];"
        : "=r"(r[0]), "=r"(r[1]), "=r"(r[2]), "=r"(r[3]) : "r"(addr));
}
__device__ __forceinline__ void ldsm2(uint32_t* r, uint32_t addr) {
    asm volatile("ldmatrix.sync.aligned.m8n8.x2.shared.b16 {%0,%1}, [%2];"
        : "=r"(r[0]), "=r"(r[1]) : "r"(addr));
}
__device__ __forceinline__ void mma_bf16(float* c, const uint32_t* a, const uint32_t* b) {
    asm volatile(
        "mma.sync.aligned.m16n8k16.row.col.f32.bf16.bf16.f32 "
        "{%0,%1,%2,%3}, {%4,%5,%6,%7}, {%8,%9}, {%0,%1,%2,%3};"
        : "+f"(c[0]), "+f"(c[1]), "+f"(c[2]), "+f"(c[3])
        : "r"(a[0]), "r"(a[1]), "r"(a[2]), "r"(a[3]), "r"(b[0]), "r"(b[1]));
}

// ---------------- valid-row maps ----------------
__global__ void build_maps(const int* __restrict__ length) {
    __shared__ int cnt[Bn], start[Bn];
    int tid = threadIdx.x;
    if (tid < Bn) {
        int c = length[tid] - 1;
        if (c < 0) c = 0;
        if (c > STEPS) c = STEPS;
        cnt[tid] = c;
        g_bcnt[tid] = c;
    }
    __syncthreads();
    if (tid == 0) {
        int s = 0;
        for (int b = 0; b < Bn; b++) { start[b] = s; g_bstart[b] = s; s += cnt[b]; }
        g_V[0] = s;
    }
    __syncthreads();
    for (int bt = tid; bt < ROWS; bt += 256) {
        int b = bt / STEPS, t = bt % STEPS;
        g_rmap[bt] = (t < cnt[b]) ? (start[b] + t) : -1;
    }
}

// ---------------- prep: image_mean, x_static, h0, m0 ----------------
__global__ void prep_kernel(const float* __restrict__ image,
                            const float* __restrict__ vp,
                            const float* __restrict__ label,
                            const float* __restrict__ topic,
                            const float* __restrict__ Wh, const float* __restrict__ bh,
                            const float* __restrict__ Wm, const float* __restrict__ bm) {
    int b = blockIdx.x;
    int tid = threadIdx.x;   // 256
    __shared__ __align__(16) float im[En];

    float s = 0.f;
    #pragma unroll 7
    for (int p = 0; p < Pn; p++) s += image[(b*Pn + p)*En + tid];
    float mean = s * (1.0f/49.0f);
    im[tid] = mean;

    g_xs[b*XSn + tid] = mean;
    if (tid < 8)  g_xs[b*XSn + 256 + tid] = vp[b*8 + tid];
    if (tid < 16) g_xs[b*XSn + 264 + tid] = label[b*16 + tid];
    g_xs[b*XSn + 280 + tid] = topic[b*Hn + tid];
    __syncthreads();

    float ah = bh[tid], am = bm[tid];
    #pragma unroll 8
    for (int k = 0; k < En; k++) {
        float x = im[k];
        ah = fmaf(x, Wh[tid*En + k], ah);
        am = fmaf(x, Wm[tid*En + k], am);
    }
    g_h0[b*Hn + tid] = tanhf(ah);
    g_m0[b*Hn + tid] = tanhf(am);
}

// ---------------- Whh reorder for coalesced LSTM reads ----------------
__global__ void whh_transpose(const float* __restrict__ Whh) {
    int k = blockIdx.x;
    int j = threadIdx.x;
    float4 w;
    w.x = Whh[(0*Hn + j)*Hn + k];
    w.y = Whh[(1*Hn + j)*Hn + k];
    w.z = Whh[(2*Hn + j)*Hn + k];
    w.w = Whh[(3*Hn + j)*Hn + k];
    g_whhR4[k*Hn + j] = w;
}

// ---------------- build concat rows (compact) ----------------
__global__ void xcat_kernel(const int* __restrict__ text,
                            const float* __restrict__ emb) {
    int bt = blockIdx.x;
    int v = g_rmap[bt];
    if (v < 0) return;
    int b = bt / STEPS, t = bt % STEPS;
    int tid = threadIdx.x;
    int tok = text[b*Tn + t];
    float* row = g_xcat + (size_t)v*INn;
    for (int i = tid; i < XSn; i += 256) row[i] = g_xs[b*XSn + i];
    row[XSn + tid] = emb[(size_t)tok*En + tid];
}

// ---------------- bf16 hi/lo split (for Wp) ----------------
__global__ void split_bf16(const float* __restrict__ src,
                           __nv_bfloat16* __restrict__ hi,
                           __nv_bfloat16* __restrict__ lo, int n4) {
    int i = blockIdx.x*256 + threadIdx.x;
    if (i >= n4) return;
    float4 v = ((const float4*)src)[i];
    float f[4] = {v.x, v.y, v.z, v.w};
    unsigned short h[4], l[4];
    #pragma unroll
    for (int k = 0; k < 4; k++) {
        __nv_bfloat16 hb = __float2bfloat16_rn(f[k]);
        float r = f[k] - __bfloat162float(hb);
        __nv_bfloat16 lb = __float2bfloat16_rn(r);
        h[k] = __bfloat16_as_ushort(hb);
        l[k] = __bfloat16_as_ushort(lb);
    }
    uint2 uh, ul;
    uh.x = (uint32_t)h[0] | ((uint32_t)h[1] << 16);
    uh.y = (uint32_t)h[2] | ((uint32_t)h[3] << 16);
    ul.x = (uint32_t)l[0] | ((uint32_t)l[1] << 16);
    ul.y = (uint32_t)l[2] | ((uint32_t)l[3] << 16);
    ((uint2*)hi)[i] = uh;
    ((uint2*)lo)[i] = ul;
}

// ============== SIMT fp32 GEMM (128x128), runtime M ==============
#define SPAD 132
__global__ __launch_bounds__(256, 2)
void gemm_tn128(const float* __restrict__ A, int lda,
                const float* __restrict__ W,
                const float* __restrict__ bias,
                float* __restrict__ C,
                int M, int N, int K, int doRelu,
                const int* __restrict__ Mdev) {
    const int Mv = Mdev ? Mdev[0] : M;
    const int m0 = blockIdx.y * 128, n0 = blockIdx.x * 128;
    if (m0 >= Mv) return;

    __shared__ __align__(16) float As[2][16][SPAD];
    __shared__ __align__(16) float Bs[2][16][SPAD];

    const int tid = threadIdx.x;
    const int tx = tid & 15, ty = tid >> 4;

    const int lr = tid >> 2;
    const int lk = (tid & 3) * 4;

    unsigned long long acc[8][4];
    #pragma unroll
    for (int i = 0; i < 8; i++)
        #pragma unroll
        for (int j = 0; j < 4; j++) acc[i][j] = 0ULL;

    const int KT = (K + 15) / 16;
    const float4 z4 = make_float4(0.f, 0.f, 0.f, 0.f);
    float4 fa0, fa1, fb0, fb1;

    {
        int k = lk;
        bool kok = (k < K);
        int mA0 = m0 + lr, mA1 = m0 + lr + 64;
        int nB0 = n0 + lr, nB1 = n0 + lr + 64;
        fa0 = (kok && mA0 < Mv) ? *(const float4*)&A[(size_t)mA0*lda + k] : z4;
        fa1 = (kok && mA1 < Mv) ? *(const float4*)&A[(size_t)mA1*lda + k] : z4;
        fb0 = (kok && nB0 < N) ? *(const float4*)&W[(size_t)nB0*K + k] : z4;
        fb1 = (kok && nB1 < N) ? *(const float4*)&W[(size_t)nB1*K + k] : z4;
    }
    As[0][lk+0][lr] = fa0.x; As[0][lk+1][lr] = fa0.y; As[0][lk+2][lr] = fa0.z; As[0][lk+3][lr] = fa0.w;
    As[0][lk+0][lr+64] = fa1.x; As[0][lk+1][lr+64] = fa1.y; As[0][lk+2][lr+64] = fa1.z; As[0][lk+3][lr+64] = fa1.w;
    Bs[0][lk+0][lr] = fb0.x; Bs[0][lk+1][lr] = fb0.y; Bs[0][lk+2][lr] = fb0.z; Bs[0][lk+3][lr] = fb0.w;
    Bs[0][lk+0][lr+64] = fb1.x; Bs[0][lk+1][lr+64] = fb1.y; Bs[0][lk+2][lr+64] = fb1.z; Bs[0][lk+3][lr+64] = fb1.w;
    __syncthreads();

    for (int kt = 0; kt < KT; kt++) {
        int cur = kt & 1;
        if (kt + 1 < KT) {
            int k = (kt + 1) * 16 + lk;
            bool kok = (k < K);
            int mA0 = m0 + lr, mA1 = m0 + lr + 64;
            int nB0 = n0 + lr, nB1 = n0 + lr + 64;
            fa0 = (kok && mA0 < Mv) ? *(const float4*)&A[(size_t)mA0*lda + k] : z4;
            fa1 = (kok && mA1 < Mv) ? *(const float4*)&A[(size_t)mA1*lda + k] : z4;
            fb0 = (kok && nB0 < N) ? *(const float4*)&W[(size_t)nB0*K + k] : z4;
            fb1 = (kok && nB1 < N) ? *(const float4*)&W[(size_t)nB1*K + k] : z4;
        }
        #pragma unroll
        for (int kk = 0; kk < 16; kk++) {
            float4 a0 = *(const float4*)&As[cur][kk][ty*8];
            float4 a1 = *(const float4*)&As[cur][kk][ty*8 + 4];
            float4 b0 = *(const float4*)&Bs[cur][kk][tx*8];
            float4 b1 = *(const float4*)&Bs[cur][kk][tx*8 + 4];
            unsigned long long bp0 = fpk(b0.x, b0.y);
            unsigned long long bp1 = fpk(b0.z, b0.w);
            unsigned long long bp2 = fpk(b1.x, b1.y);
            unsigned long long bp3 = fpk(b1.z, b1.w);
            float av[8] = {a0.x, a0.y, a0.z, a0.w, a1.x, a1.y, a1.z, a1.w};
            #pragma unroll
            for (int i = 0; i < 8; i++) {
                unsigned long long ad = fpk(av[i], av[i]);
                ffma2(acc[i][0], ad, bp0);
                ffma2(acc[i][1], ad, bp1);
                ffma2(acc[i][2], ad, bp2);
                ffma2(acc[i][3], ad, bp3);
            }
        }
        if (kt + 1 < KT) {
            int nxt = cur ^ 1;
            As[nxt][lk+0][lr] = fa0.x; As[nxt][lk+1][lr] = fa0.y; As[nxt][lk+2][lr] = fa0.z; As[nxt][lk+3][lr] = fa0.w;
            As[nxt][lk+0][lr+64] = fa1.x; As[nxt][lk+1][lr+64] = fa1.y; As[nxt][lk+2][lr+64] = fa1.z; As[nxt][lk+3][lr+64] = fa1.w;
            Bs[nxt][lk+0][lr] = fb0.x; Bs[nxt][lk+1][lr] = fb0.y; Bs[nxt][lk+2][lr] = fb0.z; Bs[nxt][lk+3][lr] = fb0.w;
            Bs[nxt][lk+0][lr+64] = fb1.x; Bs[nxt][lk+1][lr+64] = fb1.y; Bs[nxt][lk+2][lr+64] = fb1.z; Bs[nxt][lk+3][lr+64] = fb1.w;
            __syncthreads();
        }
    }

    int nb = n0 + tx*8;
    float bvals[8];
    #pragma unroll
    for (int j = 0; j < 8; j++) bvals[j] = (nb + j < N) ? bias[nb + j] : 0.f;

    #pragma unroll
    for (int i = 0; i < 8; i++) {
        int m = m0 + ty*8 + i;
        if (m >= Mv) continue;
        float out[8];
        #pragma unroll
        for (int j = 0; j < 4; j++) {
            float2 v = fup(acc[i][j]);
            out[2*j]   = v.x + bvals[2*j];
            out[2*j+1] = v.y + bvals[2*j+1];
        }
        if (doRelu) {
            #pragma unroll
            for (int j = 0; j < 8; j++) out[j] = fmaxf(out[j], 0.f);
        }
        if (nb + 7 < N) {
            *(float4*)&C[(size_t)m*N + nb]     = make_float4(out[0], out[1], out[2], out[3]);
            *(float4*)&C[(size_t)m*N + nb + 4] = make_float4(out[4], out[5], out[6], out[7]);
        } else {
            #pragma unroll
            for (int j = 0; j < 8; j++)
                if (nb + j < N) C[(size_t)m*N + nb + j] = out[j];
        }
    }
}

// ---------------- small fp32 GEMM (64x64) with runtime M ----------------
__global__ void gemm_tn(const float* __restrict__ A, int lda,
                        const float* __restrict__ W,
                        const float* __restrict__ bias,
                        float* __restrict__ C,
                        int M, int N, int K, int doRelu,
                        const int* __restrict__ Mdev) {
    const int Mv = Mdev ? Mdev[0] : M;
    const int m0 = blockIdx.y * 64, n0 = blockIdx.x * 64;
    if (m0 >= Mv) return;

    __shared__ __align__(16) float As[16][64];
    __shared__ __align__(16) float Bs[16][64];

    const int tid = threadIdx.x;
    const int tx = tid & 15, ty = tid >> 4;

    unsigned long long acc[4][2];
    #pragma unroll
    for (int i = 0; i < 4; i++) { acc[i][0] = 0ULL; acc[i][1] = 0ULL; }

    for (int k0 = 0; k0 < K; k0 += 16) {
        #pragma unroll
        for (int i = 0; i < 4; i++) {
            int idx = tid + i*256;
            int r = idx >> 4, kk = idx & 15;
            int m = m0 + r, k = k0 + kk, n = n0 + r;
            As[kk][r] = (m < Mv && k < K) ? A[(size_t)m*lda + k] : 0.f;
            Bs[kk][r] = (n < N && k < K) ? W[(size_t)n*K + k] : 0.f;
        }
        __syncthreads();
        #pragma unroll
        for (int kk = 0; kk < 16; kk++) {
            float4 a4 = *(const float4*)&As[kk][ty*4];
            float4 b4 = *(const float4*)&Bs[kk][tx*4];
            unsigned long long b01 = fpk(b4.x, b4.y);
            unsigned long long b23 = fpk(b4.z, b4.w);
            unsigned long long a0 = fpk(a4.x, a4.x);
            unsigned long long a1 = fpk(a4.y, a4.y);
            unsigned long long a2 = fpk(a4.z, a4.z);
            unsigned long long a3 = fpk(a4.w, a4.w);
            ffma2(acc[0][0], a0, b01); ffma2(acc[0][1], a0, b23);
            ffma2(acc[1][0], a1, b01); ffma2(acc[1][1], a1, b23);
            ffma2(acc[2][0], a2, b01); ffma2(acc[2][1], a2, b23);
            ffma2(acc[3][0], a3, b01); ffma2(acc[3][1], a3, b23);
        }
        __syncthreads();
    }

    #pragma unroll
    for (int i = 0; i < 4; i++) {
        int m = m0 + ty*4 + i;
        if (m >= Mv) continue;
        float2 v0 = fup(acc[i][0]);
        float2 v1 = fup(acc[i][1]);
        float vals[4] = {v0.x, v0.y, v1.x, v1.y};
        #pragma unroll
        for (int jj = 0; jj < 4; jj++) {
            int n = n0 + tx*4 + jj;
            if (n < N) {
                float o = vals[jj] + bias[n];
                if (doRelu) o = fmaxf(o, 0.f);
                C[(size_t)m*N + n] = o;
            }
        }
    }
}

// ---------------- sequential LSTM: 4-CTA cluster per batch ----------------
// Each CTA owns 64 hidden units; W slice per step = 256 KB (4x less than full).
// h_new broadcast to all 4 peers' double-buffered hs via DSMEM; 1 cluster.sync/step.
#define CLUSTER_SYNC() do { \
    asm volatile("barrier.cluster.arrive.aligned;" ::: "memory"); \
    asm volatile("barrier.cluster.wait.aligned;" ::: "memory"); \
} while (0)

__global__ void __cluster_dims__(4, 1, 1) lstm_kernel(const float* __restrict__ bhh) {
    const int tid = threadIdx.x;           // 256
    const int j   = tid & 63;              // unit within this CTA's 64
    const int s   = tid >> 6;              // k-slice 0..3
    uint32_t rank;
    asm("mov.u32 %0, %%cluster_ctarank;" : "=r"(rank));
    const int b  = blockIdx.x >> 2;
    const int j0 = rank * 64;              // this CTA's unit base

    const int steps    = g_bcnt[b];
    const int base_row = g_bstart[b];

    __shared__ __align__(16) float hs[2][Hn];
    __shared__ unsigned long long pIF[4][64], pGO[4][64];

    hs[0][tid] = g_h0[b*Hn + tid];

    float mc = 0.f, bi = 0.f, bf = 0.f, bg = 0.f, bo = 0.f;
    if (tid < 64) {
        int ju = j0 + tid;
        mc = g_m0[b*Hn + ju];
        bi = bhh[ju]; bf = bhh[256 + ju]; bg = bhh[512 + ju]; bo = bhh[768 + ju];
    }
    const ulonglong2* W2 = reinterpret_cast<const ulonglong2*>(g_whhR4);
    const uint32_t hs_u32 = smem_u32(hs);

    CLUSTER_SYNC();   // hs[0] init visible everywhere (and in-block sync)

    int cur = 0;
    for (int t = 0; t < steps; t++) {
        unsigned long long aIF = 0ULL, aGO = 0ULL;
        const float* h = hs[cur];
        const int kb = s * 64;
        #pragma unroll 4
        for (int k0 = 0; k0 < 64; k0 += 4) {
            float4 h4 = *(const float4*)&h[kb + k0];
            ulonglong2 w;
            unsigned long long hd;
            w = W2[(size_t)(kb+k0+0)*Hn + j0 + j]; hd = fpk(h4.x, h4.x); ffma2(aIF, hd, w.x); ffma2(aGO, hd, w.y);
            w = W2[(size_t)(kb+k0+1)*Hn + j0 + j]; hd = fpk(h4.y, h4.y); ffma2(aIF, hd, w.x); ffma2(aGO, hd, w.y);
            w = W2[(size_t)(kb+k0+2)*Hn + j0 + j]; hd = fpk(h4.z, h4.z); ffma2(aIF, hd, w.x); ffma2(aGO, hd, w.y);
            w = W2[(size_t)(kb+k0+3)*Hn + j0 + j]; hd = fpk(h4.w, h4.w); ffma2(aIF, hd, w.x); ffma2(aGO, hd, w.y);
        }
        pIF[s][j] = aIF;
        pGO[s][j] = aGO;
        __syncthreads();

        if (tid < 64) {
            float2 i0 = fup(pIF[0][tid]), i1 = fup(pIF[1][tid]);
            float2 i2 = fup(pIF[2][tid]), i3 = fup(pIF[3][tid]);
            float2 g0 = fup(pGO[0][tid]), g1 = fup(pGO[1][tid]);
            float2 g2 = fup(pGO[2][tid]), g3 = fup(pGO[3][tid]);
            float iacc = ((i0.x + i1.x) + i2.x) + i3.x;
            float facc = ((i0.y + i1.y) + i2.y) + i3.y;
            float gacc = ((g0.x + g1.x) + g2.x) + g3.x;
            float oacc = ((g0.y + g1.y) + g2.y) + g3.y;

            size_t base = (size_t)(base_row + t) * (4*Hn) + j0 + tid;
            float gi = g_xg[base]        + bi + iacc;
            float gf = g_xg[base + 256]  + bf + facc;
            float gg = g_xg[base + 512]  + bg + gacc;
            float go = g_xg[base + 768]  + bo + oacc;
            mc = sigm(gf)*mc + sigm(gi)*tanhf(gg);
            float hn = sigm(go)*tanhf(mc);
            g_hs[(size_t)(base_row + t)*Hn + j0 + tid] = hn;

            // broadcast hn into all 4 cluster CTAs' hs[cur^1][j0+tid]
            uint32_t laddr = hs_u32 + (uint32_t)(((cur ^ 1) * Hn + j0 + tid) * 4);
            #pragma unroll
            for (int rr = 0; rr < 4; rr++) {
                uint32_t pa;
                asm("mapa.shared::cluster.u32 %0, %1, %2;" : "=r"(pa) : "r"(laddr), "r"(rr));
                asm volatile("st.shared::cluster.f32 [%0], %1;" :: "r"(pa), "f"(hn));
            }
        }
        CLUSTER_SYNC();
        cur ^= 1;
    }
}

// ---------------- fused attention per (b,t), compact-aware, fused chh split ----------------
__global__ void attn_kernel(const float* __restrict__ image,
                            const float* __restrict__ Wz,
                            const float* __restrict__ bz,
                            float* __restrict__ dout) {
    int bt = blockIdx.x;
    int b = bt / STEPS;
    int tid = threadIdx.x;             // 128
    int wid = tid >> 5, lane = tid & 31;
    int v = g_rmap[bt];

    if (v < 0) {
        if (tid < Pn+1)
            dout[ATT_OFF + (size_t)bt*(Pn+1) + tid] = 0.f;
        return;
    }

    __shared__ float shh2[Hn], shh[Hn], ss[Hn], ss2[Hn];
    __shared__ float zz[Pn+1], aw[Pn+1];

    for (int k = tid; k < Hn; k += 128) {
        shh2[k] = g_hh2[(size_t)v*Hn + k];
        shh [k] = g_fo [(size_t)v*2*En + k];
        ss  [k] = g_fo [(size_t)v*2*En + En + k];
        ss2 [k] = g_ss2[(size_t)v*Hn + k];
    }
    __syncthreads();

    for (int p = wid; p < Pn+1; p += 4) {
        float part = 0.f;
        const float* vrow = (p < Pn) ? (g_v + (size_t)(b*Pn + p)*Hn) : ss2;
        for (int k = lane; k < Hn; k += 32)
            part += Wz[k] * tanhf(vrow[k] + shh2[k]);
        #pragma unroll
        for (int off = 16; off > 0; off >>= 1)
            part += __shfl_down_sync(0xffffffff, part, off);
        if (lane == 0) zz[p] = part + bz[0];
    }
    __syncthreads();

    if (tid == 0) {
        float mx = zz[0];
        for (int p = 1; p < Pn+1; p++) mx = fmaxf(mx, zz[p]);
        float s = 0.f;
        for (int p = 0; p < Pn+1; p++) { float e = __expf(zz[p]-mx); aw[p] = e; s += e; }
        float inv = 1.f / s;
        for (int p = 0; p < Pn+1; p++) aw[p] *= inv;
    }
    __syncthreads();

    if (tid < Pn+1)
        dout[ATT_OFF + (size_t)bt*(Pn+1) + tid] = aw[tid];

    // chh = c + hh, split to bf16 hi/lo inline (2 elements per thread)
    #pragma unroll
    for (int kk = 0; kk < 2; kk++) {
        int k = tid + kk*128;
        float c = aw[Pn] * ss[k];
        #pragma unroll 7
        for (int p = 0; p < Pn; p++)
            c = fmaf(aw[p], image[(size_t)(b*Pn + p)*En + k], c);
        float f = c + shh[k];
        __nv_bfloat16 hb = __float2bfloat16_rn(f);
        float r = f - __bfloat162float(hb);
        g_chh_h[(size_t)v*En + k] = hb;
        g_chh_l[(size_t)v*En + k] = __float2bfloat16_rn(r);
    }
}

// ============== tensor-core logits GEMM via mma.sync (bf16 hi/lo, fp32 acc) ==============
// Tile 128x64, 8 warps (4x2), warp tile 32x32, 2 CTAs/SM.
#define LTK 64
#define LCHUNK_A (128*LTK*2)            // 16384 bytes per A buffer
#define LCHUNK_Bt (64*LTK*2)            // 8192 bytes per B buffer
#define LOGITS_SMEM (2*LCHUNK_A + 2*LCHUNK_Bt)   // 49152

__device__ __forceinline__ void load_chunk_a(__nv_bfloat16* dst,
                                             const __nv_bfloat16* __restrict__ src,
                                             int row0, int rows_valid, int kc, int tid) {
    #pragma unroll
    for (int i = 0; i < 4; i++) {
        int idx = tid + i*256;
        int row = idx >> 3, ch = idx & 7;
        uint32_t off = (uint32_t)(row*128 + ch*16);
        off ^= (off >> 3) & 0x70;
        int gr = row0 + row;
        uint4 v = (gr < rows_valid) ? *(const uint4*)(src + (size_t)gr*256 + kc + ch*8)
                                    : make_uint4(0u, 0u, 0u, 0u);
        *(uint4*)((char*)dst + off) = v;
    }
}
__device__ __forceinline__ void load_chunk_b(__nv_bfloat16* dst,
                                             const __nv_bfloat16* __restrict__ src,
                                             int row0, int kc, int tid) {
    #pragma unroll
    for (int i = 0; i < 2; i++) {
        int idx = tid + i*256;
        int row = idx >> 3, ch = idx & 7;
        uint32_t off = (uint32_t)(row*128 + ch*16);
        off ^= (off >> 3) & 0x70;
        uint4 v = *(const uint4*)(src + (size_t)(row0 + row)*256 + kc + ch*8);
        *(uint4*)((char*)dst + off) = v;
    }
}

__global__ __launch_bounds__(256, 2)
void logits_mma(const __nv_bfloat16* __restrict__ Ah, const __nv_bfloat16* __restrict__ Al,
                const __nv_bfloat16* __restrict__ Bh, const __nv_bfloat16* __restrict__ Bl,
                const float* __restrict__ bp, float* __restrict__ out,
                const int* __restrict__ Vdev) {
    const int V = Vdev[0];
    const int m0 = blockIdx.y * 128;
    if (m0 >= V) return;
    const int n0 = blockIdx.x * 64;

    extern __shared__ char smem[];
    __nv_bfloat16* sAh = (__nv_bfloat16*)smem;
    __nv_bfloat16* sAl = (__nv_bfloat16*)(smem + LCHUNK_A);
    __nv_bfloat16* sBh = (__nv_bfloat16*)(smem + 2*LCHUNK_A);
    __nv_bfloat16* sBl = (__nv_bfloat16*)(smem + 2*LCHUNK_A + LCHUNK_Bt);
    const uint32_t uAh = smem_u32(sAh), uAl = smem_u32(sAl);
    const uint32_t uBh = smem_u32(sBh), uBl = smem_u32(sBl);

    const int tid = threadIdx.x;
    const int wid = tid >> 5, lane = tid & 31;
    const int wm = wid >> 1;      // 0..3
    const int wn = wid & 1;       // 0..1

    float acc[2][4][4];
    #pragma unroll
    for (int a = 0; a < 2; a++)
        #pragma unroll
        for (int b = 0; b < 4; b++)
            #pragma unroll
            for (int c = 0; c < 4; c++) acc[a][b][c] = 0.f;

    const int a_lr = lane & 15, a_lc = lane >> 4;
    const int b_lr = lane & 7,  b_lc = (lane >> 3) & 1;

    for (int kc = 0; kc < En; kc += LTK) {
        load_chunk_a(sAh, Ah, m0, V, kc, tid);
        load_chunk_a(sAl, Al, m0, V, kc, tid);
        load_chunk_b(sBh, Bh, n0, kc, tid);
        load_chunk_b(sBl, Bl, n0, kc, tid);
        __syncthreads();

        #pragma unroll
        for (int ks = 0; ks < LTK/16; ks++) {
            uint32_t ah[2][4], al[2][4], bh[4][2], bl[4][2];
            #pragma unroll
            for (int mt = 0; mt < 2; mt++) {
                uint32_t off = (uint32_t)((wm*32 + mt*16 + a_lr)*128 + ks*32 + a_lc*16);
                off ^= (off >> 3) & 0x70;
                ldsm4(ah[mt], uAh + off);
                ldsm4(al[mt], uAl + off);
            }
            #pragma unroll
            for (int nt = 0; nt < 4; nt++) {
                uint32_t off = (uint32_t)((wn*32 + nt*8 + b_lr)*128 + ks*32 + b_lc*16);
                off ^= (off >> 3) & 0x70;
                ldsm2(bh[nt], uBh + off);
                ldsm2(bl[nt], uBl + off);
            }
            #pragma unroll
            for (int mt = 0; mt < 2; mt++)
                #pragma unroll
                for (int nt = 0; nt < 4; nt++)
                    mma_bf16(acc[mt][nt], ah[mt], bh[nt]);
            #pragma unroll
            for (int mt = 0; mt < 2; mt++)
                #pragma unroll
                for (int nt = 0; nt < 4; nt++)
                    mma_bf16(acc[mt][nt], ah[mt], bl[nt]);
            #pragma unroll
            for (int mt = 0; mt < 2; mt++)
                #pragma unroll
                for (int nt = 0; nt < 4; nt++)
                    mma_bf16(acc[mt][nt], al[mt], bh[nt]);
        }
        __syncthreads();
    }

    #pragma unroll
    for (int mt = 0; mt < 2; mt++) {
        int m1 = m0 + wm*32 + mt*16 + (lane >> 2);
        int m2 = m1 + 8;
        #pragma unroll
        for (int nt = 0; nt < 4; nt++) {
            int n = n0 + wn*32 + nt*8 + (lane & 3)*2;
            float2 bb = *(const float2*)&bp[n];
            const float* c = acc[mt][nt];
            if (m1 < V)
                *(float2*)&out[(size_t)m1*Vn + n] = make_float2(c[0] + bb.x, c[1] + bb.y);
            if (m2 < V)
                *(float2*)&out[(size_t)m2*Vn + n] = make_float2(c[2] + bb.x, c[3] + bb.y);
        }
    }
}

// ---------------- online log-softmax + argmax + mask + output ----------------
__global__ void softmax_kernel(const float* __restrict__ temp,
                               float* __restrict__ dout) {
    int bt = blockIdx.x;
    int b = bt / STEPS;
    int tid = threadIdx.x;             // 512
    int crow = g_rmap[bt];
    float4* lp4 = (float4*)(dout + LOGP_OFF + (size_t)bt*Vn);

    __shared__ float smx[512]; __shared__ int sai[512]; __shared__ float ssum[512];

    if (crow < 0) {
        float4 z = make_float4(0.f, 0.f, 0.f, 0.f);
        for (int i = tid; i < Vn/4; i += 512) lp4[i] = z;
        if (tid == 0) dout[TXT_OFF + bt] = 0.f;
        return;
    }

    float ls = 1.0f / temp[b];
    const float4* row4 = (const float4*)(g_logits + (size_t)crow*Vn);

    float mx = -3.402823466e38f; float sum = 0.f; int ai = 0;
    for (int i = tid; i < Vn/4; i += 512) {
        float4 v = row4[i];
        float vv[4] = {v.x, v.y, v.z, v.w};
        #pragma unroll
        for (int c = 0; c < 4; c++) {
            float x = vv[c];
            if (x > mx) {
                sum = sum * __expf((mx - x)*ls) + 1.f;
                mx = x; ai = 4*i + c;
            } else {
                sum += __expf((x - mx)*ls);
            }
        }
    }
    smx[tid] = mx; sai[tid] = ai; ssum[tid] = sum; __syncthreads();
    for (int s = 256; s > 0; s >>= 1) {
        if (tid < s) {
            float m1 = smx[tid],   m2 = smx[tid+s];
            float s1 = ssum[tid],  s2 = ssum[tid+s];
            int   i1 = sai[tid],   i2 = sai[tid+s];
            if (m2 > m1 || (m2 == m1 && i2 < i1)) {
                smx[tid] = m2; sai[tid] = i2;
                ssum[tid] = s2 + s1 * __expf((m1 - m2)*ls);
            } else {
                ssum[tid] = s1 + s2 * __expf((m2 - m1)*ls);
            }
        }
        __syncthreads();
    }
    mx = smx[0]; ai = sai[0];
    float lse = logf(ssum[0]);

    for (int i = tid; i < Vn/4; i += 512) {
        float4 v = row4[i];
        float4 o;
        o.x = (v.x - mx)*ls - lse;
        o.y = (v.y - mx)*ls - lse;
        o.z = (v.z - mx)*ls - lse;
        o.w = (v.w - mx)*ls - lse;
        lp4[i] = o;
    }
    if (tid == 0) dout[TXT_OFF + bt] = (float)ai;
}

// ---------------- launcher ----------------
extern "C" void kernel_launch(void* const* d_in, const int* in_sizes, int n_in,
                              void* d_out, int out_size) {
    const float* image = (const float*)d_in[0];
    const float* vp    = (const float*)d_in[1];
    const float* label = (const float*)d_in[2];
    const float* topic = (const float*)d_in[3];
    const float* temp  = (const float*)d_in[4];
    const int*   text  = (const int*)  d_in[5];
    const int*   length= (const int*)  d_in[6];
    const float* emb   = (const float*)d_in[7];
    const float* Wv    = (const float*)d_in[8];
    const float* bv    = (const float*)d_in[9];
    const float* Wh    = (const float*)d_in[10];
    const float* bh    = (const float*)d_in[11];
    const float* Wm    = (const float*)d_in[12];
    const float* bm    = (const float*)d_in[13];
    const float* Wih   = (const float*)d_in[14];
    const float* bih   = (const float*)d_in[15];
    const float* Whh   = (const float*)d_in[16];
    const float* bhh   = (const float*)d_in[17];
    const float* Wfc   = (const float*)d_in[18];
    const float* bfc   = (const float*)d_in[19];
    const float* Whh2  = (const float*)d_in[20];
    const float* bhh2  = (const float*)d_in[21];
    const float* Ws    = (const float*)d_in[22];
    const float* bs    = (const float*)d_in[23];
    const float* Wz    = (const float*)d_in[24];
    const float* bz    = (const float*)d_in[25];
    const float* Wp    = (const float*)d_in[26];
    const float* bp    = (const float*)d_in[27];
    float* dout = (float*)d_out;

    float *p_xcat, *p_xg, *p_v, *p_hs, *p_fo, *p_hh2, *p_ss2, *p_logits;
    __nv_bfloat16 *p_wph, *p_wpl, *p_chh_h, *p_chh_l;
    int *p_V;
    cudaGetSymbolAddress((void**)&p_xcat,   g_xcat);
    cudaGetSymbolAddress((void**)&p_xg,     g_xg);
    cudaGetSymbolAddress((void**)&p_v,      g_v);
    cudaGetSymbolAddress((void**)&p_hs,     g_hs);
    cudaGetSymbolAddress((void**)&p_fo,     g_fo);
    cudaGetSymbolAddress((void**)&p_hh2,    g_hh2);
    cudaGetSymbolAddress((void**)&p_ss2,    g_ss2);
    cudaGetSymbolAddress((void**)&p_logits, g_logits);
    cudaGetSymbolAddress((void**)&p_wph,    g_wph);
    cudaGetSymbolAddress((void**)&p_wpl,    g_wpl);
    cudaGetSymbolAddress((void**)&p_chh_h,  g_chh_h);
    cudaGetSymbolAddress((void**)&p_chh_l,  g_chh_l);
    cudaGetSymbolAddress((void**)&p_V,      g_V);

    cudaFuncSetAttribute(logits_mma, cudaFuncAttributeMaxDynamicSharedMemorySize,
                         LOGITS_SMEM);

    // valid-row maps + Wp hi/lo split (independent)
    build_maps<<<1, 256>>>(length);
    split_bf16<<<(Vn*En/4 + 255)/256, 256>>>(Wp, p_wph, p_wpl, Vn*En/4);

    prep_kernel<<<Bn, 256>>>(image, vp, label, topic, Wh, bh, Wm, bm);
    whh_transpose<<<Hn, Hn>>>(Whh);
    xcat_kernel<<<ROWS, 256>>>(text, emb);   // compact rows

    // Xg = Xcat @ Wih^T + bih on COMPACT rows : (V x 1024), K=792
    gemm_tn128<<<dim3((4*Hn+127)/128, (ROWS+127)/128), 256>>>(p_xcat, INn, Wih, bih, p_xg,
                                                              ROWS, 4*Hn, INn, 0, p_V);
    // v = image @ Wv^T + bv (all rows)
    gemm_tn<<<dim3((Hn+63)/64, (Bn*Pn+63)/64), 256>>>(image, En, Wv, bv, p_v,
                                                      Bn*Pn, Hn, En, 0, nullptr);
    // sequential LSTM: 4-CTA cluster per batch (128 CTAs)
    lstm_kernel<<<Bn*4, 256>>>(bhh);

    // fo = relu(Hs @ Wfc^T + bfc) on compact rows
    gemm_tn<<<dim3((2*En+63)/64, (ROWS+63)/64), 256>>>(p_hs, Hn, Wfc, bfc, p_fo,
                                                       ROWS, 2*En, Hn, 1, p_V);
    // _hh, _s on compact rows
    gemm_tn<<<dim3((Hn+63)/64, (ROWS+63)/64), 256>>>(p_fo, 2*En, Whh2, bhh2, p_hh2,
                                                     ROWS, Hn, En, 0, p_V);
    gemm_tn<<<dim3((Hn+63)/64, (ROWS+63)/64), 256>>>(p_fo + En, 2*En, Ws, bs, p_ss2,
                                                     ROWS, Hn, En, 0, p_V);
    // attention: att out + chh bf16 hi/lo split fused into epilogue
    attn_kernel<<<ROWS, 128>>>(image, Wz, bz, dout);

    // tensor-core logits GEMM (compact rows), 128x64 tiles, 2 CTAs/SM
    logits_mma<<<dim3(Vn/64, (ROWS+127)/128), 256, LOGITS_SMEM>>>(
        p_chh_h, p_chh_l, p_wph, p_wpl, bp, p_logits, p_V);

    // online log-softmax + argmax + masking + outputs
    softmax_kernel<<<ROWS, 512>>>(temp, dout);
}

// round 15
// speedup vs baseline: 2.0901x; 1.0866x over previous
#include <cuda_runtime.h>
#include <cuda_bf16.h>
#include <math.h>
#include <stdint.h>

// ---------------- problem constants ----------------
#define Bn 32
#define Pn 49
#define En 256
#define Hn 256
#define Tn 48
#define STEPS 47
#define Vn 32000
#define INn 792          // E + VP + LB + H + E
#define XSn 536          // E + VP + LB + H
#define ROWS (Bn*STEPS)  // 1504

#define ATT_OFF 0
#define LOGP_OFF (ROWS*(Pn+1))                 // 75200
#define TXT_OFF  (LOGP_OFF + (size_t)ROWS*Vn)

// ---------------- scratch (device globals; no allocation) ----------------
__device__ float g_xs  [Bn*XSn];
__device__ float g_h0  [Bn*Hn];
__device__ float g_m0  [Bn*Hn];
__device__ float g_xcat[ROWS*INn];          // compact rows
__device__ float g_xg  [ROWS*4*Hn];         // compact rows
__device__ float4 g_whhR4[Hn*Hn];
__device__ float g_v   [Bn*Pn*Hn];
__device__ float g_hs  [ROWS*Hn];           // compact rows
__device__ float g_fo  [ROWS*2*En];         // compact rows
__device__ float g_hh2 [ROWS*Hn];           // compact rows
__device__ float g_ss2 [ROWS*Hn];           // compact rows
__device__ float g_logits[(size_t)ROWS*Vn]; // compact rows (~192 MB cap)

// valid-row compaction maps
__device__ int g_V[1];
__device__ int g_rmap[ROWS];   // bt -> compact index (or -1)
__device__ int g_bcnt[Bn];     // valid steps per batch
__device__ int g_bstart[Bn];   // compact row offset per batch

// bf16 hi/lo splits for tensor-core logits GEMM
__device__ __align__(256) __nv_bfloat16 g_wph[(size_t)Vn*En];
__device__ __align__(256) __nv_bfloat16 g_wpl[(size_t)Vn*En];
__device__ __align__(256) __nv_bfloat16 g_chh_h[ROWS*En];
__device__ __align__(256) __nv_bfloat16 g_chh_l[ROWS*En];

// ---------------- packed f32x2 helpers (Blackwell FFMA2) ----------------
__device__ __forceinline__ unsigned long long fpk(float lo, float hi) {
    unsigned long long r;
    asm("mov.b64 %0, {%1, %2};" : "=l"(r) : "f"(lo), "f"(hi));
    return r;
}
__device__ __forceinline__ void ffma2(unsigned long long& d,
                                      unsigned long long a,
                                      unsigned long long b) {
    asm("fma.rn.f32x2 %0, %1, %2, %3;" : "=l"(d) : "l"(a), "l"(b), "l"(d));
}
__device__ __forceinline__ float2 fup(unsigned long long v) {
    float2 r;
    asm("mov.b64 {%0, %1}, %2;" : "=f"(r.x), "=f"(r.y) : "l"(v));
    return r;
}
__device__ __forceinline__ float sigm(float x) {
    return 1.0f / (1.0f + __expf(-x));
}
__device__ __forceinline__ uint32_t smem_u32(const void* p) {
    uint32_t a;
    asm("{ .reg .u64 t; cvta.to.shared.u64 t, %1; cvt.u32.u64 %0, t; }"
        : "=r"(a) : "l"(p));
    return a;
}

// ---------------- warp-level tensor core helpers (sm_80+ ISA) ----------------
__device__ __forceinline__ void ldsm4(uint32_t* r, uint32_t addr) {
    asm volatile("ldmatrix.sync.aligned.m8n8.x4.shared.b16 {%0,%1,%2,%3}, [%4];"
        : "=r"(r[0]), "=r"(r[1]), "=r"(r[2]), "=r"(r[3]) : "r"(addr));
}
__device__ __forceinline__ void ldsm2(uint32_t* r, uint32_t addr) {
    asm volatile("ldmatrix.sync.aligned.m8n8.x2.shared.b16 {%0,%1}, [%2];"
        : "=r"(r[0]), "=r"(r[1]) : "r"(addr));
}
__device__ __forceinline__ void mma_bf16(float* c, const uint32_t* a, const uint32_t* b) {
    asm volatile(
        "mma.sync.aligned.m16n8k16.row.col.f32.bf16.bf16.f32 "
        "{%0,%1,%2,%3}, {%4,%5,%6,%7}, {%8,%9}, {%0,%1,%2,%3};"
        : "+f"(c[0]), "+f"(c[1]), "+f"(c[2]), "+f"(c[3])
        : "r"(a[0]), "r"(a[1]), "r"(a[2]), "r"(a[3]), "r"(b[0]), "r"(b[1]));
}
// cp.async 16B with src-size (0 => zero-fill)
__device__ __forceinline__ void cpa16(uint32_t dst, const void* src, int szbytes) {
    asm volatile("cp.async.cg.shared.global [%0], [%1], 16, %2;"
        :: "r"(dst), "l"(src), "r"(szbytes));
}
#define CP_COMMIT() asm volatile("cp.async.commit_group;" ::: "memory")
#define CP_WAIT1()  asm volatile("cp.async.wait_group 1;" ::: "memory")
#define CP_WAIT0()  asm volatile("cp.async.wait_group 0;" ::: "memory")

// ---------------- valid-row maps ----------------
__global__ void build_maps(const int* __restrict__ length) {
    __shared__ int cnt[Bn], start[Bn];
    int tid = threadIdx.x;
    if (tid < Bn) {
        int c = length[tid] - 1;
        if (c < 0) c = 0;
        if (c > STEPS) c = STEPS;
        cnt[tid] = c;
        g_bcnt[tid] = c;
    }
    __syncthreads();
    if (tid == 0) {
        int s = 0;
        for (int b = 0; b < Bn; b++) { start[b] = s; g_bstart[b] = s; s += cnt[b]; }
        g_V[0] = s;
    }
    __syncthreads();
    for (int bt = tid; bt < ROWS; bt += 256) {
        int b = bt / STEPS, t = bt % STEPS;
        g_rmap[bt] = (t < cnt[b]) ? (start[b] + t) : -1;
    }
}

// ---------------- prep: image_mean, x_static, h0, m0 ----------------
__global__ void prep_kernel(const float* __restrict__ image,
                            const float* __restrict__ vp,
                            const float* __restrict__ label,
                            const float* __restrict__ topic,
                            const float* __restrict__ Wh, const float* __restrict__ bh,
                            const float* __restrict__ Wm, const float* __restrict__ bm) {
    int b = blockIdx.x;
    int tid = threadIdx.x;   // 256
    __shared__ __align__(16) float im[En];

    float s = 0.f;
    #pragma unroll 7
    for (int p = 0; p < Pn; p++) s += image[(b*Pn + p)*En + tid];
    float mean = s * (1.0f/49.0f);
    im[tid] = mean;

    g_xs[b*XSn + tid] = mean;
    if (tid < 8)  g_xs[b*XSn + 256 + tid] = vp[b*8 + tid];
    if (tid < 16) g_xs[b*XSn + 264 + tid] = label[b*16 + tid];
    g_xs[b*XSn + 280 + tid] = topic[b*Hn + tid];
    __syncthreads();

    float ah = bh[tid], am = bm[tid];
    #pragma unroll 8
    for (int k = 0; k < En; k++) {
        float x = im[k];
        ah = fmaf(x, Wh[tid*En + k], ah);
        am = fmaf(x, Wm[tid*En + k], am);
    }
    g_h0[b*Hn + tid] = tanhf(ah);
    g_m0[b*Hn + tid] = tanhf(am);
}

// ---------------- Whh reorder for coalesced LSTM reads ----------------
__global__ void whh_transpose(const float* __restrict__ Whh) {
    int k = blockIdx.x;
    int j = threadIdx.x;
    float4 w;
    w.x = Whh[(0*Hn + j)*Hn + k];
    w.y = Whh[(1*Hn + j)*Hn + k];
    w.z = Whh[(2*Hn + j)*Hn + k];
    w.w = Whh[(3*Hn + j)*Hn + k];
    g_whhR4[k*Hn + j] = w;
}

// ---------------- build concat rows (compact) ----------------
__global__ void xcat_kernel(const int* __restrict__ text,
                            const float* __restrict__ emb) {
    int bt = blockIdx.x;
    int v = g_rmap[bt];
    if (v < 0) return;
    int b = bt / STEPS, t = bt % STEPS;
    int tid = threadIdx.x;
    int tok = text[b*Tn + t];
    float* row = g_xcat + (size_t)v*INn;
    for (int i = tid; i < XSn; i += 256) row[i] = g_xs[b*XSn + i];
    row[XSn + tid] = emb[(size_t)tok*En + tid];
}

// ---------------- bf16 hi/lo split (for Wp) ----------------
__global__ void split_bf16(const float* __restrict__ src,
                           __nv_bfloat16* __restrict__ hi,
                           __nv_bfloat16* __restrict__ lo, int n4) {
    int i = blockIdx.x*256 + threadIdx.x;
    if (i >= n4) return;
    float4 v = ((const float4*)src)[i];
    float f[4] = {v.x, v.y, v.z, v.w};
    unsigned short h[4], l[4];
    #pragma unroll
    for (int k = 0; k < 4; k++) {
        __nv_bfloat16 hb = __float2bfloat16_rn(f[k]);
        float r = f[k] - __bfloat162float(hb);
        __nv_bfloat16 lb = __float2bfloat16_rn(r);
        h[k] = __bfloat16_as_ushort(hb);
        l[k] = __bfloat16_as_ushort(lb);
    }
    uint2 uh, ul;
    uh.x = (uint32_t)h[0] | ((uint32_t)h[1] << 16);
    uh.y = (uint32_t)h[2] | ((uint32_t)h[3] << 16);
    ul.x = (uint32_t)l[0] | ((uint32_t)l[1] << 16);
    ul.y = (uint32_t)l[2] | ((uint32_t)l[3] << 16);
    ((uint2*)hi)[i] = uh;
    ((uint2*)lo)[i] = ul;
}

// ============== SIMT fp32 GEMM (128x128), runtime M ==============
#define SPAD 132
__global__ __launch_bounds__(256, 2)
void gemm_tn128(const float* __restrict__ A, int lda,
                const float* __restrict__ W,
                const float* __restrict__ bias,
                float* __restrict__ C,
                int M, int N, int K, int doRelu,
                const int* __restrict__ Mdev) {
    const int Mv = Mdev ? Mdev[0] : M;
    const int m0 = blockIdx.y * 128, n0 = blockIdx.x * 128;
    if (m0 >= Mv) return;

    __shared__ __align__(16) float As[2][16][SPAD];
    __shared__ __align__(16) float Bs[2][16][SPAD];

    const int tid = threadIdx.x;
    const int tx = tid & 15, ty = tid >> 4;

    const int lr = tid >> 2;
    const int lk = (tid & 3) * 4;

    unsigned long long acc[8][4];
    #pragma unroll
    for (int i = 0; i < 8; i++)
        #pragma unroll
        for (int j = 0; j < 4; j++) acc[i][j] = 0ULL;

    const int KT = (K + 15) / 16;
    const float4 z4 = make_float4(0.f, 0.f, 0.f, 0.f);
    float4 fa0, fa1, fb0, fb1;

    {
        int k = lk;
        bool kok = (k < K);
        int mA0 = m0 + lr, mA1 = m0 + lr + 64;
        int nB0 = n0 + lr, nB1 = n0 + lr + 64;
        fa0 = (kok && mA0 < Mv) ? *(const float4*)&A[(size_t)mA0*lda + k] : z4;
        fa1 = (kok && mA1 < Mv) ? *(const float4*)&A[(size_t)mA1*lda + k] : z4;
        fb0 = (kok && nB0 < N) ? *(const float4*)&W[(size_t)nB0*K + k] : z4;
        fb1 = (kok && nB1 < N) ? *(const float4*)&W[(size_t)nB1*K + k] : z4;
    }
    As[0][lk+0][lr] = fa0.x; As[0][lk+1][lr] = fa0.y; As[0][lk+2][lr] = fa0.z; As[0][lk+3][lr] = fa0.w;
    As[0][lk+0][lr+64] = fa1.x; As[0][lk+1][lr+64] = fa1.y; As[0][lk+2][lr+64] = fa1.z; As[0][lk+3][lr+64] = fa1.w;
    Bs[0][lk+0][lr] = fb0.x; Bs[0][lk+1][lr] = fb0.y; Bs[0][lk+2][lr] = fb0.z; Bs[0][lk+3][lr] = fb0.w;
    Bs[0][lk+0][lr+64] = fb1.x; Bs[0][lk+1][lr+64] = fb1.y; Bs[0][lk+2][lr+64] = fb1.z; Bs[0][lk+3][lr+64] = fb1.w;
    __syncthreads();

    for (int kt = 0; kt < KT; kt++) {
        int cur = kt & 1;
        if (kt + 1 < KT) {
            int k = (kt + 1) * 16 + lk;
            bool kok = (k < K);
            int mA0 = m0 + lr, mA1 = m0 + lr + 64;
            int nB0 = n0 + lr, nB1 = n0 + lr + 64;
            fa0 = (kok && mA0 < Mv) ? *(const float4*)&A[(size_t)mA0*lda + k] : z4;
            fa1 = (kok && mA1 < Mv) ? *(const float4*)&A[(size_t)mA1*lda + k] : z4;
            fb0 = (kok && nB0 < N) ? *(const float4*)&W[(size_t)nB0*K + k] : z4;
            fb1 = (kok && nB1 < N) ? *(const float4*)&W[(size_t)nB1*K + k] : z4;
        }
        #pragma unroll
        for (int kk = 0; kk < 16; kk++) {
            float4 a0 = *(const float4*)&As[cur][kk][ty*8];
            float4 a1 = *(const float4*)&As[cur][kk][ty*8 + 4];
            float4 b0 = *(const float4*)&Bs[cur][kk][tx*8];
            float4 b1 = *(const float4*)&Bs[cur][kk][tx*8 + 4];
            unsigned long long bp0 = fpk(b0.x, b0.y);
            unsigned long long bp1 = fpk(b0.z, b0.w);
            unsigned long long bp2 = fpk(b1.x, b1.y);
            unsigned long long bp3 = fpk(b1.z, b1.w);
            float av[8] = {a0.x, a0.y, a0.z, a0.w, a1.x, a1.y, a1.z, a1.w};
            #pragma unroll
            for (int i = 0; i < 8; i++) {
                unsigned long long ad = fpk(av[i], av[i]);
                ffma2(acc[i][0], ad, bp0);
                ffma2(acc[i][1], ad, bp1);
                ffma2(acc[i][2], ad, bp2);
                ffma2(acc[i][3], ad, bp3);
            }
        }
        if (kt + 1 < KT) {
            int nxt = cur ^ 1;
            As[nxt][lk+0][lr] = fa0.x; As[nxt][lk+1][lr] = fa0.y; As[nxt][lk+2][lr] = fa0.z; As[nxt][lk+3][lr] = fa0.w;
            As[nxt][lk+0][lr+64] = fa1.x; As[nxt][lk+1][lr+64] = fa1.y; As[nxt][lk+2][lr+64] = fa1.z; As[nxt][lk+3][lr+64] = fa1.w;
            Bs[nxt][lk+0][lr] = fb0.x; Bs[nxt][lk+1][lr] = fb0.y; Bs[nxt][lk+2][lr] = fb0.z; Bs[nxt][lk+3][lr] = fb0.w;
            Bs[nxt][lk+0][lr+64] = fb1.x; Bs[nxt][lk+1][lr+64] = fb1.y; Bs[nxt][lk+2][lr+64] = fb1.z; Bs[nxt][lk+3][lr+64] = fb1.w;
            __syncthreads();
        }
    }

    int nb = n0 + tx*8;
    float bvals[8];
    #pragma unroll
    for (int j = 0; j < 8; j++) bvals[j] = (nb + j < N) ? bias[nb + j] : 0.f;

    #pragma unroll
    for (int i = 0; i < 8; i++) {
        int m = m0 + ty*8 + i;
        if (m >= Mv) continue;
        float out[8];
        #pragma unroll
        for (int j = 0; j < 4; j++) {
            float2 v = fup(acc[i][j]);
            out[2*j]   = v.x + bvals[2*j];
            out[2*j+1] = v.y + bvals[2*j+1];
        }
        if (doRelu) {
            #pragma unroll
            for (int j = 0; j < 8; j++) out[j] = fmaxf(out[j], 0.f);
        }
        if (nb + 7 < N) {
            *(float4*)&C[(size_t)m*N + nb]     = make_float4(out[0], out[1], out[2], out[3]);
            *(float4*)&C[(size_t)m*N + nb + 4] = make_float4(out[4], out[5], out[6], out[7]);
        } else {
            #pragma unroll
            for (int j = 0; j < 8; j++)
                if (nb + j < N) C[(size_t)m*N + nb + j] = out[j];
        }
    }
}

// ---------------- small fp32 GEMM (64x64) with runtime M ----------------
__global__ void gemm_tn(const float* __restrict__ A, int lda,
                        const float* __restrict__ W,
                        const float* __restrict__ bias,
                        float* __restrict__ C,
                        int M, int N, int K, int doRelu,
                        const int* __restrict__ Mdev) {
    const int Mv = Mdev ? Mdev[0] : M;
    const int m0 = blockIdx.y * 64, n0 = blockIdx.x * 64;
    if (m0 >= Mv) return;

    __shared__ __align__(16) float As[16][64];
    __shared__ __align__(16) float Bs[16][64];

    const int tid = threadIdx.x;
    const int tx = tid & 15, ty = tid >> 4;

    unsigned long long acc[4][2];
    #pragma unroll
    for (int i = 0; i < 4; i++) { acc[i][0] = 0ULL; acc[i][1] = 0ULL; }

    for (int k0 = 0; k0 < K; k0 += 16) {
        #pragma unroll
        for (int i = 0; i < 4; i++) {
            int idx = tid + i*256;
            int r = idx >> 4, kk = idx & 15;
            int m = m0 + r, k = k0 + kk, n = n0 + r;
            As[kk][r] = (m < Mv && k < K) ? A[(size_t)m*lda + k] : 0.f;
            Bs[kk][r] = (n < N && k < K) ? W[(size_t)n*K + k] : 0.f;
        }
        __syncthreads();
        #pragma unroll
        for (int kk = 0; kk < 16; kk++) {
            float4 a4 = *(const float4*)&As[kk][ty*4];
            float4 b4 = *(const float4*)&Bs[kk][tx*4];
            unsigned long long b01 = fpk(b4.x, b4.y);
            unsigned long long b23 = fpk(b4.z, b4.w);
            unsigned long long a0 = fpk(a4.x, a4.x);
            unsigned long long a1 = fpk(a4.y, a4.y);
            unsigned long long a2 = fpk(a4.z, a4.z);
            unsigned long long a3 = fpk(a4.w, a4.w);
            ffma2(acc[0][0], a0, b01); ffma2(acc[0][1], a0, b23);
            ffma2(acc[1][0], a1, b01); ffma2(acc[1][1], a1, b23);
            ffma2(acc[2][0], a2, b01); ffma2(acc[2][1], a2, b23);
            ffma2(acc[3][0], a3, b01); ffma2(acc[3][1], a3, b23);
        }
        __syncthreads();
    }

    #pragma unroll
    for (int i = 0; i < 4; i++) {
        int m = m0 + ty*4 + i;
        if (m >= Mv) continue;
        float2 v0 = fup(acc[i][0]);
        float2 v1 = fup(acc[i][1]);
        float vals[4] = {v0.x, v0.y, v1.x, v1.y};
        #pragma unroll
        for (int jj = 0; jj < 4; jj++) {
            int n = n0 + tx*4 + jj;
            if (n < N) {
                float o = vals[jj] + bias[n];
                if (doRelu) o = fmaxf(o, 0.f);
                C[(size_t)m*N + n] = o;
            }
        }
    }
}

// ---------------- sequential LSTM: 8-CTA cluster per batch ----------------
// Each CTA owns 32 hidden units; W slice per step = 128 KB.
// h_new broadcast to all 8 peers' double-buffered hs via DSMEM; 1 cluster.sync/step.
#define CLUSTER_SYNC() do { \
    asm volatile("barrier.cluster.arrive.aligned;" ::: "memory"); \
    asm volatile("barrier.cluster.wait.aligned;" ::: "memory"); \
} while (0)

__global__ void __cluster_dims__(8, 1, 1) lstm_kernel(const float* __restrict__ bhh) {
    const int tid = threadIdx.x;           // 256
    const int j   = tid & 31;              // unit within this CTA's 32
    const int s   = tid >> 5;              // k-slice 0..7 (32 k each)
    uint32_t rank;
    asm("mov.u32 %0, %%cluster_ctarank;" : "=r"(rank));
    const int b  = blockIdx.x >> 3;
    const int j0 = rank * 32;              // this CTA's unit base

    const int steps    = g_bcnt[b];
    const int base_row = g_bstart[b];

    __shared__ __align__(16) float hs[2][Hn];
    __shared__ unsigned long long pIF[8][32], pGO[8][32];

    hs[0][tid] = g_h0[b*Hn + tid];

    float mc = 0.f, bi = 0.f, bf = 0.f, bg = 0.f, bo = 0.f;
    if (tid < 32) {
        int ju = j0 + tid;
        mc = g_m0[b*Hn + ju];
        bi = bhh[ju]; bf = bhh[256 + ju]; bg = bhh[512 + ju]; bo = bhh[768 + ju];
    }
    const ulonglong2* W2 = reinterpret_cast<const ulonglong2*>(g_whhR4);
    const uint32_t hs_u32 = smem_u32(hs);

    CLUSTER_SYNC();   // hs[0] init visible everywhere (and in-block sync)

    int cur = 0;
    for (int t = 0; t < steps; t++) {
        unsigned long long aIF = 0ULL, aGO = 0ULL;
        const float* h = hs[cur];
        const int kb = s * 32;
        #pragma unroll 4
        for (int k0 = 0; k0 < 32; k0 += 4) {
            float4 h4 = *(const float4*)&h[kb + k0];
            ulonglong2 w;
            unsigned long long hd;
            w = W2[(size_t)(kb+k0+0)*Hn + j0 + j]; hd = fpk(h4.x, h4.x); ffma2(aIF, hd, w.x); ffma2(aGO, hd, w.y);
            w = W2[(size_t)(kb+k0+1)*Hn + j0 + j]; hd = fpk(h4.y, h4.y); ffma2(aIF, hd, w.x); ffma2(aGO, hd, w.y);
            w = W2[(size_t)(kb+k0+2)*Hn + j0 + j]; hd = fpk(h4.z, h4.z); ffma2(aIF, hd, w.x); ffma2(aGO, hd, w.y);
            w = W2[(size_t)(kb+k0+3)*Hn + j0 + j]; hd = fpk(h4.w, h4.w); ffma2(aIF, hd, w.x); ffma2(aGO, hd, w.y);
        }
        pIF[s][j] = aIF;
        pGO[s][j] = aGO;
        __syncthreads();

        if (tid < 32) {
            float iacc = 0.f, facc = 0.f, gacc = 0.f, oacc = 0.f;
            #pragma unroll
            for (int r = 0; r < 8; r++) {
                float2 iv = fup(pIF[r][tid]);
                float2 gv = fup(pGO[r][tid]);
                iacc += iv.x; facc += iv.y;
                gacc += gv.x; oacc += gv.y;
            }

            size_t base = (size_t)(base_row + t) * (4*Hn) + j0 + tid;
            float gi = g_xg[base]        + bi + iacc;
            float gf = g_xg[base + 256]  + bf + facc;
            float gg = g_xg[base + 512]  + bg + gacc;
            float go = g_xg[base + 768]  + bo + oacc;
            mc = sigm(gf)*mc + sigm(gi)*tanhf(gg);
            float hn = sigm(go)*tanhf(mc);
            g_hs[(size_t)(base_row + t)*Hn + j0 + tid] = hn;

            // broadcast hn into all 8 cluster CTAs' hs[cur^1][j0+tid]
            uint32_t laddr = hs_u32 + (uint32_t)(((cur ^ 1) * Hn + j0 + tid) * 4);
            #pragma unroll
            for (int rr = 0; rr < 8; rr++) {
                uint32_t pa;
                asm("mapa.shared::cluster.u32 %0, %1, %2;" : "=r"(pa) : "r"(laddr), "r"(rr));
                asm volatile("st.shared::cluster.f32 [%0], %1;" :: "r"(pa), "f"(hn));
            }
        }
        CLUSTER_SYNC();
        cur ^= 1;
    }
}

// ---------------- fused attention per (b,t), compact-aware, fused chh split ----------------
__global__ void attn_kernel(const float* __restrict__ image,
                            const float* __restrict__ Wz,
                            const float* __restrict__ bz,
                            float* __restrict__ dout) {
    int bt = blockIdx.x;
    int b = bt / STEPS;
    int tid = threadIdx.x;             // 128
    int wid = tid >> 5, lane = tid & 31;
    int v = g_rmap[bt];

    if (v < 0) {
        if (tid < Pn+1)
            dout[ATT_OFF + (size_t)bt*(Pn+1) + tid] = 0.f;
        return;
    }

    __shared__ float shh2[Hn], shh[Hn], ss[Hn], ss2[Hn];
    __shared__ float zz[Pn+1], aw[Pn+1];

    for (int k = tid; k < Hn; k += 128) {
        shh2[k] = g_hh2[(size_t)v*Hn + k];
        shh [k] = g_fo [(size_t)v*2*En + k];
        ss  [k] = g_fo [(size_t)v*2*En + En + k];
        ss2 [k] = g_ss2[(size_t)v*Hn + k];
    }
    __syncthreads();

    for (int p = wid; p < Pn+1; p += 4) {
        float part = 0.f;
        const float* vrow = (p < Pn) ? (g_v + (size_t)(b*Pn + p)*Hn) : ss2;
        for (int k = lane; k < Hn; k += 32)
            part += Wz[k] * tanhf(vrow[k] + shh2[k]);
        #pragma unroll
        for (int off = 16; off > 0; off >>= 1)
            part += __shfl_down_sync(0xffffffff, part, off);
        if (lane == 0) zz[p] = part + bz[0];
    }
    __syncthreads();

    if (tid == 0) {
        float mx = zz[0];
        for (int p = 1; p < Pn+1; p++) mx = fmaxf(mx, zz[p]);
        float s = 0.f;
        for (int p = 0; p < Pn+1; p++) { float e = __expf(zz[p]-mx); aw[p] = e; s += e; }
        float inv = 1.f / s;
        for (int p = 0; p < Pn+1; p++) aw[p] *= inv;
    }
    __syncthreads();

    if (tid < Pn+1)
        dout[ATT_OFF + (size_t)bt*(Pn+1) + tid] = aw[tid];

    // chh = c + hh, split to bf16 hi/lo inline (2 elements per thread)
    #pragma unroll
    for (int kk = 0; kk < 2; kk++) {
        int k = tid + kk*128;
        float c = aw[Pn] * ss[k];
        #pragma unroll 7
        for (int p = 0; p < Pn; p++)
            c = fmaf(aw[p], image[(size_t)(b*Pn + p)*En + k], c);
        float f = c + shh[k];
        __nv_bfloat16 hb = __float2bfloat16_rn(f);
        float r = f - __bfloat162float(hb);
        g_chh_h[(size_t)v*En + k] = hb;
        g_chh_l[(size_t)v*En + k] = __float2bfloat16_rn(r);
    }
}

// ============== tensor-core logits GEMM via mma.sync (bf16 hi/lo, fp32 acc) ==============
// Tile 128x64, 8 warps (4x2), warp tile 32x32, 2 CTAs/SM.
// Double-buffered k-chunks prefetched with cp.async.
#define LTK 64
#define LCHUNK_A (128*LTK*2)            // 16384 bytes per A buffer
#define LCHUNK_Bt (64*LTK*2)            // 8192 bytes per B buffer
#define LBUF (2*LCHUNK_A + 2*LCHUNK_Bt) // 49152 per stage
#define LOGITS_SMEM (2*LBUF)            // 98304

__device__ __forceinline__ void load_chunk_a_async(uint32_t dstu,
                                                   const __nv_bfloat16* __restrict__ src,
                                                   int row0, int rows_valid, int kc, int tid) {
    #pragma unroll
    for (int i = 0; i < 4; i++) {       // 128 rows x 8 chunks = 1024
        int idx = tid + i*256;
        int row = idx >> 3, ch = idx & 7;
        uint32_t off = (uint32_t)(row*128 + ch*16);
        off ^= (off >> 3) & 0x70;
        int gr = row0 + row;
        int ok = (gr < rows_valid);
        int grc = ok ? gr : 0;
        cpa16(dstu + off, src + (size_t)grc*256 + kc + ch*8, ok ? 16 : 0);
    }
}
__device__ __forceinline__ void load_chunk_b_async(uint32_t dstu,
                                                   const __nv_bfloat16* __restrict__ src,
                                                   int row0, int kc, int tid) {
    #pragma unroll
    for (int i = 0; i < 2; i++) {       // 64 rows x 8 chunks = 512
        int idx = tid + i*256;
        int row = idx >> 3, ch = idx & 7;
        uint32_t off = (uint32_t)(row*128 + ch*16);
        off ^= (off >> 3) & 0x70;
        cpa16(dstu + off, src + (size_t)(row0 + row)*256 + kc + ch*8, 16);
    }
}

__global__ __launch_bounds__(256, 2)
void logits_mma(const __nv_bfloat16* __restrict__ Ah, const __nv_bfloat16* __restrict__ Al,
                const __nv_bfloat16* __restrict__ Bh, const __nv_bfloat16* __restrict__ Bl,
                const float* __restrict__ bp, float* __restrict__ out,
                const int* __restrict__ Vdev) {
    const int V = Vdev[0];
    const int m0 = blockIdx.y * 128;
    if (m0 >= V) return;
    const int n0 = blockIdx.x * 64;

    extern __shared__ char smem[];
    const uint32_t base_u = smem_u32(smem);
    // per-stage offsets
    const uint32_t oAh = 0, oAl = LCHUNK_A, oBh = 2*LCHUNK_A, oBl = 2*LCHUNK_A + LCHUNK_Bt;

    const int tid = threadIdx.x;
    const int wid = tid >> 5, lane = tid & 31;
    const int wm = wid >> 1;      // 0..3
    const int wn = wid & 1;       // 0..1

    float acc[2][4][4];
    #pragma unroll
    for (int a = 0; a < 2; a++)
        #pragma unroll
        for (int b = 0; b < 4; b++)
            #pragma unroll
            for (int c = 0; c < 4; c++) acc[a][b][c] = 0.f;

    const int a_lr = lane & 15, a_lc = lane >> 4;
    const int b_lr = lane & 7,  b_lc = (lane >> 3) & 1;

    // prologue: prefetch chunk 0 into stage 0
    {
        uint32_t st = base_u;
        load_chunk_a_async(st + oAh, Ah, m0, V, 0, tid);
        load_chunk_a_async(st + oAl, Al, m0, V, 0, tid);
        load_chunk_b_async(st + oBh, Bh, n0, 0, tid);
        load_chunk_b_async(st + oBl, Bl, n0, 0, tid);
        CP_COMMIT();
    }

    const int NCH = En / LTK;   // 4
    for (int kci = 0; kci < NCH; kci++) {
        const int cur = kci & 1;
        const uint32_t st = base_u + cur * LBUF;
        if (kci + 1 < NCH) {
            uint32_t nx = base_u + (cur ^ 1) * LBUF;
            int kc = (kci + 1) * LTK;
            load_chunk_a_async(nx + oAh, Ah, m0, V, kc, tid);
            load_chunk_a_async(nx + oAl, Al, m0, V, kc, tid);
            load_chunk_b_async(nx + oBh, Bh, n0, kc, tid);
            load_chunk_b_async(nx + oBl, Bl, n0, kc, tid);
            CP_COMMIT();
            CP_WAIT1();
        } else {
            CP_WAIT0();
        }
        __syncthreads();

        const uint32_t uAh = st + oAh, uAl = st + oAl;
        const uint32_t uBh = st + oBh, uBl = st + oBl;
        #pragma unroll
        for (int ks = 0; ks < LTK/16; ks++) {
            uint32_t ah[2][4], al[2][4], bh[4][2], bl[4][2];
            #pragma unroll
            for (int mt = 0; mt < 2; mt++) {
                uint32_t off = (uint32_t)((wm*32 + mt*16 + a_lr)*128 + ks*32 + a_lc*16);
                off ^= (off >> 3) & 0x70;
                ldsm4(ah[mt], uAh + off);
                ldsm4(al[mt], uAl + off);
            }
            #pragma unroll
            for (int nt = 0; nt < 4; nt++) {
                uint32_t off = (uint32_t)((wn*32 + nt*8 + b_lr)*128 + ks*32 + b_lc*16);
                off ^= (off >> 3) & 0x70;
                ldsm2(bh[nt], uBh + off);
                ldsm2(bl[nt], uBl + off);
            }
            #pragma unroll
            for (int mt = 0; mt < 2; mt++)
                #pragma unroll
                for (int nt = 0; nt < 4; nt++)
                    mma_bf16(acc[mt][nt], ah[mt], bh[nt]);
            #pragma unroll
            for (int mt = 0; mt < 2; mt++)
                #pragma unroll
                for (int nt = 0; nt < 4; nt++)
                    mma_bf16(acc[mt][nt], ah[mt], bl[nt]);
            #pragma unroll
            for (int mt = 0; mt < 2; mt++)
                #pragma unroll
                for (int nt = 0; nt < 4; nt++)
                    mma_bf16(acc[mt][nt], al[mt], bh[nt]);
        }
        __syncthreads();
    }

    #pragma unroll
    for (int mt = 0; mt < 2; mt++) {
        int m1 = m0 + wm*32 + mt*16 + (lane >> 2);
        int m2 = m1 + 8;
        #pragma unroll
        for (int nt = 0; nt < 4; nt++) {
            int n = n0 + wn*32 + nt*8 + (lane & 3)*2;
            float2 bb = *(const float2*)&bp[n];
            const float* c = acc[mt][nt];
            if (m1 < V)
                *(float2*)&out[(size_t)m1*Vn + n] = make_float2(c[0] + bb.x, c[1] + bb.y);
            if (m2 < V)
                *(float2*)&out[(size_t)m2*Vn + n] = make_float2(c[2] + bb.x, c[3] + bb.y);
        }
    }
}

// ---------------- online log-softmax + argmax + mask + output ----------------
__global__ void softmax_kernel(const float* __restrict__ temp,
                               float* __restrict__ dout) {
    int bt = blockIdx.x;
    int b = bt / STEPS;
    int tid = threadIdx.x;             // 512
    int crow = g_rmap[bt];
    float4* lp4 = (float4*)(dout + LOGP_OFF + (size_t)bt*Vn);

    __shared__ float smx[512]; __shared__ int sai[512]; __shared__ float ssum[512];

    if (crow < 0) {
        float4 z = make_float4(0.f, 0.f, 0.f, 0.f);
        for (int i = tid; i < Vn/4; i += 512) lp4[i] = z;
        if (tid == 0) dout[TXT_OFF + bt] = 0.f;
        return;
    }

    float ls = 1.0f / temp[b];
    const float4* row4 = (const float4*)(g_logits + (size_t)crow*Vn);

    float mx = -3.402823466e38f; float sum = 0.f; int ai = 0;
    for (int i = tid; i < Vn/4; i += 512) {
        float4 v = row4[i];
        float vv[4] = {v.x, v.y, v.z, v.w};
        #pragma unroll
        for (int c = 0; c < 4; c++) {
            float x = vv[c];
            if (x > mx) {
                sum = sum * __expf((mx - x)*ls) + 1.f;
                mx = x; ai = 4*i + c;
            } else {
                sum += __expf((x - mx)*ls);
            }
        }
    }
    smx[tid] = mx; sai[tid] = ai; ssum[tid] = sum; __syncthreads();
    for (int s = 256; s > 0; s >>= 1) {
        if (tid < s) {
            float m1 = smx[tid],   m2 = smx[tid+s];
            float s1 = ssum[tid],  s2 = ssum[tid+s];
            int   i1 = sai[tid],   i2 = sai[tid+s];
            if (m2 > m1 || (m2 == m1 && i2 < i1)) {
                smx[tid] = m2; sai[tid] = i2;
                ssum[tid] = s2 + s1 * __expf((m1 - m2)*ls);
            } else {
                ssum[tid] = s1 + s2 * __expf((m2 - m1)*ls);
            }
        }
        __syncthreads();
    }
    mx = smx[0]; ai = sai[0];
    float lse = logf(ssum[0]);

    for (int i = tid; i < Vn/4; i += 512) {
        float4 v = row4[i];
        float4 o;
        o.x = (v.x - mx)*ls - lse;
        o.y = (v.y - mx)*ls - lse;
        o.z = (v.z - mx)*ls - lse;
        o.w = (v.w - mx)*ls - lse;
        lp4[i] = o;
    }
    if (tid == 0) dout[TXT_OFF + bt] = (float)ai;
}

// ---------------- launcher ----------------
extern "C" void kernel_launch(void* const* d_in, const int* in_sizes, int n_in,
                              void* d_out, int out_size) {
    const float* image = (const float*)d_in[0];
    const float* vp    = (const float*)d_in[1];
    const float* label = (const float*)d_in[2];
    const float* topic = (const float*)d_in[3];
    const float* temp  = (const float*)d_in[4];
    const int*   text  = (const int*)  d_in[5];
    const int*   length= (const int*)  d_in[6];
    const float* emb   = (const float*)d_in[7];
    const float* Wv    = (const float*)d_in[8];
    const float* bv    = (const float*)d_in[9];
    const float* Wh    = (const float*)d_in[10];
    const float* bh    = (const float*)d_in[11];
    const float* Wm    = (const float*)d_in[12];
    const float* bm    = (const float*)d_in[13];
    const float* Wih   = (const float*)d_in[14];
    const float* bih   = (const float*)d_in[15];
    const float* Whh   = (const float*)d_in[16];
    const float* bhh   = (const float*)d_in[17];
    const float* Wfc   = (const float*)d_in[18];
    const float* bfc   = (const float*)d_in[19];
    const float* Whh2  = (const float*)d_in[20];
    const float* bhh2  = (const float*)d_in[21];
    const float* Ws    = (const float*)d_in[22];
    const float* bs    = (const float*)d_in[23];
    const float* Wz    = (const float*)d_in[24];
    const float* bz    = (const float*)d_in[25];
    const float* Wp    = (const float*)d_in[26];
    const float* bp    = (const float*)d_in[27];
    float* dout = (float*)d_out;

    float *p_xcat, *p_xg, *p_v, *p_hs, *p_fo, *p_hh2, *p_ss2, *p_logits;
    __nv_bfloat16 *p_wph, *p_wpl, *p_chh_h, *p_chh_l;
    int *p_V;
    cudaGetSymbolAddress((void**)&p_xcat,   g_xcat);
    cudaGetSymbolAddress((void**)&p_xg,     g_xg);
    cudaGetSymbolAddress((void**)&p_v,      g_v);
    cudaGetSymbolAddress((void**)&p_hs,     g_hs);
    cudaGetSymbolAddress((void**)&p_fo,     g_fo);
    cudaGetSymbolAddress((void**)&p_hh2,    g_hh2);
    cudaGetSymbolAddress((void**)&p_ss2,    g_ss2);
    cudaGetSymbolAddress((void**)&p_logits, g_logits);
    cudaGetSymbolAddress((void**)&p_wph,    g_wph);
    cudaGetSymbolAddress((void**)&p_wpl,    g_wpl);
    cudaGetSymbolAddress((void**)&p_chh_h,  g_chh_h);
    cudaGetSymbolAddress((void**)&p_chh_l,  g_chh_l);
    cudaGetSymbolAddress((void**)&p_V,      g_V);

    cudaFuncSetAttribute(logits_mma, cudaFuncAttributeMaxDynamicSharedMemorySize,
                         LOGITS_SMEM);

    // valid-row maps + Wp hi/lo split (independent)
    build_maps<<<1, 256>>>(length);
    split_bf16<<<(Vn*En/4 + 255)/256, 256>>>(Wp, p_wph, p_wpl, Vn*En/4);

    prep_kernel<<<Bn, 256>>>(image, vp, label, topic, Wh, bh, Wm, bm);
    whh_transpose<<<Hn, Hn>>>(Whh);
    xcat_kernel<<<ROWS, 256>>>(text, emb);   // compact rows

    // Xg = Xcat @ Wih^T + bih on COMPACT rows : (V x 1024), K=792
    gemm_tn128<<<dim3((4*Hn+127)/128, (ROWS+127)/128), 256>>>(p_xcat, INn, Wih, bih, p_xg,
                                                              ROWS, 4*Hn, INn, 0, p_V);
    // v = image @ Wv^T + bv (all rows)
    gemm_tn<<<dim3((Hn+63)/64, (Bn*Pn+63)/64), 256>>>(image, En, Wv, bv, p_v,
                                                      Bn*Pn, Hn, En, 0, nullptr);
    // sequential LSTM: 8-CTA cluster per batch (256 CTAs)
    lstm_kernel<<<Bn*8, 256>>>(bhh);

    // fo = relu(Hs @ Wfc^T + bfc) on compact rows
    gemm_tn<<<dim3((2*En+63)/64, (ROWS+63)/64), 256>>>(p_hs, Hn, Wfc, bfc, p_fo,
                                                       ROWS, 2*En, Hn, 1, p_V);
    // _hh, _s on compact rows
    gemm_tn<<<dim3((Hn+63)/64, (ROWS+63)/64), 256>>>(p_fo, 2*En, Whh2, bhh2, p_hh2,
                                                     ROWS, Hn, En, 0, p_V);
    gemm_tn<<<dim3((Hn+63)/64, (ROWS+63)/64), 256>>>(p_fo + En, 2*En, Ws, bs, p_ss2,
                                                     ROWS, Hn, En, 0, p_V);
    // attention: att out + chh bf16 hi/lo split fused into epilogue
    attn_kernel<<<ROWS, 128>>>(image, Wz, bz, dout);

    // tensor-core logits GEMM (compact rows), 128x64 tiles, cp.async double-buffered
    logits_mma<<<dim3(Vn/64, (ROWS+127)/128), 256, LOGITS_SMEM>>>(
        p_chh_h, p_chh_l, p_wph, p_wpl, bp, p_logits, p_V);

    // online log-softmax + argmax + masking + outputs
    softmax_kernel<<<ROWS, 512>>>(temp, dout);
}

// round 16
// speedup vs baseline: 2.4011x; 1.1488x over previous
#include <cuda_runtime.h>
#include <cuda_bf16.h>
#include <math.h>
#include <stdint.h>

// ---------------- problem constants ----------------
#define Bn 32
#define Pn 49
#define En 256
#define Hn 256
#define Tn 48
#define STEPS 47
#define Vn 32000
#define INn 792          // E + VP + LB + H + E
#define KP  832          // INn padded to 13*64 for mma k-chunks
#define XSn 536          // E + VP + LB + H
#define ROWS (Bn*STEPS)  // 1504

#define ATT_OFF 0
#define LOGP_OFF (ROWS*(Pn+1))                 // 75200
#define TXT_OFF  (LOGP_OFF + (size_t)ROWS*Vn)

// ---------------- scratch (device globals; no allocation) ----------------
__device__ float g_xs  [Bn*XSn];
__device__ float g_h0  [Bn*Hn];
__device__ float g_m0  [Bn*Hn];
__device__ float g_xg  [ROWS*4*Hn];         // compact rows
__device__ float4 g_whhR4[Hn*Hn];
__device__ float g_v   [Bn*Pn*Hn];
__device__ float g_hs  [ROWS*Hn];           // compact rows
__device__ float g_fo  [ROWS*2*En];         // compact rows
__device__ float g_hh2 [ROWS*Hn];           // compact rows
__device__ float g_ss2 [ROWS*Hn];           // compact rows
__device__ float g_logits[(size_t)ROWS*Vn]; // compact rows (~192 MB cap)

// valid-row compaction maps
__device__ int g_V[1];
__device__ int g_rmap[ROWS];   // bt -> compact index (or -1)
__device__ int g_bcnt[Bn];     // valid steps per batch
__device__ int g_bstart[Bn];   // compact row offset per batch

// bf16 hi/lo splits for tensor-core GEMMs
__device__ __align__(256) __nv_bfloat16 g_wph[(size_t)Vn*En];
__device__ __align__(256) __nv_bfloat16 g_wpl[(size_t)Vn*En];
__device__ __align__(256) __nv_bfloat16 g_chh_h[ROWS*En];
__device__ __align__(256) __nv_bfloat16 g_chh_l[ROWS*En];
__device__ __align__(256) __nv_bfloat16 g_xcat_h[ROWS*KP];
__device__ __align__(256) __nv_bfloat16 g_xcat_l[ROWS*KP];
__device__ __align__(256) __nv_bfloat16 g_wih_h[4*Hn*KP];
__device__ __align__(256) __nv_bfloat16 g_wih_l[4*Hn*KP];

// ---------------- packed f32x2 helpers (Blackwell FFMA2) ----------------
__device__ __forceinline__ unsigned long long fpk(float lo, float hi) {
    unsigned long long r;
    asm("mov.b64 %0, {%1, %2};" : "=l"(r) : "f"(lo), "f"(hi));
    return r;
}
__device__ __forceinline__ void ffma2(unsigned long long& d,
                                      unsigned long long a,
                                      unsigned long long b) {
    asm("fma.rn.f32x2 %0, %1, %2, %3;" : "=l"(d) : "l"(a), "l"(b), "l"(d));
}
__device__ __forceinline__ float2 fup(unsigned long long v) {
    float2 r;
    asm("mov.b64 {%0, %1}, %2;" : "=f"(r.x), "=f"(r.y) : "l"(v));
    return r;
}
__device__ __forceinline__ float sigm(float x) {
    return 1.0f / (1.0f + __expf(-x));
}
__device__ __forceinline__ uint32_t smem_u32(const void* p) {
    uint32_t a;
    asm("{ .reg .u64 t; cvta.to.shared.u64 t, %1; cvt.u32.u64 %0, t; }"
        : "=r"(a) : "l"(p));
    return a;
}

// ---------------- warp-level tensor core helpers (sm_80+ ISA) ----------------
__device__ __forceinline__ void ldsm4(uint32_t* r, uint32_t addr) {
    asm volatile("ldmatrix.sync.aligned.m8n8.x4.shared.b16 {%0,%1,%2,%3}, [%4];"
        : "=r"(r[0]), "=r"(r[1]), "=r"(r[2]), "=r"(r[3]) : "r"(addr));
}
__device__ __forceinline__ void ldsm2(uint32_t* r, uint32_t addr) {
    asm volatile("ldmatrix.sync.aligned.m8n8.x2.shared.b16 {%0,%1}, [%2];"
        : "=r"(r[0]), "=r"(r[1]) : "r"(addr));
}
__device__ __forceinline__ void mma_bf16(float* c, const uint32_t* a, const uint32_t* b) {
    asm volatile(
        "mma.sync.aligned.m16n8k16.row.col.f32.bf16.bf16.f32 "
        "{%0,%1,%2,%3}, {%4,%5,%6,%7}, {%8,%9}, {%0,%1,%2,%3};"
        : "+f"(c[0]), "+f"(c[1]), "+f"(c[2]), "+f"(c[3])
        : "r"(a[0]), "r"(a[1]), "r"(a[2]), "r"(a[3]), "r"(b[0]), "r"(b[1]));
}
// cp.async 16B with src-size (0 => zero-fill)
__device__ __forceinline__ void cpa16(uint32_t dst, const void* src, int szbytes) {
    asm volatile("cp.async.cg.shared.global [%0], [%1], 16, %2;"
        :: "r"(dst), "l"(src), "r"(szbytes));
}
#define CP_COMMIT() asm volatile("cp.async.commit_group;" ::: "memory")
#define CP_WAIT1()  asm volatile("cp.async.wait_group 1;" ::: "memory")
#define CP_WAIT0()  asm volatile("cp.async.wait_group 0;" ::: "memory")

__device__ __forceinline__ void split1(float f, __nv_bfloat16& h, __nv_bfloat16& l) {
    h = __float2bfloat16_rn(f);
    l = __float2bfloat16_rn(f - __bfloat162float(h));
}

// ---------------- valid-row maps ----------------
__global__ void build_maps(const int* __restrict__ length) {
    __shared__ int cnt[Bn], start[Bn];
    int tid = threadIdx.x;
    if (tid < Bn) {
        int c = length[tid] - 1;
        if (c < 0) c = 0;
        if (c > STEPS) c = STEPS;
        cnt[tid] = c;
        g_bcnt[tid] = c;
    }
    __syncthreads();
    if (tid == 0) {
        int s = 0;
        for (int b = 0; b < Bn; b++) { start[b] = s; g_bstart[b] = s; s += cnt[b]; }
        g_V[0] = s;
    }
    __syncthreads();
    for (int bt = tid; bt < ROWS; bt += 256) {
        int b = bt / STEPS, t = bt % STEPS;
        g_rmap[bt] = (t < cnt[b]) ? (start[b] + t) : -1;
    }
}

// ---------------- prep: image_mean, x_static, h0, m0 ----------------
__global__ void prep_kernel(const float* __restrict__ image,
                            const float* __restrict__ vp,
                            const float* __restrict__ label,
                            const float* __restrict__ topic,
                            const float* __restrict__ Wh, const float* __restrict__ bh,
                            const float* __restrict__ Wm, const float* __restrict__ bm) {
    int b = blockIdx.x;
    int tid = threadIdx.x;   // 256
    __shared__ __align__(16) float im[En];

    float s = 0.f;
    #pragma unroll 7
    for (int p = 0; p < Pn; p++) s += image[(b*Pn + p)*En + tid];
    float mean = s * (1.0f/49.0f);
    im[tid] = mean;

    g_xs[b*XSn + tid] = mean;
    if (tid < 8)  g_xs[b*XSn + 256 + tid] = vp[b*8 + tid];
    if (tid < 16) g_xs[b*XSn + 264 + tid] = label[b*16 + tid];
    g_xs[b*XSn + 280 + tid] = topic[b*Hn + tid];
    __syncthreads();

    float ah = bh[tid], am = bm[tid];
    #pragma unroll 8
    for (int k = 0; k < En; k++) {
        float x = im[k];
        ah = fmaf(x, Wh[tid*En + k], ah);
        am = fmaf(x, Wm[tid*En + k], am);
    }
    g_h0[b*Hn + tid] = tanhf(ah);
    g_m0[b*Hn + tid] = tanhf(am);
}

// ---------------- Whh reorder for coalesced LSTM reads ----------------
__global__ void whh_transpose(const float* __restrict__ Whh) {
    int k = blockIdx.x;
    int j = threadIdx.x;
    float4 w;
    w.x = Whh[(0*Hn + j)*Hn + k];
    w.y = Whh[(1*Hn + j)*Hn + k];
    w.z = Whh[(2*Hn + j)*Hn + k];
    w.w = Whh[(3*Hn + j)*Hn + k];
    g_whhR4[k*Hn + j] = w;
}

// ---------------- build concat rows (compact), bf16 hi/lo direct ----------------
__global__ void xcat_kernel(const int* __restrict__ text,
                            const float* __restrict__ emb) {
    int bt = blockIdx.x;
    int v = g_rmap[bt];
    if (v < 0) return;
    int b = bt / STEPS, t = bt % STEPS;
    int tid = threadIdx.x;      // 256
    int tok = text[b*Tn + t];
    __nv_bfloat16* rh = g_xcat_h + (size_t)v*KP;
    __nv_bfloat16* rl = g_xcat_l + (size_t)v*KP;
    for (int i = tid; i < XSn; i += 256) {
        __nv_bfloat16 h, l;
        split1(g_xs[b*XSn + i], h, l);
        rh[i] = h; rl[i] = l;
    }
    {
        __nv_bfloat16 h, l;
        split1(emb[(size_t)tok*En + tid], h, l);
        rh[XSn + tid] = h; rl[XSn + tid] = l;
    }
    // pad 792..831 with zeros
    if (tid < KP - INn) {
        rh[INn + tid] = __float2bfloat16_rn(0.f);
        rl[INn + tid] = __float2bfloat16_rn(0.f);
    }
}

// ---------------- bf16 hi/lo split (for Wp, contiguous) ----------------
__global__ void split_bf16(const float* __restrict__ src,
                           __nv_bfloat16* __restrict__ hi,
                           __nv_bfloat16* __restrict__ lo, int n4) {
    int i = blockIdx.x*256 + threadIdx.x;
    if (i >= n4) return;
    float4 v = ((const float4*)src)[i];
    float f[4] = {v.x, v.y, v.z, v.w};
    unsigned short h[4], l[4];
    #pragma unroll
    for (int k = 0; k < 4; k++) {
        __nv_bfloat16 hb = __float2bfloat16_rn(f[k]);
        float r = f[k] - __bfloat162float(hb);
        __nv_bfloat16 lb = __float2bfloat16_rn(r);
        h[k] = __bfloat16_as_ushort(hb);
        l[k] = __bfloat16_as_ushort(lb);
    }
    uint2 uh, ul;
    uh.x = (uint32_t)h[0] | ((uint32_t)h[1] << 16);
    uh.y = (uint32_t)h[2] | ((uint32_t)h[3] << 16);
    ul.x = (uint32_t)l[0] | ((uint32_t)l[1] << 16);
    ul.y = (uint32_t)l[2] | ((uint32_t)l[3] << 16);
    ((uint2*)hi)[i] = uh;
    ((uint2*)lo)[i] = ul;
}

// ---------------- pad-split for Wih: [1024 x 792] -> [1024 x 832] hi/lo ----------------
__global__ void split_pad_wih(const float* __restrict__ src) {
    int row = blockIdx.x;        // 1024
    int tid = threadIdx.x;       // 256
    const float* s = src + (size_t)row*INn;
    __nv_bfloat16* rh = g_wih_h + (size_t)row*KP;
    __nv_bfloat16* rl = g_wih_l + (size_t)row*KP;
    for (int i = tid; i < KP; i += 256) {
        float f = (i < INn) ? s[i] : 0.f;
        __nv_bfloat16 h, l;
        split1(f, h, l);
        rh[i] = h; rl[i] = l;
    }
}

// ---------------- small fp32 GEMM (64x64) with runtime M ----------------
__global__ void gemm_tn(const float* __restrict__ A, int lda,
                        const float* __restrict__ W,
                        const float* __restrict__ bias,
                        float* __restrict__ C,
                        int M, int N, int K, int doRelu,
                        const int* __restrict__ Mdev) {
    const int Mv = Mdev ? Mdev[0] : M;
    const int m0 = blockIdx.y * 64, n0 = blockIdx.x * 64;
    if (m0 >= Mv) return;

    __shared__ __align__(16) float As[16][64];
    __shared__ __align__(16) float Bs[16][64];

    const int tid = threadIdx.x;
    const int tx = tid & 15, ty = tid >> 4;

    unsigned long long acc[4][2];
    #pragma unroll
    for (int i = 0; i < 4; i++) { acc[i][0] = 0ULL; acc[i][1] = 0ULL; }

    for (int k0 = 0; k0 < K; k0 += 16) {
        #pragma unroll
        for (int i = 0; i < 4; i++) {
            int idx = tid + i*256;
            int r = idx >> 4, kk = idx & 15;
            int m = m0 + r, k = k0 + kk, n = n0 + r;
            As[kk][r] = (m < Mv && k < K) ? A[(size_t)m*lda + k] : 0.f;
            Bs[kk][r] = (n < N && k < K) ? W[(size_t)n*K + k] : 0.f;
        }
        __syncthreads();
        #pragma unroll
        for (int kk = 0; kk < 16; kk++) {
            float4 a4 = *(const float4*)&As[kk][ty*4];
            float4 b4 = *(const float4*)&Bs[kk][tx*4];
            unsigned long long b01 = fpk(b4.x, b4.y);
            unsigned long long b23 = fpk(b4.z, b4.w);
            unsigned long long a0 = fpk(a4.x, a4.x);
            unsigned long long a1 = fpk(a4.y, a4.y);
            unsigned long long a2 = fpk(a4.z, a4.z);
            unsigned long long a3 = fpk(a4.w, a4.w);
            ffma2(acc[0][0], a0, b01); ffma2(acc[0][1], a0, b23);
            ffma2(acc[1][0], a1, b01); ffma2(acc[1][1], a1, b23);
            ffma2(acc[2][0], a2, b01); ffma2(acc[2][1], a2, b23);
            ffma2(acc[3][0], a3, b01); ffma2(acc[3][1], a3, b23);
        }
        __syncthreads();
    }

    #pragma unroll
    for (int i = 0; i < 4; i++) {
        int m = m0 + ty*4 + i;
        if (m >= Mv) continue;
        float2 v0 = fup(acc[i][0]);
        float2 v1 = fup(acc[i][1]);
        float vals[4] = {v0.x, v0.y, v1.x, v1.y};
        #pragma unroll
        for (int jj = 0; jj < 4; jj++) {
            int n = n0 + tx*4 + jj;
            if (n < N) {
                float o = vals[jj] + bias[n];
                if (doRelu) o = fmaxf(o, 0.f);
                C[(size_t)m*N + n] = o;
            }
        }
    }
}

// ---------------- sequential LSTM: 8-CTA cluster per batch ----------------
#define CLUSTER_SYNC() do { \
    asm volatile("barrier.cluster.arrive.aligned;" ::: "memory"); \
    asm volatile("barrier.cluster.wait.aligned;" ::: "memory"); \
} while (0)

__global__ void __cluster_dims__(8, 1, 1) lstm_kernel(const float* __restrict__ bhh) {
    const int tid = threadIdx.x;           // 256
    const int j   = tid & 31;              // unit within this CTA's 32
    const int s   = tid >> 5;              // k-slice 0..7 (32 k each)
    uint32_t rank;
    asm("mov.u32 %0, %%cluster_ctarank;" : "=r"(rank));
    const int b  = blockIdx.x >> 3;
    const int j0 = rank * 32;              // this CTA's unit base

    const int steps    = g_bcnt[b];
    const int base_row = g_bstart[b];

    __shared__ __align__(16) float hs[2][Hn];
    __shared__ unsigned long long pIF[8][32], pGO[8][32];

    hs[0][tid] = g_h0[b*Hn + tid];

    float mc = 0.f, bi = 0.f, bf = 0.f, bg = 0.f, bo = 0.f;
    if (tid < 32) {
        int ju = j0 + tid;
        mc = g_m0[b*Hn + ju];
        bi = bhh[ju]; bf = bhh[256 + ju]; bg = bhh[512 + ju]; bo = bhh[768 + ju];
    }
    const ulonglong2* W2 = reinterpret_cast<const ulonglong2*>(g_whhR4);
    const uint32_t hs_u32 = smem_u32(hs);

    CLUSTER_SYNC();   // hs[0] init visible everywhere (and in-block sync)

    int cur = 0;
    for (int t = 0; t < steps; t++) {
        unsigned long long aIF = 0ULL, aGO = 0ULL;
        const float* h = hs[cur];
        const int kb = s * 32;
        #pragma unroll 4
        for (int k0 = 0; k0 < 32; k0 += 4) {
            float4 h4 = *(const float4*)&h[kb + k0];
            ulonglong2 w;
            unsigned long long hd;
            w = W2[(size_t)(kb+k0+0)*Hn + j0 + j]; hd = fpk(h4.x, h4.x); ffma2(aIF, hd, w.x); ffma2(aGO, hd, w.y);
            w = W2[(size_t)(kb+k0+1)*Hn + j0 + j]; hd = fpk(h4.y, h4.y); ffma2(aIF, hd, w.x); ffma2(aGO, hd, w.y);
            w = W2[(size_t)(kb+k0+2)*Hn + j0 + j]; hd = fpk(h4.z, h4.z); ffma2(aIF, hd, w.x); ffma2(aGO, hd, w.y);
            w = W2[(size_t)(kb+k0+3)*Hn + j0 + j]; hd = fpk(h4.w, h4.w); ffma2(aIF, hd, w.x); ffma2(aGO, hd, w.y);
        }
        pIF[s][j] = aIF;
        pGO[s][j] = aGO;
        __syncthreads();

        if (tid < 32) {
            float iacc = 0.f, facc = 0.f, gacc = 0.f, oacc = 0.f;
            #pragma unroll
            for (int r = 0; r < 8; r++) {
                float2 iv = fup(pIF[r][tid]);
                float2 gv = fup(pGO[r][tid]);
                iacc += iv.x; facc += iv.y;
                gacc += gv.x; oacc += gv.y;
            }

            size_t base = (size_t)(base_row + t) * (4*Hn) + j0 + tid;
            float gi = g_xg[base]        + bi + iacc;
            float gf = g_xg[base + 256]  + bf + facc;
            float gg = g_xg[base + 512]  + bg + gacc;
            float go = g_xg[base + 768]  + bo + oacc;
            mc = sigm(gf)*mc + sigm(gi)*tanhf(gg);
            float hn = sigm(go)*tanhf(mc);
            g_hs[(size_t)(base_row + t)*Hn + j0 + tid] = hn;

            // broadcast hn into all 8 cluster CTAs' hs[cur^1][j0+tid]
            uint32_t laddr = hs_u32 + (uint32_t)(((cur ^ 1) * Hn + j0 + tid) * 4);
            #pragma unroll
            for (int rr = 0; rr < 8; rr++) {
                uint32_t pa;
                asm("mapa.shared::cluster.u32 %0, %1, %2;" : "=r"(pa) : "r"(laddr), "r"(rr));
                asm volatile("st.shared::cluster.f32 [%0], %1;" :: "r"(pa), "f"(hn));
            }
        }
        CLUSTER_SYNC();
        cur ^= 1;
    }
}

// ---------------- fused attention per (b,t), compact-aware, fused chh split ----------------
__global__ void attn_kernel(const float* __restrict__ image,
                            const float* __restrict__ Wz,
                            const float* __restrict__ bz,
                            float* __restrict__ dout) {
    int bt = blockIdx.x;
    int b = bt / STEPS;
    int tid = threadIdx.x;             // 128
    int wid = tid >> 5, lane = tid & 31;
    int v = g_rmap[bt];

    if (v < 0) {
        if (tid < Pn+1)
            dout[ATT_OFF + (size_t)bt*(Pn+1) + tid] = 0.f;
        return;
    }

    __shared__ float shh2[Hn], shh[Hn], ss[Hn], ss2[Hn];
    __shared__ float zz[Pn+1], aw[Pn+1];

    for (int k = tid; k < Hn; k += 128) {
        shh2[k] = g_hh2[(size_t)v*Hn + k];
        shh [k] = g_fo [(size_t)v*2*En + k];
        ss  [k] = g_fo [(size_t)v*2*En + En + k];
        ss2 [k] = g_ss2[(size_t)v*Hn + k];
    }
    __syncthreads();

    for (int p = wid; p < Pn+1; p += 4) {
        float part = 0.f;
        const float* vrow = (p < Pn) ? (g_v + (size_t)(b*Pn + p)*Hn) : ss2;
        for (int k = lane; k < Hn; k += 32)
            part += Wz[k] * tanhf(vrow[k] + shh2[k]);
        #pragma unroll
        for (int off = 16; off > 0; off >>= 1)
            part += __shfl_down_sync(0xffffffff, part, off);
        if (lane == 0) zz[p] = part + bz[0];
    }
    __syncthreads();

    if (tid == 0) {
        float mx = zz[0];
        for (int p = 1; p < Pn+1; p++) mx = fmaxf(mx, zz[p]);
        float s = 0.f;
        for (int p = 0; p < Pn+1; p++) { float e = __expf(zz[p]-mx); aw[p] = e; s += e; }
        float inv = 1.f / s;
        for (int p = 0; p < Pn+1; p++) aw[p] *= inv;
    }
    __syncthreads();

    if (tid < Pn+1)
        dout[ATT_OFF + (size_t)bt*(Pn+1) + tid] = aw[tid];

    // chh = c + hh, split to bf16 hi/lo inline (2 elements per thread)
    #pragma unroll
    for (int kk = 0; kk < 2; kk++) {
        int k = tid + kk*128;
        float c = aw[Pn] * ss[k];
        #pragma unroll 7
        for (int p = 0; p < Pn; p++)
            c = fmaf(aw[p], image[(size_t)(b*Pn + p)*En + k], c);
        float f = c + shh[k];
        __nv_bfloat16 hb, lb;
        split1(f, hb, lb);
        g_chh_h[(size_t)v*En + k] = hb;
        g_chh_l[(size_t)v*En + k] = lb;
    }
}

// ============== tensor-core GEMM via mma.sync (bf16 hi/lo, fp32 acc) ==============
// Tile 128x64, 8 warps (4x2), warp tile 32x32, cp.async double-buffered k-chunks.
#define LTK 64
#define LCHUNK_A (128*LTK*2)            // 16384 bytes per A buffer
#define LCHUNK_Bt (64*LTK*2)            // 8192 bytes per B buffer
#define LBUF (2*LCHUNK_A + 2*LCHUNK_Bt) // 49152 per stage
#define LOGITS_SMEM (2*LBUF)            // 98304

__device__ __forceinline__ void load_chunk_a_async(uint32_t dstu,
                                                   const __nv_bfloat16* __restrict__ src,
                                                   int row0, int rows_valid, int kc, int tid,
                                                   int stride) {
    #pragma unroll
    for (int i = 0; i < 4; i++) {       // 128 rows x 8 chunks = 1024
        int idx = tid + i*256;
        int row = idx >> 3, ch = idx & 7;
        uint32_t off = (uint32_t)(row*128 + ch*16);
        off ^= (off >> 3) & 0x70;
        int gr = row0 + row;
        int ok = (gr < rows_valid);
        int grc = ok ? gr : 0;
        cpa16(dstu + off, src + (size_t)grc*stride + kc + ch*8, ok ? 16 : 0);
    }
}
__device__ __forceinline__ void load_chunk_b_async(uint32_t dstu,
                                                   const __nv_bfloat16* __restrict__ src,
                                                   int row0, int kc, int tid, int stride) {
    #pragma unroll
    for (int i = 0; i < 2; i++) {       // 64 rows x 8 chunks = 512
        int idx = tid + i*256;
        int row = idx >> 3, ch = idx & 7;
        uint32_t off = (uint32_t)(row*128 + ch*16);
        off ^= (off >> 3) & 0x70;
        cpa16(dstu + off, src + (size_t)(row0 + row)*stride + kc + ch*8, 16);
    }
}

// Generic: out[M x N] (ldc = Nld) = Ahi/lo[M x Kstride] @ Bhi/lo[Nrows x Kstride]^T + bias
__global__ __launch_bounds__(256, 2)
void mma_tn(const __nv_bfloat16* __restrict__ Ah, const __nv_bfloat16* __restrict__ Al,
            const __nv_bfloat16* __restrict__ Bh, const __nv_bfloat16* __restrict__ Bl,
            const float* __restrict__ bias, float* __restrict__ out,
            const int* __restrict__ Vdev, int kstride, int nch, int Nld) {
    const int V = Vdev[0];
    const int m0 = blockIdx.y * 128;
    if (m0 >= V) return;
    const int n0 = blockIdx.x * 64;

    extern __shared__ char smem[];
    const uint32_t base_u = smem_u32(smem);
    const uint32_t oAh = 0, oAl = LCHUNK_A, oBh = 2*LCHUNK_A, oBl = 2*LCHUNK_A + LCHUNK_Bt;

    const int tid = threadIdx.x;
    const int wid = tid >> 5, lane = tid & 31;
    const int wm = wid >> 1;      // 0..3
    const int wn = wid & 1;       // 0..1

    float acc[2][4][4];
    #pragma unroll
    for (int a = 0; a < 2; a++)
        #pragma unroll
        for (int b = 0; b < 4; b++)
            #pragma unroll
            for (int c = 0; c < 4; c++) acc[a][b][c] = 0.f;

    const int a_lr = lane & 15, a_lc = lane >> 4;
    const int b_lr = lane & 7,  b_lc = (lane >> 3) & 1;

    // prologue: prefetch chunk 0 into stage 0
    {
        uint32_t st = base_u;
        load_chunk_a_async(st + oAh, Ah, m0, V, 0, tid, kstride);
        load_chunk_a_async(st + oAl, Al, m0, V, 0, tid, kstride);
        load_chunk_b_async(st + oBh, Bh, n0, 0, tid, kstride);
        load_chunk_b_async(st + oBl, Bl, n0, 0, tid, kstride);
        CP_COMMIT();
    }

    for (int kci = 0; kci < nch; kci++) {
        const int cur = kci & 1;
        const uint32_t st = base_u + cur * LBUF;
        if (kci + 1 < nch) {
            uint32_t nx = base_u + (cur ^ 1) * LBUF;
            int kc = (kci + 1) * LTK;
            load_chunk_a_async(nx + oAh, Ah, m0, V, kc, tid, kstride);
            load_chunk_a_async(nx + oAl, Al, m0, V, kc, tid, kstride);
            load_chunk_b_async(nx + oBh, Bh, n0, kc, tid, kstride);
            load_chunk_b_async(nx + oBl, Bl, n0, kc, tid, kstride);
            CP_COMMIT();
            CP_WAIT1();
        } else {
            CP_WAIT0();
        }
        __syncthreads();

        const uint32_t uAh = st + oAh, uAl = st + oAl;
        const uint32_t uBh = st + oBh, uBl = st + oBl;
        #pragma unroll
        for (int ks = 0; ks < LTK/16; ks++) {
            uint32_t ah[2][4], al[2][4], bh[4][2], bl[4][2];
            #pragma unroll
            for (int mt = 0; mt < 2; mt++) {
                uint32_t off = (uint32_t)((wm*32 + mt*16 + a_lr)*128 + ks*32 + a_lc*16);
                off ^= (off >> 3) & 0x70;
                ldsm4(ah[mt], uAh + off);
                ldsm4(al[mt], uAl + off);
            }
            #pragma unroll
            for (int nt = 0; nt < 4; nt++) {
                uint32_t off = (uint32_t)((wn*32 + nt*8 + b_lr)*128 + ks*32 + b_lc*16);
                off ^= (off >> 3) & 0x70;
                ldsm2(bh[nt], uBh + off);
                ldsm2(bl[nt], uBl + off);
            }
            #pragma unroll
            for (int mt = 0; mt < 2; mt++)
                #pragma unroll
                for (int nt = 0; nt < 4; nt++)
                    mma_bf16(acc[mt][nt], ah[mt], bh[nt]);
            #pragma unroll
            for (int mt = 0; mt < 2; mt++)
                #pragma unroll
                for (int nt = 0; nt < 4; nt++)
                    mma_bf16(acc[mt][nt], ah[mt], bl[nt]);
            #pragma unroll
            for (int mt = 0; mt < 2; mt++)
                #pragma unroll
                for (int nt = 0; nt < 4; nt++)
                    mma_bf16(acc[mt][nt], al[mt], bh[nt]);
        }
        __syncthreads();
    }

    #pragma unroll
    for (int mt = 0; mt < 2; mt++) {
        int m1 = m0 + wm*32 + mt*16 + (lane >> 2);
        int m2 = m1 + 8;
        #pragma unroll
        for (int nt = 0; nt < 4; nt++) {
            int n = n0 + wn*32 + nt*8 + (lane & 3)*2;
            float2 bb = *(const float2*)&bias[n];
            const float* c = acc[mt][nt];
            if (m1 < V)
                *(float2*)&out[(size_t)m1*Nld + n] = make_float2(c[0] + bb.x, c[1] + bb.y);
            if (m2 < V)
                *(float2*)&out[(size_t)m2*Nld + n] = make_float2(c[2] + bb.x, c[3] + bb.y);
        }
    }
}

// ---------------- online log-softmax + argmax + mask + output ----------------
__global__ void softmax_kernel(const float* __restrict__ temp,
                               float* __restrict__ dout) {
    int bt = blockIdx.x;
    int b = bt / STEPS;
    int tid = threadIdx.x;             // 512
    int crow = g_rmap[bt];
    float4* lp4 = (float4*)(dout + LOGP_OFF + (size_t)bt*Vn);

    __shared__ float smx[512]; __shared__ int sai[512]; __shared__ float ssum[512];

    if (crow < 0) {
        float4 z = make_float4(0.f, 0.f, 0.f, 0.f);
        for (int i = tid; i < Vn/4; i += 512) lp4[i] = z;
        if (tid == 0) dout[TXT_OFF + bt] = 0.f;
        return;
    }

    float ls = 1.0f / temp[b];
    const float4* row4 = (const float4*)(g_logits + (size_t)crow*Vn);

    float mx = -3.402823466e38f; float sum = 0.f; int ai = 0;
    for (int i = tid; i < Vn/4; i += 512) {
        float4 v = row4[i];
        float vv[4] = {v.x, v.y, v.z, v.w};
        #pragma unroll
        for (int c = 0; c < 4; c++) {
            float x = vv[c];
            if (x > mx) {
                sum = sum * __expf((mx - x)*ls) + 1.f;
                mx = x; ai = 4*i + c;
            } else {
                sum += __expf((x - mx)*ls);
            }
        }
    }
    smx[tid] = mx; sai[tid] = ai; ssum[tid] = sum; __syncthreads();
    for (int s = 256; s > 0; s >>= 1) {
        if (tid < s) {
            float m1 = smx[tid],   m2 = smx[tid+s];
            float s1 = ssum[tid],  s2 = ssum[tid+s];
            int   i1 = sai[tid],   i2 = sai[tid+s];
            if (m2 > m1 || (m2 == m1 && i2 < i1)) {
                smx[tid] = m2; sai[tid] = i2;
                ssum[tid] = s2 + s1 * __expf((m1 - m2)*ls);
            } else {
                ssum[tid] = s1 + s2 * __expf((m2 - m1)*ls);
            }
        }
        __syncthreads();
    }
    mx = smx[0]; ai = sai[0];
    float lse = logf(ssum[0]);

    for (int i = tid; i < Vn/4; i += 512) {
        float4 v = row4[i];
        float4 o;
        o.x = (v.x - mx)*ls - lse;
        o.y = (v.y - mx)*ls - lse;
        o.z = (v.z - mx)*ls - lse;
        o.w = (v.w - mx)*ls - lse;
        lp4[i] = o;
    }
    if (tid == 0) dout[TXT_OFF + bt] = (float)ai;
}

// ---------------- launcher ----------------
extern "C" void kernel_launch(void* const* d_in, const int* in_sizes, int n_in,
                              void* d_out, int out_size) {
    const float* image = (const float*)d_in[0];
    const float* vp    = (const float*)d_in[1];
    const float* label = (const float*)d_in[2];
    const float* topic = (const float*)d_in[3];
    const float* temp  = (const float*)d_in[4];
    const int*   text  = (const int*)  d_in[5];
    const int*   length= (const int*)  d_in[6];
    const float* emb   = (const float*)d_in[7];
    const float* Wv    = (const float*)d_in[8];
    const float* bv    = (const float*)d_in[9];
    const float* Wh    = (const float*)d_in[10];
    const float* bh    = (const float*)d_in[11];
    const float* Wm    = (const float*)d_in[12];
    const float* bm    = (const float*)d_in[13];
    const float* Wih   = (const float*)d_in[14];
    const float* bih   = (const float*)d_in[15];
    const float* Whh   = (const float*)d_in[16];
    const float* bhh   = (const float*)d_in[17];
    const float* Wfc   = (const float*)d_in[18];
    const float* bfc   = (const float*)d_in[19];
    const float* Whh2  = (const float*)d_in[20];
    const float* bhh2  = (const float*)d_in[21];
    const float* Ws    = (const float*)d_in[22];
    const float* bs    = (const float*)d_in[23];
    const float* Wz    = (const float*)d_in[24];
    const float* bz    = (const float*)d_in[25];
    const float* Wp    = (const float*)d_in[26];
    const float* bp    = (const float*)d_in[27];
    float* dout = (float*)d_out;

    float *p_xg, *p_v, *p_hs, *p_fo, *p_hh2, *p_ss2, *p_logits;
    __nv_bfloat16 *p_wph, *p_wpl, *p_chh_h, *p_chh_l;
    __nv_bfloat16 *p_xcat_h, *p_xcat_l, *p_wih_h, *p_wih_l;
    int *p_V;
    cudaGetSymbolAddress((void**)&p_xg,     g_xg);
    cudaGetSymbolAddress((void**)&p_v,      g_v);
    cudaGetSymbolAddress((void**)&p_hs,     g_hs);
    cudaGetSymbolAddress((void**)&p_fo,     g_fo);
    cudaGetSymbolAddress((void**)&p_hh2,    g_hh2);
    cudaGetSymbolAddress((void**)&p_ss2,    g_ss2);
    cudaGetSymbolAddress((void**)&p_logits, g_logits);
    cudaGetSymbolAddress((void**)&p_wph,    g_wph);
    cudaGetSymbolAddress((void**)&p_wpl,    g_wpl);
    cudaGetSymbolAddress((void**)&p_chh_h,  g_chh_h);
    cudaGetSymbolAddress((void**)&p_chh_l,  g_chh_l);
    cudaGetSymbolAddress((void**)&p_xcat_h, g_xcat_h);
    cudaGetSymbolAddress((void**)&p_xcat_l, g_xcat_l);
    cudaGetSymbolAddress((void**)&p_wih_h,  g_wih_h);
    cudaGetSymbolAddress((void**)&p_wih_l,  g_wih_l);
    cudaGetSymbolAddress((void**)&p_V,      g_V);

    cudaFuncSetAttribute(mma_tn, cudaFuncAttributeMaxDynamicSharedMemorySize,
                         LOGITS_SMEM);

    // valid-row maps + weight splits (independent)
    build_maps<<<1, 256>>>(length);
    split_bf16<<<(Vn*En/4 + 255)/256, 256>>>(Wp, p_wph, p_wpl, Vn*En/4);
    split_pad_wih<<<4*Hn, 256>>>(Wih);

    prep_kernel<<<Bn, 256>>>(image, vp, label, topic, Wh, bh, Wm, bm);
    whh_transpose<<<Hn, Hn>>>(Whh);
    xcat_kernel<<<ROWS, 256>>>(text, emb);   // compact rows, bf16 hi/lo

    // Xg = Xcat @ Wih^T + bih on COMPACT rows : (V x 1024), K=832 (padded) -> tensor cores
    mma_tn<<<dim3((4*Hn)/64, (ROWS+127)/128), 256, LOGITS_SMEM>>>(
        p_xcat_h, p_xcat_l, p_wih_h, p_wih_l, bih, p_xg, p_V, KP, KP/LTK, 4*Hn);

    // v = image @ Wv^T + bv (all rows)
    gemm_tn<<<dim3((Hn+63)/64, (Bn*Pn+63)/64), 256>>>(image, En, Wv, bv, p_v,
                                                      Bn*Pn, Hn, En, 0, nullptr);
    // sequential LSTM: 8-CTA cluster per batch (256 CTAs)
    lstm_kernel<<<Bn*8, 256>>>(bhh);

    // fo = relu(Hs @ Wfc^T + bfc) on compact rows
    gemm_tn<<<dim3((2*En+63)/64, (ROWS+63)/64), 256>>>(p_hs, Hn, Wfc, bfc, p_fo,
                                                       ROWS, 2*En, Hn, 1, p_V);
    // _hh, _s on compact rows
    gemm_tn<<<dim3((Hn+63)/64, (ROWS+63)/64), 256>>>(p_fo, 2*En, Whh2, bhh2, p_hh2,
                                                     ROWS, Hn, En, 0, p_V);
    gemm_tn<<<dim3((Hn+63)/64, (ROWS+63)/64), 256>>>(p_fo + En, 2*En, Ws, bs, p_ss2,
                                                     ROWS, Hn, En, 0, p_V);
    // attention: att out + chh bf16 hi/lo split fused into epilogue
    attn_kernel<<<ROWS, 128>>>(image, Wz, bz, dout);

    // logits = chh @ Wp^T + bp (compact rows), K=256 -> tensor cores
    mma_tn<<<dim3(Vn/64, (ROWS+127)/128), 256, LOGITS_SMEM>>>(
        p_chh_h, p_chh_l, p_wph, p_wpl, bp, p_logits, p_V, En, En/LTK, Vn);

    // online log-softmax + argmax + masking + outputs
    softmax_kernel<<<ROWS, 512>>>(temp, dout);
}

// round 17
// speedup vs baseline: 2.4909x; 1.0374x over previous
#include <cuda_runtime.h>
#include <cuda_bf16.h>
#include <math.h>
#include <stdint.h>

// ---------------- problem constants ----------------
#define Bn 32
#define Pn 49
#define En 256
#define Hn 256
#define Tn 48
#define STEPS 47
#define Vn 32000
#define INn 792          // E + VP + LB + H + E
#define KP  832          // INn padded to 13*64 for mma k-chunks
#define XSn 536          // E + VP + LB + H
#define ROWS (Bn*STEPS)  // 1504

#define ATT_OFF 0
#define LOGP_OFF (ROWS*(Pn+1))                 // 75200
#define TXT_OFF  (LOGP_OFF + (size_t)ROWS*Vn)

// ---------------- scratch (device globals; no allocation) ----------------
__device__ float g_xs  [Bn*XSn];
__device__ float g_mean[Bn*En];
__device__ float g_h0m0[2*Bn*Hn];           // [0..Bn*Hn)=h0 (b-major), [Bn*Hn..)=m0
__device__ float g_xg  [ROWS*4*Hn];         // compact rows
__device__ float4 g_whhR4[Hn*Hn];
__device__ float g_v   [Bn*Pn*Hn];
__device__ float g_hs  [ROWS*Hn];           // compact rows
__device__ float g_fo  [ROWS*2*En];         // compact rows
__device__ float g_hh2 [ROWS*Hn];           // compact rows
__device__ float g_ss2 [ROWS*Hn];           // compact rows
__device__ float g_logits[(size_t)ROWS*Vn]; // compact rows (~192 MB cap)

// valid-row compaction maps
__device__ int g_V[1];
__device__ int g_rmap[ROWS];   // bt -> compact index (or -1)
__device__ int g_bcnt[Bn];     // valid steps per batch
__device__ int g_bstart[Bn];   // compact row offset per batch

// bf16 hi/lo splits for tensor-core GEMMs
__device__ __align__(256) __nv_bfloat16 g_wph[(size_t)Vn*En];
__device__ __align__(256) __nv_bfloat16 g_wpl[(size_t)Vn*En];
__device__ __align__(256) __nv_bfloat16 g_chh_h[ROWS*En];
__device__ __align__(256) __nv_bfloat16 g_chh_l[ROWS*En];
__device__ __align__(256) __nv_bfloat16 g_xcat_h[ROWS*KP];
__device__ __align__(256) __nv_bfloat16 g_xcat_l[ROWS*KP];
__device__ __align__(256) __nv_bfloat16 g_wih_h[4*Hn*KP];
__device__ __align__(256) __nv_bfloat16 g_wih_l[4*Hn*KP];

// ---------------- packed f32x2 helpers (Blackwell FFMA2) ----------------
__device__ __forceinline__ unsigned long long fpk(float lo, float hi) {
    unsigned long long r;
    asm("mov.b64 %0, {%1, %2};" : "=l"(r) : "f"(lo), "f"(hi));
    return r;
}
__device__ __forceinline__ void ffma2(unsigned long long& d,
                                      unsigned long long a,
                                      unsigned long long b) {
    asm("fma.rn.f32x2 %0, %1, %2, %3;" : "=l"(d) : "l"(a), "l"(b), "l"(d));
}
__device__ __forceinline__ float2 fup(unsigned long long v) {
    float2 r;
    asm("mov.b64 {%0, %1}, %2;" : "=f"(r.x), "=f"(r.y) : "l"(v));
    return r;
}
__device__ __forceinline__ float sigm(float x) {
    return 1.0f / (1.0f + __expf(-x));
}
__device__ __forceinline__ uint32_t smem_u32(const void* p) {
    uint32_t a;
    asm("{ .reg .u64 t; cvta.to.shared.u64 t, %1; cvt.u32.u64 %0, t; }"
        : "=r"(a) : "l"(p));
    return a;
}

// ---------------- warp-level tensor core helpers (sm_80+ ISA) ----------------
__device__ __forceinline__ void ldsm4(uint32_t* r, uint32_t addr) {
    asm volatile("ldmatrix.sync.aligned.m8n8.x4.shared.b16 {%0,%1,%2,%3}, [%4];"
        : "=r"(r[0]), "=r"(r[1]), "=r"(r[2]), "=r"(r[3]) : "r"(addr));
}
__device__ __forceinline__ void ldsm2(uint32_t* r, uint32_t addr) {
    asm volatile("ldmatrix.sync.aligned.m8n8.x2.shared.b16 {%0,%1}, [%2];"
        : "=r"(r[0]), "=r"(r[1]) : "r"(addr));
}
__device__ __forceinline__ void mma_bf16(float* c, const uint32_t* a, const uint32_t* b) {
    asm volatile(
        "mma.sync.aligned.m16n8k16.row.col.f32.bf16.bf16.f32 "
        "{%0,%1,%2,%3}, {%4,%5,%6,%7}, {%8,%9}, {%0,%1,%2,%3};"
        : "+f"(c[0]), "+f"(c[1]), "+f"(c[2]), "+f"(c[3])
        : "r"(a[0]), "r"(a[1]), "r"(a[2]), "r"(a[3]), "r"(b[0]), "r"(b[1]));
}
// cp.async 16B with src-size (0 => zero-fill)
__device__ __forceinline__ void cpa16(uint32_t dst, const void* src, int szbytes) {
    asm volatile("cp.async.cg.shared.global [%0], [%1], 16, %2;"
        :: "r"(dst), "l"(src), "r"(szbytes));
}
#define CP_COMMIT() asm volatile("cp.async.commit_group;" ::: "memory")
#define CP_WAIT1()  asm volatile("cp.async.wait_group 1;" ::: "memory")
#define CP_WAIT0()  asm volatile("cp.async.wait_group 0;" ::: "memory")

__device__ __forceinline__ void split1(float f, __nv_bfloat16& h, __nv_bfloat16& l) {
    h = __float2bfloat16_rn(f);
    l = __float2bfloat16_rn(f - __bfloat162float(h));
}

// ---------------- valid-row maps ----------------
__global__ void build_maps(const int* __restrict__ length) {
    __shared__ int cnt[Bn], start[Bn];
    int tid = threadIdx.x;
    if (tid < Bn) {
        int c = length[tid] - 1;
        if (c < 0) c = 0;
        if (c > STEPS) c = STEPS;
        cnt[tid] = c;
        g_bcnt[tid] = c;
    }
    __syncthreads();
    if (tid == 0) {
        int s = 0;
        for (int b = 0; b < Bn; b++) { start[b] = s; g_bstart[b] = s; s += cnt[b]; }
        g_V[0] = s;
    }
    __syncthreads();
    for (int bt = tid; bt < ROWS; bt += 256) {
        int b = bt / STEPS, t = bt % STEPS;
        g_rmap[bt] = (t < cnt[b]) ? (start[b] + t) : -1;
    }
}

// ---------------- prep: image_mean, x_static (no matvec) ----------------
__global__ void prep_kernel(const float* __restrict__ image,
                            const float* __restrict__ vp,
                            const float* __restrict__ label,
                            const float* __restrict__ topic) {
    int b = blockIdx.x;
    int tid = threadIdx.x;   // 256

    float s = 0.f;
    #pragma unroll 7
    for (int p = 0; p < Pn; p++) s += image[(b*Pn + p)*En + tid];
    float mean = s * (1.0f/49.0f);

    g_mean[b*En + tid] = mean;
    g_xs[b*XSn + tid] = mean;
    if (tid < 8)  g_xs[b*XSn + 256 + tid] = vp[b*8 + tid];
    if (tid < 16) g_xs[b*XSn + 264 + tid] = label[b*16 + tid];
    g_xs[b*XSn + 280 + tid] = topic[b*Hn + tid];
}

// ---------------- Whh reorder for coalesced LSTM reads ----------------
__global__ void whh_transpose(const float* __restrict__ Whh) {
    int k = blockIdx.x;
    int j = threadIdx.x;
    float4 w;
    w.x = Whh[(0*Hn + j)*Hn + k];
    w.y = Whh[(1*Hn + j)*Hn + k];
    w.z = Whh[(2*Hn + j)*Hn + k];
    w.w = Whh[(3*Hn + j)*Hn + k];
    g_whhR4[k*Hn + j] = w;
}

// ---------------- build concat rows (compact), bf16 hi/lo direct ----------------
__global__ void xcat_kernel(const int* __restrict__ text,
                            const float* __restrict__ emb) {
    int bt = blockIdx.x;
    int v = g_rmap[bt];
    if (v < 0) return;
    int b = bt / STEPS, t = bt % STEPS;
    int tid = threadIdx.x;      // 256
    int tok = text[b*Tn + t];
    __nv_bfloat16* rh = g_xcat_h + (size_t)v*KP;
    __nv_bfloat16* rl = g_xcat_l + (size_t)v*KP;
    for (int i = tid; i < XSn; i += 256) {
        __nv_bfloat16 h, l;
        split1(g_xs[b*XSn + i], h, l);
        rh[i] = h; rl[i] = l;
    }
    {
        __nv_bfloat16 h, l;
        split1(emb[(size_t)tok*En + tid], h, l);
        rh[XSn + tid] = h; rl[XSn + tid] = l;
    }
    if (tid < KP - INn) {
        rh[INn + tid] = __float2bfloat16_rn(0.f);
        rl[INn + tid] = __float2bfloat16_rn(0.f);
    }
}

// ---------------- bf16 hi/lo split (for Wp, contiguous) ----------------
__global__ void split_bf16(const float* __restrict__ src,
                           __nv_bfloat16* __restrict__ hi,
                           __nv_bfloat16* __restrict__ lo, int n4) {
    int i = blockIdx.x*256 + threadIdx.x;
    if (i >= n4) return;
    float4 v = ((const float4*)src)[i];
    float f[4] = {v.x, v.y, v.z, v.w};
    unsigned short h[4], l[4];
    #pragma unroll
    for (int k = 0; k < 4; k++) {
        __nv_bfloat16 hb = __float2bfloat16_rn(f[k]);
        float r = f[k] - __bfloat162float(hb);
        __nv_bfloat16 lb = __float2bfloat16_rn(r);
        h[k] = __bfloat16_as_ushort(hb);
        l[k] = __bfloat16_as_ushort(lb);
    }
    uint2 uh, ul;
    uh.x = (uint32_t)h[0] | ((uint32_t)h[1] << 16);
    uh.y = (uint32_t)h[2] | ((uint32_t)h[3] << 16);
    ul.x = (uint32_t)l[0] | ((uint32_t)l[1] << 16);
    ul.y = (uint32_t)l[2] | ((uint32_t)l[3] << 16);
    ((uint2*)hi)[i] = uh;
    ((uint2*)lo)[i] = ul;
}

// ---------------- pad-split for Wih: [1024 x 792] -> [1024 x 832] hi/lo ----------------
__global__ void split_pad_wih(const float* __restrict__ src) {
    int row = blockIdx.x;        // 1024
    int tid = threadIdx.x;       // 256
    const float* s = src + (size_t)row*INn;
    __nv_bfloat16* rh = g_wih_h + (size_t)row*KP;
    __nv_bfloat16* rl = g_wih_l + (size_t)row*KP;
    for (int i = tid; i < KP; i += 256) {
        float f = (i < INn) ? s[i] : 0.f;
        __nv_bfloat16 h, l;
        split1(f, h, l);
        rh[i] = h; rl[i] = l;
    }
}

// ---------------- small fp32 GEMM (64x64), runtime M; act: 0=none,1=relu,2=tanh ----------------
__global__ void gemm_tn(const float* __restrict__ A, int lda,
                        const float* __restrict__ W,
                        const float* __restrict__ bias,
                        float* __restrict__ C,
                        int M, int N, int K, int act,
                        const int* __restrict__ Mdev) {
    const int Mv = Mdev ? Mdev[0] : M;
    const int m0 = blockIdx.y * 64, n0 = blockIdx.x * 64;
    if (m0 >= Mv) return;

    __shared__ __align__(16) float As[16][64];
    __shared__ __align__(16) float Bs[16][64];

    const int tid = threadIdx.x;
    const int tx = tid & 15, ty = tid >> 4;

    unsigned long long acc[4][2];
    #pragma unroll
    for (int i = 0; i < 4; i++) { acc[i][0] = 0ULL; acc[i][1] = 0ULL; }

    for (int k0 = 0; k0 < K; k0 += 16) {
        #pragma unroll
        for (int i = 0; i < 4; i++) {
            int idx = tid + i*256;
            int r = idx >> 4, kk = idx & 15;
            int m = m0 + r, k = k0 + kk, n = n0 + r;
            As[kk][r] = (m < Mv && k < K) ? A[(size_t)m*lda + k] : 0.f;
            Bs[kk][r] = (n < N && k < K) ? W[(size_t)n*K + k] : 0.f;
        }
        __syncthreads();
        #pragma unroll
        for (int kk = 0; kk < 16; kk++) {
            float4 a4 = *(const float4*)&As[kk][ty*4];
            float4 b4 = *(const float4*)&Bs[kk][tx*4];
            unsigned long long b01 = fpk(b4.x, b4.y);
            unsigned long long b23 = fpk(b4.z, b4.w);
            unsigned long long a0 = fpk(a4.x, a4.x);
            unsigned long long a1 = fpk(a4.y, a4.y);
            unsigned long long a2 = fpk(a4.z, a4.z);
            unsigned long long a3 = fpk(a4.w, a4.w);
            ffma2(acc[0][0], a0, b01); ffma2(acc[0][1], a0, b23);
            ffma2(acc[1][0], a1, b01); ffma2(acc[1][1], a1, b23);
            ffma2(acc[2][0], a2, b01); ffma2(acc[2][1], a2, b23);
            ffma2(acc[3][0], a3, b01); ffma2(acc[3][1], a3, b23);
        }
        __syncthreads();
    }

    #pragma unroll
    for (int i = 0; i < 4; i++) {
        int m = m0 + ty*4 + i;
        if (m >= Mv) continue;
        float2 v0 = fup(acc[i][0]);
        float2 v1 = fup(acc[i][1]);
        float vals[4] = {v0.x, v0.y, v1.x, v1.y};
        #pragma unroll
        for (int jj = 0; jj < 4; jj++) {
            int n = n0 + tx*4 + jj;
            if (n < N) {
                float o = vals[jj] + bias[n];
                if (act == 1) o = fmaxf(o, 0.f);
                else if (act == 2) o = tanhf(o);
                C[(size_t)m*N + n] = o;
            }
        }
    }
}

// ---------------- sequential LSTM: 8-CTA cluster per batch ----------------
#define CLUSTER_SYNC() do { \
    asm volatile("barrier.cluster.arrive.aligned;" ::: "memory"); \
    asm volatile("barrier.cluster.wait.aligned;" ::: "memory"); \
} while (0)

__global__ void __cluster_dims__(8, 1, 1) lstm_kernel(const float* __restrict__ bhh) {
    const int tid = threadIdx.x;           // 256
    const int j   = tid & 31;
    const int s   = tid >> 5;
    uint32_t rank;
    asm("mov.u32 %0, %%cluster_ctarank;" : "=r"(rank));
    const int b  = blockIdx.x >> 3;
    const int j0 = rank * 32;

    const int steps    = g_bcnt[b];
    const int base_row = g_bstart[b];

    __shared__ __align__(16) float hs[2][Hn];
    __shared__ unsigned long long pIF[8][32], pGO[8][32];

    hs[0][tid] = g_h0m0[b*Hn + tid];                 // h0 block (b-major)

    float mc = 0.f, bi = 0.f, bf = 0.f, bg = 0.f, bo = 0.f;
    if (tid < 32) {
        int ju = j0 + tid;
        mc = g_h0m0[Bn*Hn + b*Hn + ju];              // m0 block
        bi = bhh[ju]; bf = bhh[256 + ju]; bg = bhh[512 + ju]; bo = bhh[768 + ju];
    }
    const ulonglong2* W2 = reinterpret_cast<const ulonglong2*>(g_whhR4);
    const uint32_t hs_u32 = smem_u32(hs);

    CLUSTER_SYNC();

    int cur = 0;
    for (int t = 0; t < steps; t++) {
        unsigned long long aIF = 0ULL, aGO = 0ULL;
        const float* h = hs[cur];
        const int kb = s * 32;
        #pragma unroll 4
        for (int k0 = 0; k0 < 32; k0 += 4) {
            float4 h4 = *(const float4*)&h[kb + k0];
            ulonglong2 w;
            unsigned long long hd;
            w = W2[(size_t)(kb+k0+0)*Hn + j0 + j]; hd = fpk(h4.x, h4.x); ffma2(aIF, hd, w.x); ffma2(aGO, hd, w.y);
            w = W2[(size_t)(kb+k0+1)*Hn + j0 + j]; hd = fpk(h4.y, h4.y); ffma2(aIF, hd, w.x); ffma2(aGO, hd, w.y);
            w = W2[(size_t)(kb+k0+2)*Hn + j0 + j]; hd = fpk(h4.z, h4.z); ffma2(aIF, hd, w.x); ffma2(aGO, hd, w.y);
            w = W2[(size_t)(kb+k0+3)*Hn + j0 + j]; hd = fpk(h4.w, h4.w); ffma2(aIF, hd, w.x); ffma2(aGO, hd, w.y);
        }
        pIF[s][j] = aIF;
        pGO[s][j] = aGO;
        __syncthreads();

        if (tid < 32) {
            float iacc = 0.f, facc = 0.f, gacc = 0.f, oacc = 0.f;
            #pragma unroll
            for (int r = 0; r < 8; r++) {
                float2 iv = fup(pIF[r][tid]);
                float2 gv = fup(pGO[r][tid]);
                iacc += iv.x; facc += iv.y;
                gacc += gv.x; oacc += gv.y;
            }

            size_t base = (size_t)(base_row + t) * (4*Hn) + j0 + tid;
            float gi = g_xg[base]        + bi + iacc;
            float gf = g_xg[base + 256]  + bf + facc;
            float gg = g_xg[base + 512]  + bg + gacc;
            float go = g_xg[base + 768]  + bo + oacc;
            mc = sigm(gf)*mc + sigm(gi)*tanhf(gg);
            float hn = sigm(go)*tanhf(mc);
            g_hs[(size_t)(base_row + t)*Hn + j0 + tid] = hn;

            uint32_t laddr = hs_u32 + (uint32_t)(((cur ^ 1) * Hn + j0 + tid) * 4);
            #pragma unroll
            for (int rr = 0; rr < 8; rr++) {
                uint32_t pa;
                asm("mapa.shared::cluster.u32 %0, %1, %2;" : "=r"(pa) : "r"(laddr), "r"(rr));
                asm volatile("st.shared::cluster.f32 [%0], %1;" :: "r"(pa), "f"(hn));
            }
        }
        CLUSTER_SYNC();
        cur ^= 1;
    }
}

// ---------------- fused attention per (b,t), compact-aware, fused chh split ----------------
__global__ void attn_kernel(const float* __restrict__ image,
                            const float* __restrict__ Wz,
                            const float* __restrict__ bz,
                            float* __restrict__ dout) {
    int bt = blockIdx.x;
    int b = bt / STEPS;
    int tid = threadIdx.x;             // 128
    int wid = tid >> 5, lane = tid & 31;
    int v = g_rmap[bt];

    if (v < 0) {
        if (tid < Pn+1)
            dout[ATT_OFF + (size_t)bt*(Pn+1) + tid] = 0.f;
        return;
    }

    __shared__ float shh2[Hn], shh[Hn], ss[Hn], ss2[Hn];
    __shared__ float zz[Pn+1], aw[Pn+1];

    for (int k = tid; k < Hn; k += 128) {
        shh2[k] = g_hh2[(size_t)v*Hn + k];
        shh [k] = g_fo [(size_t)v*2*En + k];
        ss  [k] = g_fo [(size_t)v*2*En + En + k];
        ss2 [k] = g_ss2[(size_t)v*Hn + k];
    }
    __syncthreads();

    for (int p = wid; p < Pn+1; p += 4) {
        float part = 0.f;
        const float* vrow = (p < Pn) ? (g_v + (size_t)(b*Pn + p)*Hn) : ss2;
        for (int k = lane; k < Hn; k += 32)
            part += Wz[k] * tanhf(vrow[k] + shh2[k]);
        #pragma unroll
        for (int off = 16; off > 0; off >>= 1)
            part += __shfl_down_sync(0xffffffff, part, off);
        if (lane == 0) zz[p] = part + bz[0];
    }
    __syncthreads();

    if (tid == 0) {
        float mx = zz[0];
        for (int p = 1; p < Pn+1; p++) mx = fmaxf(mx, zz[p]);
        float s = 0.f;
        for (int p = 0; p < Pn+1; p++) { float e = __expf(zz[p]-mx); aw[p] = e; s += e; }
        float inv = 1.f / s;
        for (int p = 0; p < Pn+1; p++) aw[p] *= inv;
    }
    __syncthreads();

    if (tid < Pn+1)
        dout[ATT_OFF + (size_t)bt*(Pn+1) + tid] = aw[tid];

    #pragma unroll
    for (int kk = 0; kk < 2; kk++) {
        int k = tid + kk*128;
        float c = aw[Pn] * ss[k];
        #pragma unroll 7
        for (int p = 0; p < Pn; p++)
            c = fmaf(aw[p], image[(size_t)(b*Pn + p)*En + k], c);
        float f = c + shh[k];
        __nv_bfloat16 hb, lb;
        split1(f, hb, lb);
        g_chh_h[(size_t)v*En + k] = hb;
        g_chh_l[(size_t)v*En + k] = lb;
    }
}

// ============== tensor-core GEMM via mma.sync (bf16 hi/lo, fp32 acc) ==============
#define LTK 64
#define LCHUNK_A (128*LTK*2)
#define LCHUNK_Bt (64*LTK*2)
#define LBUF (2*LCHUNK_A + 2*LCHUNK_Bt)
#define LOGITS_SMEM (2*LBUF)            // 98304

__device__ __forceinline__ void load_chunk_a_async(uint32_t dstu,
                                                   const __nv_bfloat16* __restrict__ src,
                                                   int row0, int rows_valid, int kc, int tid,
                                                   int stride) {
    #pragma unroll
    for (int i = 0; i < 4; i++) {
        int idx = tid + i*256;
        int row = idx >> 3, ch = idx & 7;
        uint32_t off = (uint32_t)(row*128 + ch*16);
        off ^= (off >> 3) & 0x70;
        int gr = row0 + row;
        int ok = (gr < rows_valid);
        int grc = ok ? gr : 0;
        cpa16(dstu + off, src + (size_t)grc*stride + kc + ch*8, ok ? 16 : 0);
    }
}
__device__ __forceinline__ void load_chunk_b_async(uint32_t dstu,
                                                   const __nv_bfloat16* __restrict__ src,
                                                   int row0, int kc, int tid, int stride) {
    #pragma unroll
    for (int i = 0; i < 2; i++) {
        int idx = tid + i*256;
        int row = idx >> 3, ch = idx & 7;
        uint32_t off = (uint32_t)(row*128 + ch*16);
        off ^= (off >> 3) & 0x70;
        cpa16(dstu + off, src + (size_t)(row0 + row)*stride + kc + ch*8, 16);
    }
}

__global__ __launch_bounds__(256, 2)
void mma_tn(const __nv_bfloat16* __restrict__ Ah, const __nv_bfloat16* __restrict__ Al,
            const __nv_bfloat16* __restrict__ Bh, const __nv_bfloat16* __restrict__ Bl,
            const float* __restrict__ bias, float* __restrict__ out,
            const int* __restrict__ Vdev, int kstride, int nch, int Nld) {
    const int V = Vdev[0];
    const int m0 = blockIdx.y * 128;
    if (m0 >= V) return;
    const int n0 = blockIdx.x * 64;

    extern __shared__ char smem[];
    const uint32_t base_u = smem_u32(smem);
    const uint32_t oAh = 0, oAl = LCHUNK_A, oBh = 2*LCHUNK_A, oBl = 2*LCHUNK_A + LCHUNK_Bt;

    const int tid = threadIdx.x;
    const int wid = tid >> 5, lane = tid & 31;
    const int wm = wid >> 1;
    const int wn = wid & 1;

    float acc[2][4][4];
    #pragma unroll
    for (int a = 0; a < 2; a++)
        #pragma unroll
        for (int b = 0; b < 4; b++)
            #pragma unroll
            for (int c = 0; c < 4; c++) acc[a][b][c] = 0.f;

    const int a_lr = lane & 15, a_lc = lane >> 4;
    const int b_lr = lane & 7,  b_lc = (lane >> 3) & 1;

    {
        uint32_t st = base_u;
        load_chunk_a_async(st + oAh, Ah, m0, V, 0, tid, kstride);
        load_chunk_a_async(st + oAl, Al, m0, V, 0, tid, kstride);
        load_chunk_b_async(st + oBh, Bh, n0, 0, tid, kstride);
        load_chunk_b_async(st + oBl, Bl, n0, 0, tid, kstride);
        CP_COMMIT();
    }

    for (int kci = 0; kci < nch; kci++) {
        const int cur = kci & 1;
        const uint32_t st = base_u + cur * LBUF;
        if (kci + 1 < nch) {
            uint32_t nx = base_u + (cur ^ 1) * LBUF;
            int kc = (kci + 1) * LTK;
            load_chunk_a_async(nx + oAh, Ah, m0, V, kc, tid, kstride);
            load_chunk_a_async(nx + oAl, Al, m0, V, kc, tid, kstride);
            load_chunk_b_async(nx + oBh, Bh, n0, kc, tid, kstride);
            load_chunk_b_async(nx + oBl, Bl, n0, kc, tid, kstride);
            CP_COMMIT();
            CP_WAIT1();
        } else {
            CP_WAIT0();
        }
        __syncthreads();

        const uint32_t uAh = st + oAh, uAl = st + oAl;
        const uint32_t uBh = st + oBh, uBl = st + oBl;
        #pragma unroll
        for (int ks = 0; ks < LTK/16; ks++) {
            uint32_t ah[2][4], al[2][4], bh[4][2], bl[4][2];
            #pragma unroll
            for (int mt = 0; mt < 2; mt++) {
                uint32_t off = (uint32_t)((wm*32 + mt*16 + a_lr)*128 + ks*32 + a_lc*16);
                off ^= (off >> 3) & 0x70;
                ldsm4(ah[mt], uAh + off);
                ldsm4(al[mt], uAl + off);
            }
            #pragma unroll
            for (int nt = 0; nt < 4; nt++) {
                uint32_t off = (uint32_t)((wn*32 + nt*8 + b_lr)*128 + ks*32 + b_lc*16);
                off ^= (off >> 3) & 0x70;
                ldsm2(bh[nt], uBh + off);
                ldsm2(bl[nt], uBl + off);
            }
            #pragma unroll
            for (int mt = 0; mt < 2; mt++)
                #pragma unroll
                for (int nt = 0; nt < 4; nt++)
                    mma_bf16(acc[mt][nt], ah[mt], bh[nt]);
            #pragma unroll
            for (int mt = 0; mt < 2; mt++)
                #pragma unroll
                for (int nt = 0; nt < 4; nt++)
                    mma_bf16(acc[mt][nt], ah[mt], bl[nt]);
            #pragma unroll
            for (int mt = 0; mt < 2; mt++)
                #pragma unroll
                for (int nt = 0; nt < 4; nt++)
                    mma_bf16(acc[mt][nt], al[mt], bh[nt]);
        }
        __syncthreads();
    }

    #pragma unroll
    for (int mt = 0; mt < 2; mt++) {
        int m1 = m0 + wm*32 + mt*16 + (lane >> 2);
        int m2 = m1 + 8;
        #pragma unroll
        for (int nt = 0; nt < 4; nt++) {
            int n = n0 + wn*32 + nt*8 + (lane & 3)*2;
            float2 bb = *(const float2*)&bias[n];
            const float* c = acc[mt][nt];
            if (m1 < V)
                *(float2*)&out[(size_t)m1*Nld + n] = make_float2(c[0] + bb.x, c[1] + bb.y);
            if (m2 < V)
                *(float2*)&out[(size_t)m2*Nld + n] = make_float2(c[2] + bb.x, c[3] + bb.y);
        }
    }
}

// ---------------- online log-softmax + argmax + mask + output ----------------
__global__ void softmax_kernel(const float* __restrict__ temp,
                               float* __restrict__ dout) {
    int bt = blockIdx.x;
    int b = bt / STEPS;
    int tid = threadIdx.x;             // 512
    int crow = g_rmap[bt];
    float4* lp4 = (float4*)(dout + LOGP_OFF + (size_t)bt*Vn);

    __shared__ float smx[512]; __shared__ int sai[512]; __shared__ float ssum[512];

    if (crow < 0) {
        float4 z = make_float4(0.f, 0.f, 0.f, 0.f);
        for (int i = tid; i < Vn/4; i += 512) lp4[i] = z;
        if (tid == 0) dout[TXT_OFF + bt] = 0.f;
        return;
    }

    float ls = 1.0f / temp[b];
    const float4* row4 = (const float4*)(g_logits + (size_t)crow*Vn);

    float mx = -3.402823466e38f; float sum = 0.f; int ai = 0;
    for (int i = tid; i < Vn/4; i += 512) {
        float4 v = row4[i];
        float vv[4] = {v.x, v.y, v.z, v.w};
        #pragma unroll
        for (int c = 0; c < 4; c++) {
            float x = vv[c];
            if (x > mx) {
                sum = sum * __expf((mx - x)*ls) + 1.f;
                mx = x; ai = 4*i + c;
            } else {
                sum += __expf((x - mx)*ls);
            }
        }
    }
    smx[tid] = mx; sai[tid] = ai; ssum[tid] = sum; __syncthreads();
    for (int s = 256; s > 0; s >>= 1) {
        if (tid < s) {
            float m1 = smx[tid],   m2 = smx[tid+s];
            float s1 = ssum[tid],  s2 = ssum[tid+s];
            int   i1 = sai[tid],   i2 = sai[tid+s];
            if (m2 > m1 || (m2 == m1 && i2 < i1)) {
                smx[tid] = m2; sai[tid] = i2;
                ssum[tid] = s2 + s1 * __expf((m1 - m2)*ls);
            } else {
                ssum[tid] = s1 + s2 * __expf((m2 - m1)*ls);
            }
        }
        __syncthreads();
    }
    mx = smx[0]; ai = sai[0];
    float lse = logf(ssum[0]);

    for (int i = tid; i < Vn/4; i += 512) {
        float4 v = row4[i];
        float4 o;
        o.x = (v.x - mx)*ls - lse;
        o.y = (v.y - mx)*ls - lse;
        o.z = (v.z - mx)*ls - lse;
        o.w = (v.w - mx)*ls - lse;
        lp4[i] = o;
    }
    if (tid == 0) dout[TXT_OFF + bt] = (float)ai;
}

// ---------------- launcher ----------------
extern "C" void kernel_launch(void* const* d_in, const int* in_sizes, int n_in,
                              void* d_out, int out_size) {
    const float* image = (const float*)d_in[0];
    const float* vp    = (const float*)d_in[1];
    const float* label = (const float*)d_in[2];
    const float* topic = (const float*)d_in[3];
    const float* temp  = (const float*)d_in[4];
    const int*   text  = (const int*)  d_in[5];
    const int*   length= (const int*)  d_in[6];
    const float* emb   = (const float*)d_in[7];
    const float* Wv    = (const float*)d_in[8];
    const float* bv    = (const float*)d_in[9];
    const float* Wh    = (const float*)d_in[10];
    const float* bh    = (const float*)d_in[11];
    const float* Wm    = (const float*)d_in[12];
    const float* bm    = (const float*)d_in[13];
    const float* Wih   = (const float*)d_in[14];
    const float* bih   = (const float*)d_in[15];
    const float* Whh   = (const float*)d_in[16];
    const float* bhh   = (const float*)d_in[17];
    const float* Wfc   = (const float*)d_in[18];
    const float* bfc   = (const float*)d_in[19];
    const float* Whh2  = (const float*)d_in[20];
    const float* bhh2  = (const float*)d_in[21];
    const float* Ws    = (const float*)d_in[22];
    const float* bs    = (const float*)d_in[23];
    const float* Wz    = (const float*)d_in[24];
    const float* bz    = (const float*)d_in[25];
    const float* Wp    = (const float*)d_in[26];
    const float* bp    = (const float*)d_in[27];
    float* dout = (float*)d_out;

    float *p_xg, *p_v, *p_hs, *p_fo, *p_hh2, *p_ss2, *p_logits, *p_mean, *p_h0m0;
    __nv_bfloat16 *p_wph, *p_wpl, *p_chh_h, *p_chh_l;
    __nv_bfloat16 *p_xcat_h, *p_xcat_l, *p_wih_h, *p_wih_l;
    int *p_V;
    cudaGetSymbolAddress((void**)&p_xg,     g_xg);
    cudaGetSymbolAddress((void**)&p_v,      g_v);
    cudaGetSymbolAddress((void**)&p_hs,     g_hs);
    cudaGetSymbolAddress((void**)&p_fo,     g_fo);
    cudaGetSymbolAddress((void**)&p_hh2,    g_hh2);
    cudaGetSymbolAddress((void**)&p_ss2,    g_ss2);
    cudaGetSymbolAddress((void**)&p_logits, g_logits);
    cudaGetSymbolAddress((void**)&p_mean,   g_mean);
    cudaGetSymbolAddress((void**)&p_h0m0,   g_h0m0);
    cudaGetSymbolAddress((void**)&p_wph,    g_wph);
    cudaGetSymbolAddress((void**)&p_wpl,    g_wpl);
    cudaGetSymbolAddress((void**)&p_chh_h,  g_chh_h);
    cudaGetSymbolAddress((void**)&p_chh_l,  g_chh_l);
    cudaGetSymbolAddress((void**)&p_xcat_h, g_xcat_h);
    cudaGetSymbolAddress((void**)&p_xcat_l, g_xcat_l);
    cudaGetSymbolAddress((void**)&p_wih_h,  g_wih_h);
    cudaGetSymbolAddress((void**)&p_wih_l,  g_wih_l);
    cudaGetSymbolAddress((void**)&p_V,      g_V);

    cudaFuncSetAttribute(mma_tn, cudaFuncAttributeMaxDynamicSharedMemorySize,
                         LOGITS_SMEM);

    // valid-row maps + weight splits (independent)
    build_maps<<<1, 256>>>(length);
    split_bf16<<<(Vn*En/4 + 255)/256, 256>>>(Wp, p_wph, p_wpl, Vn*En/4);
    split_pad_wih<<<4*Hn, 256>>>(Wih);

    prep_kernel<<<Bn, 256>>>(image, vp, label, topic);
    whh_transpose<<<Hn, Hn>>>(Whh);
    xcat_kernel<<<ROWS, 256>>>(text, emb);   // compact rows, bf16 hi/lo

    // h0 = tanh(mean @ Wh^T + bh) : (32 x 256) -> g_h0m0[0 ..)
    gemm_tn<<<dim3(4, 1), 256>>>(p_mean, En, Wh, bh, p_h0m0,
                                 Bn, Hn, En, 2, nullptr);
    // m0 = tanh(mean @ Wm^T + bm) : (32 x 256) -> g_h0m0[Bn*Hn ..)
    gemm_tn<<<dim3(4, 1), 256>>>(p_mean, En, Wm, bm, p_h0m0 + Bn*Hn,
                                 Bn, Hn, En, 2, nullptr);

    // Xg = Xcat @ Wih^T + bih on COMPACT rows : (V x 1024), K=832 -> tensor cores
    mma_tn<<<dim3((4*Hn)/64, (ROWS+127)/128), 256, LOGITS_SMEM>>>(
        p_xcat_h, p_xcat_l, p_wih_h, p_wih_l, bih, p_xg, p_V, KP, KP/LTK, 4*Hn);

    // v = image @ Wv^T + bv (all rows)
    gemm_tn<<<dim3((Hn+63)/64, (Bn*Pn+63)/64), 256>>>(image, En, Wv, bv, p_v,
                                                      Bn*Pn, Hn, En, 0, nullptr);
    // sequential LSTM: 8-CTA cluster per batch (256 CTAs)
    lstm_kernel<<<Bn*8, 256>>>(bhh);

    // fo = relu(Hs @ Wfc^T + bfc) on compact rows
    gemm_tn<<<dim3((2*En+63)/64, (ROWS+63)/64), 256>>>(p_hs, Hn, Wfc, bfc, p_fo,
                                                       ROWS, 2*En, Hn, 1, p_V);
    // _hh, _s on compact rows
    gemm_tn<<<dim3((Hn+63)/64, (ROWS+63)/64), 256>>>(p_fo, 2*En, Whh2, bhh2, p_hh2,
                                                     ROWS, Hn, En, 0, p_V);
    gemm_tn<<<dim3((Hn+63)/64, (ROWS+63)/64), 256>>>(p_fo + En, 2*En, Ws, bs, p_ss2,
                                                     ROWS, Hn, En, 0, p_V);
    // attention: att out + chh bf16 hi/lo split fused into epilogue
    attn_kernel<<<ROWS, 128>>>(image, Wz, bz, dout);

    // logits = chh @ Wp^T + bp (compact rows), K=256 -> tensor cores
    mma_tn<<<dim3(Vn/64, (ROWS+127)/128), 256, LOGITS_SMEM>>>(
        p_chh_h, p_chh_l, p_wph, p_wpl, bp, p_logits, p_V, En, En/LTK, Vn);

    // online log-softmax + argmax + masking + outputs
    softmax_kernel<<<ROWS, 512>>>(temp, dout);
}